// round 1
// baseline (speedup 1.0000x reference)
#include <cuda_runtime.h>
#include <cuda_bf16.h>
#include <math.h>
#include <stdint.h>

// ---------------- problem constants (GPT-2 small forward) ----------------
#define Bq   8
#define Tt   1024
#define NT   8192          // B*T tokens
#define Cd   768
#define Hh   12
#define HSd  64
#define Fd   3072
#define Ll   12
#define Vv   50257

// ---------------- scratch (device globals: allocation-free) --------------
__device__ float g_x[(size_t)NT * Cd];     // residual stream
__device__ float g_h[(size_t)NT * Cd];     // LN output
__device__ float g_qb[(size_t)NT * Cd];
__device__ float g_kb[(size_t)NT * Cd];
__device__ float g_vb[(size_t)NT * Cd];
__device__ float g_ob[(size_t)NT * Cd];
__device__ float g_f[(size_t)NT * Fd];     // MLP hidden / logits chunks
__device__ float g_rowloss[NT];
__device__ float g_lm[NT];                 // chunked-lse state
__device__ float g_ls[NT];
__device__ float g_lt[NT];

// ---------------- block reduce helpers ----------------
__device__ __forceinline__ float blockReduceSum256(float v) {
    __shared__ float sh[8];
    int lane = threadIdx.x & 31, w = threadIdx.x >> 5;
#pragma unroll
    for (int o = 16; o; o >>= 1) v += __shfl_xor_sync(0xffffffffu, v, o);
    if (lane == 0) sh[w] = v;
    __syncthreads();
    float r = (threadIdx.x < 8) ? sh[threadIdx.x] : 0.f;
    if (w == 0) {
#pragma unroll
        for (int o = 4; o; o >>= 1) r += __shfl_xor_sync(0xffffffffu, r, o);
    }
    __syncthreads();
    if (threadIdx.x == 0) sh[0] = r;
    __syncthreads();
    return sh[0];
}

__device__ __forceinline__ float blockReduceMax256(float v) {
    __shared__ float sh[8];
    int lane = threadIdx.x & 31, w = threadIdx.x >> 5;
#pragma unroll
    for (int o = 16; o; o >>= 1) v = fmaxf(v, __shfl_xor_sync(0xffffffffu, v, o));
    if (lane == 0) sh[w] = v;
    __syncthreads();
    float r = (threadIdx.x < 8) ? sh[threadIdx.x] : -1e30f;
    if (w == 0) {
#pragma unroll
        for (int o = 4; o; o >>= 1) r = fmaxf(r, __shfl_xor_sync(0xffffffffu, r, o));
    }
    __syncthreads();
    if (threadIdx.x == 0) sh[0] = r;
    __syncthreads();
    return sh[0];
}

// ---------------- embedding ----------------
__global__ void embed_kernel(const int* __restrict__ inp,
                             const float* __restrict__ tok,
                             const float* __restrict__ pos,
                             float* __restrict__ x) {
    int i = blockIdx.x;                 // token 0..NT-1
    int t = i & (Tt - 1);
    int v = inp[i];
    const float* te = tok + (size_t)v * Cd;
    const float* pe = pos + (size_t)t * Cd;
    float* xo = x + (size_t)i * Cd;
    for (int c = threadIdx.x; c < Cd; c += blockDim.x)
        xo[c] = te[c] + pe[c];
}

// ---------------- layernorm (row per block) ----------------
__global__ __launch_bounds__(256) void ln_kernel(const float* __restrict__ x,
                                                 const float* __restrict__ g,
                                                 const float* __restrict__ b,
                                                 float* __restrict__ out) {
    int row = blockIdx.x;
    const float* xr = x + (size_t)row * Cd;
    float s = 0.f;
    for (int c = threadIdx.x; c < Cd; c += 256) s += xr[c];
    float mean = blockReduceSum256(s) * (1.0f / Cd);
    float vs = 0.f;
    for (int c = threadIdx.x; c < Cd; c += 256) {
        float d = xr[c] - mean;
        vs += d * d;
    }
    float var = blockReduceSum256(vs) * (1.0f / Cd);
    float rstd = rsqrtf(var + 1e-5f);
    float* orow = out + (size_t)row * Cd;
    for (int c = threadIdx.x; c < Cd; c += 256)
        orow[c] = (xr[c] - mean) * rstd * g[c] + b[c];
}

// ---------------- SGEMM: C[M,Nn] = A[M,K] @ W[K,*ldw] (+bias,+relu,+res) ----
// BM=128, BN=64, BK=16, 256 threads, 8x4 microtile
template<bool BIAS, bool RELU, bool RES>
__global__ __launch_bounds__(256) void sgemm_kernel(
    const float* __restrict__ A, const float* __restrict__ W,
    const float* __restrict__ bias, const float* __restrict__ res,
    float* __restrict__ Cout, int M, int Nn, int K, int ldw) {
    __shared__ float As[16][132];
    __shared__ float Bs[16][64];
    int tid = threadIdx.x;
    int m0 = blockIdx.x * 128;
    int n0 = blockIdx.y * 64;
    int tx = tid & 15, ty = tid >> 4;

    float acc[8][4];
#pragma unroll
    for (int i = 0; i < 8; i++)
#pragma unroll
        for (int j = 0; j < 4; j++) acc[i][j] = 0.f;

    int am = tid >> 1;
    int ak = (tid & 1) * 8;
    int bk = tid >> 4;
    int bn = (tid & 15) * 4;
    bool nvec = ((Nn & 3) == 0) && ((ldw & 3) == 0);

    for (int k0 = 0; k0 < K; k0 += 16) {
        const float* Ap = A + (size_t)(m0 + am) * K + k0 + ak;
        float4 a0 = *(const float4*)Ap;
        float4 a1 = *(const float4*)(Ap + 4);
        As[ak + 0][am] = a0.x; As[ak + 1][am] = a0.y;
        As[ak + 2][am] = a0.z; As[ak + 3][am] = a0.w;
        As[ak + 4][am] = a1.x; As[ak + 5][am] = a1.y;
        As[ak + 6][am] = a1.z; As[ak + 7][am] = a1.w;

        int gn = n0 + bn;
        const float* Wp = W + (size_t)(k0 + bk) * ldw + gn;
        float4 bv;
        if (nvec) {
            bv = (gn < Nn) ? *(const float4*)Wp : make_float4(0.f, 0.f, 0.f, 0.f);
        } else {
            bv.x = (gn + 0 < Nn) ? Wp[0] : 0.f;
            bv.y = (gn + 1 < Nn) ? Wp[1] : 0.f;
            bv.z = (gn + 2 < Nn) ? Wp[2] : 0.f;
            bv.w = (gn + 3 < Nn) ? Wp[3] : 0.f;
        }
        *(float4*)&Bs[bk][bn] = bv;
        __syncthreads();

#pragma unroll
        for (int kk = 0; kk < 16; kk++) {
            float4 a04 = *(const float4*)&As[kk][ty * 8];
            float4 a14 = *(const float4*)&As[kk][ty * 8 + 4];
            float4 b4  = *(const float4*)&Bs[kk][tx * 4];
            float a[8] = {a04.x, a04.y, a04.z, a04.w, a14.x, a14.y, a14.z, a14.w};
            float bb[4] = {b4.x, b4.y, b4.z, b4.w};
#pragma unroll
            for (int i = 0; i < 8; i++)
#pragma unroll
                for (int j = 0; j < 4; j++)
                    acc[i][j] += a[i] * bb[j];
        }
        __syncthreads();
    }

    int nbase = n0 + tx * 4;
    if (nvec && nbase + 3 < Nn) {
#pragma unroll
        for (int i = 0; i < 8; i++) {
            size_t off = (size_t)(m0 + ty * 8 + i) * Nn + nbase;
            float4 v = make_float4(acc[i][0], acc[i][1], acc[i][2], acc[i][3]);
            if (BIAS) {
                const float4 bb = *(const float4*)&bias[nbase];
                v.x += bb.x; v.y += bb.y; v.z += bb.z; v.w += bb.w;
            }
            if (RELU) {
                v.x = fmaxf(v.x, 0.f); v.y = fmaxf(v.y, 0.f);
                v.z = fmaxf(v.z, 0.f); v.w = fmaxf(v.w, 0.f);
            }
            if (RES) {
                const float4 rr = *(const float4*)&res[off];
                v.x += rr.x; v.y += rr.y; v.z += rr.z; v.w += rr.w;
            }
            *(float4*)&Cout[off] = v;
        }
    } else {
#pragma unroll
        for (int i = 0; i < 8; i++) {
            size_t rowoff = (size_t)(m0 + ty * 8 + i) * Nn;
#pragma unroll
            for (int j = 0; j < 4; j++) {
                int n = nbase + j;
                if (n < Nn) {
                    float v = acc[i][j];
                    if (BIAS) v += bias[n];
                    if (RELU) v = fmaxf(v, 0.f);
                    if (RES) v += res[rowoff + n];
                    Cout[rowoff + n] = v;
                }
            }
        }
    }
}

// ---------------- flash attention (fp32, causal) ----------------
// grid: (T/64, B*H), block: 64 threads, one query per thread
__global__ __launch_bounds__(64) void attn_kernel(const float* __restrict__ Q,
                                                  const float* __restrict__ Kg,
                                                  const float* __restrict__ Vg,
                                                  float* __restrict__ O) {
    __shared__ float4 Ks[64 * 16];
    __shared__ float4 Vs[64 * 16];
    int qt = blockIdx.x;
    int bh = blockIdx.y;
    int b = bh / Hh, h = bh % Hh;
    int tid = threadIdx.x;
    int t = qt * 64 + tid;
    const float scale = 0.125f;  // HS^-0.5

    float4 qreg[16];
    const float4* qp = (const float4*)(Q + (size_t)(b * Tt + t) * Cd + h * HSd);
#pragma unroll
    for (int d = 0; d < 16; d++) qreg[d] = qp[d];

    float o[64];
#pragma unroll
    for (int d = 0; d < 64; d++) o[d] = 0.f;
    float mM = -1e30f, lS = 0.f;

    for (int kt = 0; kt <= qt; kt++) {
        int j0 = kt * 64;
        __syncthreads();
#pragma unroll
        for (int it = 0; it < 16; it++) {
            int r = it * 4 + (tid >> 4);
            int c4 = tid & 15;
            size_t goff = (size_t)(b * Tt + j0 + r) * Cd + h * HSd;
            Ks[r * 16 + c4] = *(const float4*)(Kg + goff + c4 * 4);
            Vs[r * 16 + c4] = *(const float4*)(Vg + goff + c4 * 4);
        }
        __syncthreads();
        int jmax = (kt == qt) ? (tid + 1) : 64;

        float mNew = mM;
        for (int j = 0; j < jmax; j++) {
            float s = 0.f;
#pragma unroll
            for (int d = 0; d < 16; d++) {
                float4 kk = Ks[j * 16 + d];
                float4 qq = qreg[d];
                s += qq.x * kk.x + qq.y * kk.y + qq.z * kk.z + qq.w * kk.w;
            }
            mNew = fmaxf(mNew, s * scale);
        }
        float alpha = __expf(mM - mNew);
        lS *= alpha;
#pragma unroll
        for (int d = 0; d < 64; d++) o[d] *= alpha;
        mM = mNew;

        for (int j = 0; j < jmax; j++) {
            float s = 0.f;
#pragma unroll
            for (int d = 0; d < 16; d++) {
                float4 kk = Ks[j * 16 + d];
                float4 qq = qreg[d];
                s += qq.x * kk.x + qq.y * kk.y + qq.z * kk.z + qq.w * kk.w;
            }
            float p = __expf(s * scale - mM);
            lS += p;
#pragma unroll
            for (int d = 0; d < 16; d++) {
                float4 vv = Vs[j * 16 + d];
                o[d * 4 + 0] += p * vv.x;
                o[d * 4 + 1] += p * vv.y;
                o[d * 4 + 2] += p * vv.z;
                o[d * 4 + 3] += p * vv.w;
            }
        }
    }
    float inv = 1.f / lS;
    float* op = O + (size_t)(b * Tt + t) * Cd + h * HSd;
#pragma unroll
    for (int d = 0; d < 64; d++) op[d] = o[d] * inv;
}

// ---------------- loss over full logits (row per block) ----------------
__global__ __launch_bounds__(256) void rowloss_kernel(const float* __restrict__ logits,
                                                      const int* __restrict__ tgt,
                                                      float* __restrict__ rl) {
    int r = blockIdx.x;
    const float* lr = logits + (size_t)r * Vv;
    float m = -1e30f;
    for (int c = threadIdx.x; c < Vv; c += 256) m = fmaxf(m, lr[c]);
    m = blockReduceMax256(m);
    float s = 0.f;
    for (int c = threadIdx.x; c < Vv; c += 256) s += __expf(lr[c] - m);
    s = blockReduceSum256(s);
    if (threadIdx.x == 0) rl[r] = m + logf(s) - lr[tgt[r]];
}

__global__ __launch_bounds__(256) void lossreduce_kernel(const float* __restrict__ rl,
                                                         float* __restrict__ out) {
    float s = 0.f;
    for (int i = threadIdx.x; i < NT; i += 256) s += rl[i];
    s = blockReduceSum256(s);
    if (threadIdx.x == 0) out[0] = s * (1.0f / NT);
}

// ---------------- chunked-lse fallback (only used if out_size < N*V) -----
__global__ void lse_init_kernel(float* lm, float* ls, float* lt) {
    int i = blockIdx.x * blockDim.x + threadIdx.x;
    if (i < NT) { lm[i] = -1e30f; ls[i] = 0.f; lt[i] = 0.f; }
}

__global__ __launch_bounds__(256) void chunkloss_kernel(const float* __restrict__ chunk,
                                                        int width, int col0,
                                                        const int* __restrict__ tgt,
                                                        float* __restrict__ lm,
                                                        float* __restrict__ ls,
                                                        float* __restrict__ lt) {
    int r = blockIdx.x;
    const float* cr = chunk + (size_t)r * width;
    float m = -1e30f;
    for (int c = threadIdx.x; c < width; c += 256) m = fmaxf(m, cr[c]);
    m = blockReduceMax256(m);
    float s = 0.f;
    for (int c = threadIdx.x; c < width; c += 256) s += __expf(cr[c] - m);
    s = blockReduceSum256(s);
    if (threadIdx.x == 0) {
        float mOld = lm[r];
        float mNew = fmaxf(mOld, m);
        ls[r] = ls[r] * __expf(mOld - mNew) + s * __expf(m - mNew);
        lm[r] = mNew;
        int tg = tgt[r] - col0;
        if (tg >= 0 && tg < width) lt[r] = cr[tg];
    }
}

__global__ void chunkfinal_kernel(const float* lm, const float* ls, const float* lt,
                                  float* rl) {
    int i = blockIdx.x * blockDim.x + threadIdx.x;
    if (i < NT) rl[i] = lm[i] + logf(ls[i]) - lt[i];
}

// ---------------- host driver ----------------
static float* devptr(const void* sym) {
    void* p = nullptr;
    cudaGetSymbolAddress(&p, sym);
    return (float*)p;
}

extern "C" void kernel_launch(void* const* d_in, const int* in_sizes, int n_in,
                              void* d_out, int out_size) {
    const int* inputs    = (const int*)d_in[0];
    const int* targets   = (const int*)d_in[1];
    const float* tok     = (const float*)d_in[2];
    const float* pos     = (const float*)d_in[3];
    const float* ln1g    = (const float*)d_in[4];
    const float* ln1b    = (const float*)d_in[5];
    const float* ln2g    = (const float*)d_in[6];
    const float* ln2b    = (const float*)d_in[7];
    const float* wq      = (const float*)d_in[8];
    const float* wk      = (const float*)d_in[9];
    const float* wv      = (const float*)d_in[10];
    const float* wo      = (const float*)d_in[11];
    const float* bo      = (const float*)d_in[12];
    const float* w1      = (const float*)d_in[13];
    const float* b1      = (const float*)d_in[14];
    const float* w2      = (const float*)d_in[15];
    const float* b2      = (const float*)d_in[16];
    const float* lnfg    = (const float*)d_in[17];
    const float* lnfb    = (const float*)d_in[18];
    const float* whead   = (const float*)d_in[19];
    const float* bhead   = (const float*)d_in[20];

    float* x  = devptr(g_x);
    float* h  = devptr(g_h);
    float* qb = devptr(g_qb);
    float* kb = devptr(g_kb);
    float* vb = devptr(g_vb);
    float* ob = devptr(g_ob);
    float* fb = devptr(g_f);
    float* rl = devptr(g_rowloss);
    float* lm = devptr(g_lm);
    float* ls = devptr(g_ls);
    float* lt = devptr(g_lt);

    dim3 gQKV(NT / 128, Cd / 64);        // 64 x 12
    dim3 gFF1(NT / 128, Fd / 64);        // 64 x 48
    dim3 gHead(NT / 128, (Vv + 63) / 64);  // 64 x 786
    dim3 gAttn(Tt / 64, Bq * Hh);        // 16 x 96

    embed_kernel<<<NT, 256>>>(inputs, tok, pos, x);

    for (int l = 0; l < Ll; l++) {
        const float* wql = wq + (size_t)l * Cd * Cd;
        const float* wkl = wk + (size_t)l * Cd * Cd;
        const float* wvl = wv + (size_t)l * Cd * Cd;
        const float* wol = wo + (size_t)l * Cd * Cd;
        const float* w1l = w1 + (size_t)l * Cd * Fd;
        const float* w2l = w2 + (size_t)l * Fd * Cd;

        ln_kernel<<<NT, 256>>>(x, ln1g + l * Cd, ln1b + l * Cd, h);
        sgemm_kernel<false, false, false><<<gQKV, 256>>>(h, wql, nullptr, nullptr, qb, NT, Cd, Cd, Cd);
        sgemm_kernel<false, false, false><<<gQKV, 256>>>(h, wkl, nullptr, nullptr, kb, NT, Cd, Cd, Cd);
        sgemm_kernel<false, false, false><<<gQKV, 256>>>(h, wvl, nullptr, nullptr, vb, NT, Cd, Cd, Cd);
        attn_kernel<<<gAttn, 64>>>(qb, kb, vb, ob);
        sgemm_kernel<true, false, true><<<gQKV, 256>>>(ob, wol, bo + l * Cd, x, x, NT, Cd, Cd, Cd);
        ln_kernel<<<NT, 256>>>(x, ln2g + l * Cd, ln2b + l * Cd, h);
        sgemm_kernel<true, true, false><<<gFF1, 256>>>(h, w1l, b1 + (size_t)l * Fd, nullptr, fb, NT, Fd, Cd, Fd);
        sgemm_kernel<true, false, true><<<gQKV, 256>>>(fb, w2l, b2 + l * Cd, x, x, NT, Cd, Fd, Cd);
    }

    ln_kernel<<<NT, 256>>>(x, lnfg, lnfb, h);

    const long long NV = (long long)NT * Vv;
    if ((long long)out_size >= NV) {
        float* logits = (float*)d_out;
        sgemm_kernel<true, false, false><<<gHead, 256>>>(h, whead, bhead, nullptr,
                                                         logits, NT, Vv, Cd, Vv);
        if ((long long)out_size > NV) {
            rowloss_kernel<<<NT, 256>>>(logits, targets, rl);
            lossreduce_kernel<<<1, 256>>>(rl, (float*)d_out + NV);
        }
    } else {
        // loss-only fallback: chunked logsumexp through g_f
        lse_init_kernel<<<(NT + 255) / 256, 256>>>(lm, ls, lt);
        const int CW = 3072;
        for (int col0 = 0; col0 < Vv; col0 += CW) {
            int width = (Vv - col0 < CW) ? (Vv - col0) : CW;
            dim3 gC(NT / 128, (width + 63) / 64);
            sgemm_kernel<true, false, false><<<gC, 256>>>(h, whead + col0, bhead + col0,
                                                          nullptr, fb, NT, width, Cd, Vv);
            chunkloss_kernel<<<NT, 256>>>(fb, width, col0, targets, lm, ls, lt);
        }
        chunkfinal_kernel<<<(NT + 255) / 256, 256>>>(lm, ls, lt, rl);
        lossreduce_kernel<<<1, 256>>>(rl, (float*)d_out);
    }
}

// round 3
// speedup vs baseline: 1.8147x; 1.8147x over previous
#include <cuda_runtime.h>
#include <cuda_bf16.h>
#include <math.h>
#include <stdint.h>

// ---------------- problem constants (GPT-2 small forward) ----------------
#define Bq   8
#define Tt   1024
#define NT   8192          // B*T tokens
#define Cd   768
#define Hh   12
#define HSd  64
#define Fd   3072
#define Ll   12
#define Vv   50257

// ---------------- scratch (device globals: allocation-free) --------------
__device__ float g_x[(size_t)NT * Cd];     // residual stream
__device__ float g_h[(size_t)NT * Cd];     // LN output
__device__ float g_qb[(size_t)NT * Cd];
__device__ float g_kb[(size_t)NT * Cd];
__device__ float g_vb[(size_t)NT * Cd];
__device__ float g_ob[(size_t)NT * Cd];
__device__ float g_f[(size_t)NT * Fd];     // MLP hidden / logits chunks
__device__ float g_rowloss[NT];
__device__ float g_lm[NT];                 // chunked-lse state
__device__ float g_ls[NT];
__device__ float g_lt[NT];

// ---------------- helpers ----------------
__device__ __forceinline__ float f2tf(float x) {
    uint32_t u;
    asm("cvt.rna.tf32.f32 %0, %1;" : "=r"(u) : "f"(x));
    return __uint_as_float(u);
}

__device__ __forceinline__ void mma8(float* c, const uint32_t* a, const uint32_t* b) {
    asm volatile(
        "mma.sync.aligned.m16n8k8.row.col.f32.tf32.tf32.f32 "
        "{%0,%1,%2,%3}, {%4,%5,%6,%7}, {%8,%9}, {%0,%1,%2,%3};\n"
        : "+f"(c[0]), "+f"(c[1]), "+f"(c[2]), "+f"(c[3])
        : "r"(a[0]), "r"(a[1]), "r"(a[2]), "r"(a[3]), "r"(b[0]), "r"(b[1]));
}

// ---------------- block reduce helpers ----------------
__device__ __forceinline__ float blockReduceSum256(float v) {
    __shared__ float sh[8];
    int lane = threadIdx.x & 31, w = threadIdx.x >> 5;
#pragma unroll
    for (int o = 16; o; o >>= 1) v += __shfl_xor_sync(0xffffffffu, v, o);
    if (lane == 0) sh[w] = v;
    __syncthreads();
    float r = (threadIdx.x < 8) ? sh[threadIdx.x] : 0.f;
    if (w == 0) {
#pragma unroll
        for (int o = 4; o; o >>= 1) r += __shfl_xor_sync(0xffffffffu, r, o);
    }
    __syncthreads();
    if (threadIdx.x == 0) sh[0] = r;
    __syncthreads();
    return sh[0];
}

__device__ __forceinline__ float blockReduceMax256(float v) {
    __shared__ float sh[8];
    int lane = threadIdx.x & 31, w = threadIdx.x >> 5;
#pragma unroll
    for (int o = 16; o; o >>= 1) v = fmaxf(v, __shfl_xor_sync(0xffffffffu, v, o));
    if (lane == 0) sh[w] = v;
    __syncthreads();
    float r = (threadIdx.x < 8) ? sh[threadIdx.x] : -1e30f;
    if (w == 0) {
#pragma unroll
        for (int o = 4; o; o >>= 1) r = fmaxf(r, __shfl_xor_sync(0xffffffffu, r, o));
    }
    __syncthreads();
    if (threadIdx.x == 0) sh[0] = r;
    __syncthreads();
    return sh[0];
}

// =====================================================================
// tf32 mma.sync GEMM: C[M,Nn] = A[M,K] @ W[K,Nn]  (+bias, +relu, +res)
// BM=128, BN=128, BK=32, 256 threads (8 warps, warp tile 64x32)
// smem layout per tile: float tile[32][136], element (k,n) at col n ^ (k & ~3)
// =====================================================================
#define TILE_FLOATS  (32 * 136)            // 4352
#define STAGE_FLOATS (2 * TILE_FLOATS)     // A tile + B tile
#define GEMM_SMEM    (2 * STAGE_FLOATS * 4)  // 69632 bytes

template<bool BIAS, bool RELU, bool RES, bool NALIGN>
__global__ __launch_bounds__(256) void mma_gemm(
    const float* __restrict__ A, const float* __restrict__ W,
    const float* __restrict__ bias, const float* __restrict__ res,
    float* __restrict__ C, int M, int Nn, int K) {
    extern __shared__ float sm[];
    const int tid = threadIdx.x;
    const int warp = tid >> 5, lane = tid & 31;
    const int g = lane >> 2, t4 = lane & 3;
    const int wm = warp >> 2, wn = warp & 3;      // 2 x 4 warp grid
    const int warp_m0 = wm * 64, warp_n0 = wn * 32;
    const int m0 = blockIdx.x * 128;
    const int n0 = blockIdx.y * 128;

    // per-thread load indices
    const int am  = (tid >> 3);          // A: row m within tile (+32*i)
    const int akq = (tid & 7);           // A: float4 index along k
    const int bk  = (tid >> 5);          // B: k row within tile (+8*i)
    const int bnq = (tid & 31);          // B: float4 index along n

    float acc[4][4][4];
#pragma unroll
    for (int mt = 0; mt < 4; mt++)
#pragma unroll
        for (int nt = 0; nt < 4; nt++)
#pragma unroll
            for (int j = 0; j < 4; j++) acc[mt][nt][j] = 0.f;

    const int nk = K >> 5;
    float4 av[4];
    float  bv[4][4];

    // ---- prologue: load tile 0 ----
#pragma unroll
    for (int i = 0; i < 4; i++) {
        int m = am + i * 32;
        av[i] = *(const float4*)(A + (size_t)(m0 + m) * K + akq * 4);
    }
#pragma unroll
    for (int i = 0; i < 4; i++) {
        int k = bk + i * 8;
        int gn = n0 + bnq * 4;
        const float* Wp = W + (size_t)k * Nn + gn;
        if (NALIGN) {
            float4 t = *(const float4*)Wp;
            bv[i][0] = t.x; bv[i][1] = t.y; bv[i][2] = t.z; bv[i][3] = t.w;
        } else {
#pragma unroll
            for (int c = 0; c < 4; c++)
                bv[i][c] = (gn + c < Nn) ? Wp[c] : 0.f;
        }
    }
    // store stage 0
    {
        float* sA = sm;
        float* sB = sm + TILE_FLOATS;
#pragma unroll
        for (int i = 0; i < 4; i++) {
            int m = am + i * 32;
            int col = m ^ (akq * 4);
            sA[(akq * 4 + 0) * 136 + col] = f2tf(av[i].x);
            sA[(akq * 4 + 1) * 136 + col] = f2tf(av[i].y);
            sA[(akq * 4 + 2) * 136 + col] = f2tf(av[i].z);
            sA[(akq * 4 + 3) * 136 + col] = f2tf(av[i].w);
        }
#pragma unroll
        for (int i = 0; i < 4; i++) {
            int k = bk + i * 8;
            int col = (bnq * 4) ^ (k & ~3);
            float4 t = make_float4(f2tf(bv[i][0]), f2tf(bv[i][1]), f2tf(bv[i][2]), f2tf(bv[i][3]));
            *(float4*)(sB + k * 136 + col) = t;
        }
    }
    __syncthreads();

    for (int kc = 0; kc < nk; kc++) {
        const int s = kc & 1;
        const bool more = (kc + 1 < nk);
        // prefetch next tile into regs
        if (more) {
            const int kb = (kc + 1) * 32;
#pragma unroll
            for (int i = 0; i < 4; i++) {
                int m = am + i * 32;
                av[i] = *(const float4*)(A + (size_t)(m0 + m) * K + kb + akq * 4);
            }
#pragma unroll
            for (int i = 0; i < 4; i++) {
                int k = bk + i * 8;
                int gn = n0 + bnq * 4;
                const float* Wp = W + (size_t)(kb + k) * Nn + gn;
                if (NALIGN) {
                    float4 t = *(const float4*)Wp;
                    bv[i][0] = t.x; bv[i][1] = t.y; bv[i][2] = t.z; bv[i][3] = t.w;
                } else {
#pragma unroll
                    for (int c = 0; c < 4; c++)
                        bv[i][c] = (gn + c < Nn) ? Wp[c] : 0.f;
                }
            }
        }
        // compute from stage s
        const float* sA = sm + s * STAGE_FLOATS;
        const float* sB = sA + TILE_FLOATS;
#pragma unroll
        for (int ks = 0; ks < 4; ks++) {
            const int k0 = ks * 8;
            uint32_t af[4][4], bf[4][2];
#pragma unroll
            for (int mt = 0; mt < 4; mt++) {
                int c0 = warp_m0 + mt * 16 + g;
                af[mt][0] = __float_as_uint(sA[(k0 + t4) * 136 + (c0 ^ k0)]);
                af[mt][1] = __float_as_uint(sA[(k0 + t4) * 136 + ((c0 + 8) ^ k0)]);
                af[mt][2] = __float_as_uint(sA[(k0 + 4 + t4) * 136 + (c0 ^ (k0 + 4))]);
                af[mt][3] = __float_as_uint(sA[(k0 + 4 + t4) * 136 + ((c0 + 8) ^ (k0 + 4))]);
            }
#pragma unroll
            for (int nt = 0; nt < 4; nt++) {
                int cn = warp_n0 + nt * 8 + g;
                bf[nt][0] = __float_as_uint(sB[(k0 + t4) * 136 + (cn ^ k0)]);
                bf[nt][1] = __float_as_uint(sB[(k0 + 4 + t4) * 136 + (cn ^ (k0 + 4))]);
            }
#pragma unroll
            for (int mt = 0; mt < 4; mt++)
#pragma unroll
                for (int nt = 0; nt < 4; nt++)
                    mma8(acc[mt][nt], af[mt], bf[nt]);
        }
        // store prefetched tile into stage s^1
        if (more) {
            float* dA = sm + (s ^ 1) * STAGE_FLOATS;
            float* dB = dA + TILE_FLOATS;
#pragma unroll
            for (int i = 0; i < 4; i++) {
                int m = am + i * 32;
                int col = m ^ (akq * 4);
                dA[(akq * 4 + 0) * 136 + col] = f2tf(av[i].x);
                dA[(akq * 4 + 1) * 136 + col] = f2tf(av[i].y);
                dA[(akq * 4 + 2) * 136 + col] = f2tf(av[i].z);
                dA[(akq * 4 + 3) * 136 + col] = f2tf(av[i].w);
            }
#pragma unroll
            for (int i = 0; i < 4; i++) {
                int k = bk + i * 8;
                int col = (bnq * 4) ^ (k & ~3);
                float4 t = make_float4(f2tf(bv[i][0]), f2tf(bv[i][1]), f2tf(bv[i][2]), f2tf(bv[i][3]));
                *(float4*)(dB + k * 136 + col) = t;
            }
        }
        __syncthreads();
    }

    // ---- epilogue ----
#pragma unroll
    for (int mt = 0; mt < 4; mt++) {
        int r0 = m0 + warp_m0 + mt * 16 + g;
#pragma unroll
        for (int nt = 0; nt < 4; nt++) {
            int cn = n0 + warp_n0 + nt * 8 + t4 * 2;
            float* a4 = acc[mt][nt];
            float b0 = 0.f, b1 = 0.f;
            if (BIAS) {
                if (NALIGN) { b0 = bias[cn]; b1 = bias[cn + 1]; }
                else {
                    b0 = (cn < Nn) ? bias[cn] : 0.f;
                    b1 = (cn + 1 < Nn) ? bias[cn + 1] : 0.f;
                }
            }
#pragma unroll
            for (int half = 0; half < 2; half++) {
                int r = r0 + half * 8;
                float v0 = a4[half * 2 + 0] + b0;
                float v1 = a4[half * 2 + 1] + b1;
                if (RELU) { v0 = fmaxf(v0, 0.f); v1 = fmaxf(v1, 0.f); }
                size_t off = (size_t)r * Nn + cn;
                if (NALIGN) {
                    if (RES) { v0 += res[off]; v1 += res[off + 1]; }
                    float2 o = make_float2(v0, v1);
                    *(float2*)(C + off) = o;
                } else {
                    if (cn < Nn) {
                        if (RES) v0 += res[off];
                        C[off] = v0;
                    }
                    if (cn + 1 < Nn) {
                        if (RES) v1 += res[off + 1];
                        C[off + 1] = v1;
                    }
                }
            }
        }
    }
}

// ---------------- embedding ----------------
__global__ void embed_kernel(const int* __restrict__ inp,
                             const float* __restrict__ tok,
                             const float* __restrict__ pos,
                             float* __restrict__ x) {
    int i = blockIdx.x;
    int t = i & (Tt - 1);
    int v = inp[i];
    const float* te = tok + (size_t)v * Cd;
    const float* pe = pos + (size_t)t * Cd;
    float* xo = x + (size_t)i * Cd;
    for (int c = threadIdx.x; c < Cd; c += blockDim.x)
        xo[c] = te[c] + pe[c];
}

// ---------------- layernorm ----------------
__global__ __launch_bounds__(256) void ln_kernel(const float* __restrict__ x,
                                                 const float* __restrict__ g,
                                                 const float* __restrict__ b,
                                                 float* __restrict__ out) {
    int row = blockIdx.x;
    const float* xr = x + (size_t)row * Cd;
    float s = 0.f;
    for (int c = threadIdx.x; c < Cd; c += 256) s += xr[c];
    float mean = blockReduceSum256(s) * (1.0f / Cd);
    float vs = 0.f;
    for (int c = threadIdx.x; c < Cd; c += 256) {
        float d = xr[c] - mean;
        vs += d * d;
    }
    float var = blockReduceSum256(vs) * (1.0f / Cd);
    float rstd = rsqrtf(var + 1e-5f);
    float* orow = out + (size_t)row * Cd;
    for (int c = threadIdx.x; c < Cd; c += 256)
        orow[c] = (xr[c] - mean) * rstd * g[c] + b[c];
}

// ---------------- SIMT SGEMM (loss-only fallback path) ----------------
template<bool BIAS, bool RELU, bool RES>
__global__ __launch_bounds__(256) void sgemm_kernel(
    const float* __restrict__ A, const float* __restrict__ W,
    const float* __restrict__ bias, const float* __restrict__ res,
    float* __restrict__ Cout, int M, int Nn, int K, int ldw) {
    __shared__ float As[16][132];
    __shared__ float Bs[16][64];
    int tid = threadIdx.x;
    int m0 = blockIdx.x * 128;
    int n0 = blockIdx.y * 64;
    int tx = tid & 15, ty = tid >> 4;
    float acc[8][4];
#pragma unroll
    for (int i = 0; i < 8; i++)
#pragma unroll
        for (int j = 0; j < 4; j++) acc[i][j] = 0.f;
    int am = tid >> 1;
    int ak = (tid & 1) * 8;
    int bk = tid >> 4;
    int bn = (tid & 15) * 4;
    bool nvec = ((Nn & 3) == 0) && ((ldw & 3) == 0);
    for (int k0 = 0; k0 < K; k0 += 16) {
        const float* Ap = A + (size_t)(m0 + am) * K + k0 + ak;
        float4 a0 = *(const float4*)Ap;
        float4 a1 = *(const float4*)(Ap + 4);
        As[ak + 0][am] = a0.x; As[ak + 1][am] = a0.y;
        As[ak + 2][am] = a0.z; As[ak + 3][am] = a0.w;
        As[ak + 4][am] = a1.x; As[ak + 5][am] = a1.y;
        As[ak + 6][am] = a1.z; As[ak + 7][am] = a1.w;
        int gn = n0 + bn;
        const float* Wp = W + (size_t)(k0 + bk) * ldw + gn;
        float4 bv;
        if (nvec) {
            bv = (gn < Nn) ? *(const float4*)Wp : make_float4(0.f, 0.f, 0.f, 0.f);
        } else {
            bv.x = (gn + 0 < Nn) ? Wp[0] : 0.f;
            bv.y = (gn + 1 < Nn) ? Wp[1] : 0.f;
            bv.z = (gn + 2 < Nn) ? Wp[2] : 0.f;
            bv.w = (gn + 3 < Nn) ? Wp[3] : 0.f;
        }
        *(float4*)&Bs[bk][bn] = bv;
        __syncthreads();
#pragma unroll
        for (int kk = 0; kk < 16; kk++) {
            float4 a04 = *(const float4*)&As[kk][ty * 8];
            float4 a14 = *(const float4*)&As[kk][ty * 8 + 4];
            float4 b4  = *(const float4*)&Bs[kk][tx * 4];
            float a[8] = {a04.x, a04.y, a04.z, a04.w, a14.x, a14.y, a14.z, a14.w};
            float bb[4] = {b4.x, b4.y, b4.z, b4.w};
#pragma unroll
            for (int i = 0; i < 8; i++)
#pragma unroll
                for (int j = 0; j < 4; j++)
                    acc[i][j] += a[i] * bb[j];
        }
        __syncthreads();
    }
    int nbase = n0 + tx * 4;
#pragma unroll
    for (int i = 0; i < 8; i++) {
        size_t rowoff = (size_t)(m0 + ty * 8 + i) * Nn;
#pragma unroll
        for (int j = 0; j < 4; j++) {
            int n = nbase + j;
            if (n < Nn) {
                float v = acc[i][j];
                if (BIAS) v += bias[n];
                if (RELU) v = fmaxf(v, 0.f);
                if (RES) v += res[rowoff + n];
                Cout[rowoff + n] = v;
            }
        }
    }
}

// ---------------- flash attention (fp32, causal) ----------------
__global__ __launch_bounds__(64) void attn_kernel(const float* __restrict__ Q,
                                                  const float* __restrict__ Kg,
                                                  const float* __restrict__ Vg,
                                                  float* __restrict__ O) {
    __shared__ float4 Ks[64 * 16];
    __shared__ float4 Vs[64 * 16];
    int qt = blockIdx.x;
    int bh = blockIdx.y;
    int b = bh / Hh, h = bh % Hh;
    int tid = threadIdx.x;
    int t = qt * 64 + tid;
    const float scale = 0.125f;

    float4 qreg[16];
    const float4* qp = (const float4*)(Q + (size_t)(b * Tt + t) * Cd + h * HSd);
#pragma unroll
    for (int d = 0; d < 16; d++) qreg[d] = qp[d];

    float o[64];
#pragma unroll
    for (int d = 0; d < 64; d++) o[d] = 0.f;
    float mM = -1e30f, lS = 0.f;

    for (int kt = 0; kt <= qt; kt++) {
        int j0 = kt * 64;
        __syncthreads();
#pragma unroll
        for (int it = 0; it < 16; it++) {
            int r = it * 4 + (tid >> 4);
            int c4 = tid & 15;
            size_t goff = (size_t)(b * Tt + j0 + r) * Cd + h * HSd;
            Ks[r * 16 + c4] = *(const float4*)(Kg + goff + c4 * 4);
            Vs[r * 16 + c4] = *(const float4*)(Vg + goff + c4 * 4);
        }
        __syncthreads();
        int jmax = (kt == qt) ? (tid + 1) : 64;

        float mNew = mM;
        for (int j = 0; j < jmax; j++) {
            float s = 0.f;
#pragma unroll
            for (int d = 0; d < 16; d++) {
                float4 kk = Ks[j * 16 + d];
                float4 qq = qreg[d];
                s += qq.x * kk.x + qq.y * kk.y + qq.z * kk.z + qq.w * kk.w;
            }
            mNew = fmaxf(mNew, s * scale);
        }
        float alpha = __expf(mM - mNew);
        lS *= alpha;
#pragma unroll
        for (int d = 0; d < 64; d++) o[d] *= alpha;
        mM = mNew;

        for (int j = 0; j < jmax; j++) {
            float s = 0.f;
#pragma unroll
            for (int d = 0; d < 16; d++) {
                float4 kk = Ks[j * 16 + d];
                float4 qq = qreg[d];
                s += qq.x * kk.x + qq.y * kk.y + qq.z * kk.z + qq.w * kk.w;
            }
            float p = __expf(s * scale - mM);
            lS += p;
#pragma unroll
            for (int d = 0; d < 16; d++) {
                float4 vv = Vs[j * 16 + d];
                o[d * 4 + 0] += p * vv.x;
                o[d * 4 + 1] += p * vv.y;
                o[d * 4 + 2] += p * vv.z;
                o[d * 4 + 3] += p * vv.w;
            }
        }
    }
    float inv = 1.f / lS;
    float* op = O + (size_t)(b * Tt + t) * Cd + h * HSd;
#pragma unroll
    for (int d = 0; d < 64; d++) op[d] = o[d] * inv;
}

// ---------------- loss kernels ----------------
__global__ __launch_bounds__(256) void rowloss_kernel(const float* __restrict__ logits,
                                                      const int* __restrict__ tgt,
                                                      float* __restrict__ rl) {
    int r = blockIdx.x;
    const float* lr = logits + (size_t)r * Vv;
    float m = -1e30f;
    for (int c = threadIdx.x; c < Vv; c += 256) m = fmaxf(m, lr[c]);
    m = blockReduceMax256(m);
    float s = 0.f;
    for (int c = threadIdx.x; c < Vv; c += 256) s += __expf(lr[c] - m);
    s = blockReduceSum256(s);
    if (threadIdx.x == 0) rl[r] = m + logf(s) - lr[tgt[r]];
}

__global__ __launch_bounds__(256) void lossreduce_kernel(const float* __restrict__ rl,
                                                         float* __restrict__ out) {
    float s = 0.f;
    for (int i = threadIdx.x; i < NT; i += 256) s += rl[i];
    s = blockReduceSum256(s);
    if (threadIdx.x == 0) out[0] = s * (1.0f / NT);
}

__global__ void lse_init_kernel(float* lm, float* ls, float* lt) {
    int i = blockIdx.x * blockDim.x + threadIdx.x;
    if (i < NT) { lm[i] = -1e30f; ls[i] = 0.f; lt[i] = 0.f; }
}

__global__ __launch_bounds__(256) void chunkloss_kernel(const float* __restrict__ chunk,
                                                        int width, int col0,
                                                        const int* __restrict__ tgt,
                                                        float* __restrict__ lm,
                                                        float* __restrict__ ls,
                                                        float* __restrict__ lt) {
    int r = blockIdx.x;
    const float* cr = chunk + (size_t)r * width;
    float m = -1e30f;
    for (int c = threadIdx.x; c < width; c += 256) m = fmaxf(m, cr[c]);
    m = blockReduceMax256(m);
    float s = 0.f;
    for (int c = threadIdx.x; c < width; c += 256) s += __expf(cr[c] - m);
    s = blockReduceSum256(s);
    if (threadIdx.x == 0) {
        float mOld = lm[r];
        float mNew = fmaxf(mOld, m);
        ls[r] = ls[r] * __expf(mOld - mNew) + s * __expf(m - mNew);
        lm[r] = mNew;
        int tg = tgt[r] - col0;
        if (tg >= 0 && tg < width) lt[r] = cr[tg];
    }
}

__global__ void chunkfinal_kernel(const float* lm, const float* ls, const float* lt,
                                  float* rl) {
    int i = blockIdx.x * blockDim.x + threadIdx.x;
    if (i < NT) rl[i] = lm[i] + logf(ls[i]) - lt[i];
}

// ---------------- host driver ----------------
static float* devptr(const void* sym) {
    void* p = nullptr;
    cudaGetSymbolAddress(&p, sym);
    return (float*)p;
}

extern "C" void kernel_launch(void* const* d_in, const int* in_sizes, int n_in,
                              void* d_out, int out_size) {
    const int* inputs    = (const int*)d_in[0];
    const int* targets   = (const int*)d_in[1];
    const float* tok     = (const float*)d_in[2];
    const float* pos     = (const float*)d_in[3];
    const float* ln1g    = (const float*)d_in[4];
    const float* ln1b    = (const float*)d_in[5];
    const float* ln2g    = (const float*)d_in[6];
    const float* ln2b    = (const float*)d_in[7];
    const float* wq      = (const float*)d_in[8];
    const float* wk      = (const float*)d_in[9];
    const float* wv      = (const float*)d_in[10];
    const float* wo      = (const float*)d_in[11];
    const float* bo      = (const float*)d_in[12];
    const float* w1      = (const float*)d_in[13];
    const float* b1      = (const float*)d_in[14];
    const float* w2      = (const float*)d_in[15];
    const float* b2      = (const float*)d_in[16];
    const float* lnfg    = (const float*)d_in[17];
    const float* lnfb    = (const float*)d_in[18];
    const float* whead   = (const float*)d_in[19];
    const float* bhead   = (const float*)d_in[20];

    float* x  = devptr(g_x);
    float* h  = devptr(g_h);
    float* qb = devptr(g_qb);
    float* kb = devptr(g_kb);
    float* vb = devptr(g_vb);
    float* ob = devptr(g_ob);
    float* fb = devptr(g_f);
    float* rl = devptr(g_rowloss);
    float* lm = devptr(g_lm);
    float* ls = devptr(g_ls);
    float* lt = devptr(g_lt);

    // opt in to large dynamic smem (idempotent)
    cudaFuncSetAttribute(mma_gemm<false, false, false, true>, cudaFuncAttributeMaxDynamicSharedMemorySize, GEMM_SMEM);
    cudaFuncSetAttribute(mma_gemm<true, false, true, true>,   cudaFuncAttributeMaxDynamicSharedMemorySize, GEMM_SMEM);
    cudaFuncSetAttribute(mma_gemm<true, true, false, true>,   cudaFuncAttributeMaxDynamicSharedMemorySize, GEMM_SMEM);
    cudaFuncSetAttribute(mma_gemm<true, false, false, false>, cudaFuncAttributeMaxDynamicSharedMemorySize, GEMM_SMEM);

    dim3 gC(NT / 128, Cd / 128);                 // 64 x 6
    dim3 gF(NT / 128, Fd / 128);                 // 64 x 24
    dim3 gV(NT / 128, (Vv + 127) / 128);         // 64 x 393
    dim3 gAttn(Tt / 64, Bq * Hh);

    embed_kernel<<<NT, 256>>>(inputs, tok, pos, x);

    for (int l = 0; l < Ll; l++) {
        const float* wql = wq + (size_t)l * Cd * Cd;
        const float* wkl = wk + (size_t)l * Cd * Cd;
        const float* wvl = wv + (size_t)l * Cd * Cd;
        const float* wol = wo + (size_t)l * Cd * Cd;
        const float* w1l = w1 + (size_t)l * Cd * Fd;
        const float* w2l = w2 + (size_t)l * Fd * Cd;

        ln_kernel<<<NT, 256>>>(x, ln1g + l * Cd, ln1b + l * Cd, h);
        mma_gemm<false, false, false, true><<<gC, 256, GEMM_SMEM>>>(h, wql, nullptr, nullptr, qb, NT, Cd, Cd);
        mma_gemm<false, false, false, true><<<gC, 256, GEMM_SMEM>>>(h, wkl, nullptr, nullptr, kb, NT, Cd, Cd);
        mma_gemm<false, false, false, true><<<gC, 256, GEMM_SMEM>>>(h, wvl, nullptr, nullptr, vb, NT, Cd, Cd);
        attn_kernel<<<gAttn, 64>>>(qb, kb, vb, ob);
        mma_gemm<true, false, true, true><<<gC, 256, GEMM_SMEM>>>(ob, wol, bo + l * Cd, x, x, NT, Cd, Cd);
        ln_kernel<<<NT, 256>>>(x, ln2g + l * Cd, ln2b + l * Cd, h);
        mma_gemm<true, true, false, true><<<gF, 256, GEMM_SMEM>>>(h, w1l, b1 + (size_t)l * Fd, nullptr, fb, NT, Fd, Cd);
        mma_gemm<true, false, true, true><<<gC, 256, GEMM_SMEM>>>(fb, w2l, b2 + l * Cd, x, x, NT, Cd, Fd);
    }

    ln_kernel<<<NT, 256>>>(x, lnfg, lnfb, h);

    const long long NV = (long long)NT * Vv;
    if ((long long)out_size >= NV) {
        float* logits = (float*)d_out;
        mma_gemm<true, false, false, false><<<gV, 256, GEMM_SMEM>>>(h, whead, bhead, nullptr,
                                                                    logits, NT, Vv, Cd);
        if ((long long)out_size > NV) {
            rowloss_kernel<<<NT, 256>>>(logits, targets, rl);
            lossreduce_kernel<<<1, 256>>>(rl, (float*)d_out + NV);
        }
    } else {
        // loss-only fallback: chunked logsumexp through g_f (SIMT path)
        lse_init_kernel<<<(NT + 255) / 256, 256>>>(lm, ls, lt);
        const int CW = 3072;
        for (int col0 = 0; col0 < Vv; col0 += CW) {
            int width = (Vv - col0 < CW) ? (Vv - col0) : CW;
            dim3 gCk(NT / 128, (width + 63) / 64);
            sgemm_kernel<true, false, false><<<gCk, 256>>>(h, whead + col0, bhead + col0,
                                                           nullptr, fb, NT, width, Cd, Vv);
            chunkloss_kernel<<<NT, 256>>>(fb, width, col0, targets, lm, ls, lt);
        }
        chunkfinal_kernel<<<(NT + 255) / 256, 256>>>(lm, ls, lt, rl);
        lossreduce_kernel<<<1, 256>>>(rl, (float*)d_out);
    }
}

// round 4
// speedup vs baseline: 2.7059x; 1.4911x over previous
#include <cuda_runtime.h>
#include <cuda_bf16.h>
#include <math.h>
#include <stdint.h>

// ---------------- problem constants (GPT-2 small forward) ----------------
#define Bq   8
#define Tt   1024
#define NT   8192          // B*T tokens
#define Cd   768
#define Hh   12
#define HSd  64
#define Fd   3072
#define Ll   12
#define Vv   50257
#define VPAD 50304         // multiple of 128 and 16B-aligned rows
#define QKVS 2304          // fused qkv width

// ---------------- scratch (device globals: allocation-free) --------------
__device__ float g_x[(size_t)NT * Cd];       // residual stream
__device__ float g_h[(size_t)NT * Cd];       // LN output (tf32-rounded)
__device__ float g_qkv[(size_t)NT * QKVS];   // fused q|k|v
__device__ float g_ob[(size_t)NT * Cd];
__device__ float g_f[(size_t)NT * Fd];       // MLP hidden / logits chunks
__device__ float g_rowloss[NT];
__device__ float g_lm[NT];
__device__ float g_ls[NT];
__device__ float g_lt[NT];

// pre-rounded (tf32) weights
#define OFF_QKV ((size_t)0)                    // [L][768][2304]
#define OFF_WO  ((size_t)21233664)             // [L][768][768]
#define OFF_W1  ((size_t)28311552)             // [L][768][3072]
#define OFF_W2  ((size_t)56623104)             // [L][3072][768]
#define OFF_HD  ((size_t)84934656)             // [768][VPAD]
#define WT_TOTAL ((size_t)84934656 + (size_t)Cd * VPAD)
__device__ float g_wt[WT_TOTAL];

// ---------------- helpers ----------------
__device__ __forceinline__ float f2tf(float x) {
    uint32_t u;
    asm("cvt.rna.tf32.f32 %0, %1;" : "=r"(u) : "f"(x));
    return __uint_as_float(u);
}

__device__ __forceinline__ uint32_t smem_u32(const void* p) {
    uint32_t a;
    asm("{ .reg .u64 t; cvta.to.shared.u64 t, %1; cvt.u32.u64 %0, t; }" : "=r"(a) : "l"(p));
    return a;
}

__device__ __forceinline__ void cp16(uint32_t saddr, const void* gaddr) {
    asm volatile("cp.async.cg.shared.global [%0], [%1], 16;" :: "r"(saddr), "l"(gaddr));
}
#define CP_COMMIT() asm volatile("cp.async.commit_group;" ::: "memory")
#define CP_WAIT1()  asm volatile("cp.async.wait_group 1;" ::: "memory")
#define CP_WAIT0()  asm volatile("cp.async.wait_group 0;" ::: "memory")

__device__ __forceinline__ void mma8(float* c, const uint32_t* a, const uint32_t* b) {
    asm volatile(
        "mma.sync.aligned.m16n8k8.row.col.f32.tf32.tf32.f32 "
        "{%0,%1,%2,%3}, {%4,%5,%6,%7}, {%8,%9}, {%0,%1,%2,%3};\n"
        : "+f"(c[0]), "+f"(c[1]), "+f"(c[2]), "+f"(c[3])
        : "r"(a[0]), "r"(a[1]), "r"(a[2]), "r"(a[3]), "r"(b[0]), "r"(b[1]));
}

// ---------------- block reduce helpers ----------------
__device__ __forceinline__ float blockReduceSum256(float v) {
    __shared__ float sh[8];
    int lane = threadIdx.x & 31, w = threadIdx.x >> 5;
#pragma unroll
    for (int o = 16; o; o >>= 1) v += __shfl_xor_sync(0xffffffffu, v, o);
    if (lane == 0) sh[w] = v;
    __syncthreads();
    float r = (threadIdx.x < 8) ? sh[threadIdx.x] : 0.f;
    if (w == 0) {
#pragma unroll
        for (int o = 4; o; o >>= 1) r += __shfl_xor_sync(0xffffffffu, r, o);
    }
    __syncthreads();
    if (threadIdx.x == 0) sh[0] = r;
    __syncthreads();
    return sh[0];
}

__device__ __forceinline__ float blockReduceMax256(float v) {
    __shared__ float sh[8];
    int lane = threadIdx.x & 31, w = threadIdx.x >> 5;
#pragma unroll
    for (int o = 16; o; o >>= 1) v = fmaxf(v, __shfl_xor_sync(0xffffffffu, v, o));
    if (lane == 0) sh[w] = v;
    __syncthreads();
    float r = (threadIdx.x < 8) ? sh[threadIdx.x] : -1e30f;
    if (w == 0) {
#pragma unroll
        for (int o = 4; o; o >>= 1) r = fmaxf(r, __shfl_xor_sync(0xffffffffu, r, o));
    }
    __syncthreads();
    if (threadIdx.x == 0) sh[0] = r;
    __syncthreads();
    return sh[0];
}

// ---------------- weight prep (per-launch, deterministic) ----------------
__global__ void qkvpack_kernel(const float* __restrict__ src, float* __restrict__ dst, int sel) {
    size_t n = (size_t)Ll * Cd * Cd;
    for (size_t i = (size_t)blockIdx.x * blockDim.x + threadIdx.x; i < n;
         i += (size_t)gridDim.x * blockDim.x) {
        size_t l = i / ((size_t)Cd * Cd);
        size_t rem = i - l * (size_t)Cd * Cd;
        size_t k = rem / Cd, nn = rem - k * Cd;
        dst[l * ((size_t)Cd * QKVS) + k * QKVS + (size_t)sel * Cd + nn] = f2tf(src[i]);
    }
}

__global__ void roundcopy_kernel(const float* __restrict__ src, float* __restrict__ dst, size_t n) {
    for (size_t i = (size_t)blockIdx.x * blockDim.x + threadIdx.x; i < n;
         i += (size_t)gridDim.x * blockDim.x)
        dst[i] = f2tf(src[i]);
}

__global__ void headpad_kernel(const float* __restrict__ src, float* __restrict__ dst) {
    int k = blockIdx.y;
    int n = blockIdx.x * 256 + threadIdx.x;
    if (n < VPAD)
        dst[(size_t)k * VPAD + n] = (n < Vv) ? f2tf(src[(size_t)k * Vv + n]) : 0.f;
}

// =====================================================================
// tf32 mma.sync GEMM v2: C[M,Nn] = A[M,K] @ W[K,ldw slice]
// BM=128, BN=128, BK=32, 256 threads (8 warps, warp tile 64x32)
// cp.async double-buffered; A smem [128][36], B smem [32][136] (pad, no XOR)
// Inputs assumed already tf32-rounded.
// =====================================================================
#define ASTR 36
#define BSTR 136
#define ATILE_F (128 * ASTR)              // 4608 floats
#define BTILE_F (32 * BSTR)               // 4352 floats
#define STG_F   (ATILE_F + BTILE_F)       // 8960 floats
#define GEMM_SMEM (2 * STG_F * 4)         // 71680 bytes

template<bool BIAS, bool RELU, bool RES, bool NBOUND, bool RND>
__global__ __launch_bounds__(256, 2) void mma_gemm(
    const float* __restrict__ A, const float* __restrict__ W,
    const float* __restrict__ bias, const float* __restrict__ res,
    float* __restrict__ C, int M, int Nn, int K, int ldw) {
    extern __shared__ float sm[];
    const uint32_t su = smem_u32(sm);
    const int tid = threadIdx.x;
    const int warp = tid >> 5, lane = tid & 31;
    const int g = lane >> 2, t4 = lane & 3;
    const int wm = warp >> 2, wn = warp & 3;
    const int warp_m0 = wm * 64, warp_n0 = wn * 32;
    const int m0 = blockIdx.x * 128;
    const int n0 = blockIdx.y * 128;

    float acc[4][4][4];
#pragma unroll
    for (int mt = 0; mt < 4; mt++)
#pragma unroll
        for (int nt = 0; nt < 4; nt++)
#pragma unroll
            for (int j = 0; j < 4; j++) acc[mt][nt][j] = 0.f;

    const int nk = K >> 5;

    // async stage loader
    auto load_stage = [&](int s, int kb) {
        uint32_t sa = su + (uint32_t)s * STG_F * 4;
#pragma unroll
        for (int i = 0; i < 4; i++) {
            int ch = tid + i * 256;
            int r = ch >> 3, c = ch & 7;
            cp16(sa + (uint32_t)(r * ASTR + c * 4) * 4,
                 A + (size_t)(m0 + r) * K + kb + c * 4);
        }
        uint32_t sb = sa + ATILE_F * 4;
#pragma unroll
        for (int i = 0; i < 4; i++) {
            int ch = tid + i * 256;
            int r = ch >> 5, c = ch & 31;
            cp16(sb + (uint32_t)(r * BSTR + c * 4) * 4,
                 W + (size_t)(kb + r) * ldw + n0 + c * 4);
        }
        CP_COMMIT();
    };

    load_stage(0, 0);
    load_stage(1, 32);

    for (int kc = 0; kc < nk; kc++) {
        const int s = kc & 1;
        if (kc == nk - 1) CP_WAIT0(); else CP_WAIT1();
        __syncthreads();

        const float* sA = sm + s * STG_F;
        const float* sB = sA + ATILE_F;
#pragma unroll
        for (int ks = 0; ks < 4; ks++) {
            const int k0 = ks * 8;
            uint32_t af[4][4], bf[4][2];
#pragma unroll
            for (int mt = 0; mt < 4; mt++) {
                int r0 = warp_m0 + mt * 16 + g;
                af[mt][0] = __float_as_uint(sA[r0 * ASTR + k0 + t4]);
                af[mt][1] = __float_as_uint(sA[(r0 + 8) * ASTR + k0 + t4]);
                af[mt][2] = __float_as_uint(sA[r0 * ASTR + k0 + t4 + 4]);
                af[mt][3] = __float_as_uint(sA[(r0 + 8) * ASTR + k0 + t4 + 4]);
            }
#pragma unroll
            for (int nt = 0; nt < 4; nt++) {
                int cn = warp_n0 + nt * 8 + g;
                bf[nt][0] = __float_as_uint(sB[(k0 + t4) * BSTR + cn]);
                bf[nt][1] = __float_as_uint(sB[(k0 + t4 + 4) * BSTR + cn]);
            }
#pragma unroll
            for (int mt = 0; mt < 4; mt++)
#pragma unroll
                for (int nt = 0; nt < 4; nt++)
                    mma8(acc[mt][nt], af[mt], bf[nt]);
        }

        if (kc + 2 < nk) {
            __syncthreads();
            load_stage(s, (kc + 2) * 32);
        }
    }

    // ---- epilogue ----
#pragma unroll
    for (int mt = 0; mt < 4; mt++) {
        int r0 = m0 + warp_m0 + mt * 16 + g;
#pragma unroll
        for (int nt = 0; nt < 4; nt++) {
            int cn = n0 + warp_n0 + nt * 8 + t4 * 2;
            float* a4 = acc[mt][nt];
            float b0 = 0.f, b1 = 0.f;
            if (BIAS) {
                if (!NBOUND) { b0 = bias[cn]; b1 = bias[cn + 1]; }
                else {
                    b0 = (cn < Nn) ? bias[cn] : 0.f;
                    b1 = (cn + 1 < Nn) ? bias[cn + 1] : 0.f;
                }
            }
#pragma unroll
            for (int half = 0; half < 2; half++) {
                int r = r0 + half * 8;
                float v0 = a4[half * 2 + 0] + b0;
                float v1 = a4[half * 2 + 1] + b1;
                if (RELU) { v0 = fmaxf(v0, 0.f); v1 = fmaxf(v1, 0.f); }
                size_t off = (size_t)r * Nn + cn;
                if (!NBOUND) {
                    if (RES) { v0 += res[off]; v1 += res[off + 1]; }
                    if (RND) { v0 = f2tf(v0); v1 = f2tf(v1); }
                    float2 o = make_float2(v0, v1);
                    *(float2*)(C + off) = o;
                } else {
                    if (cn < Nn) {
                        if (RES) v0 += res[off];
                        if (RND) v0 = f2tf(v0);
                        C[off] = v0;
                    }
                    if (cn + 1 < Nn) {
                        if (RES) v1 += res[off + 1];
                        if (RND) v1 = f2tf(v1);
                        C[off + 1] = v1;
                    }
                }
            }
        }
    }
}

// ---------------- embedding ----------------
__global__ void embed_kernel(const int* __restrict__ inp,
                             const float* __restrict__ tok,
                             const float* __restrict__ pos,
                             float* __restrict__ x) {
    int i = blockIdx.x;
    int t = i & (Tt - 1);
    int v = inp[i];
    const float* te = tok + (size_t)v * Cd;
    const float* pe = pos + (size_t)t * Cd;
    float* xo = x + (size_t)i * Cd;
    for (int c = threadIdx.x; c < Cd; c += blockDim.x)
        xo[c] = te[c] + pe[c];
}

// ---------------- layernorm (emits tf32-rounded output) ----------------
__global__ __launch_bounds__(256) void ln_kernel(const float* __restrict__ x,
                                                 const float* __restrict__ g,
                                                 const float* __restrict__ b,
                                                 float* __restrict__ out) {
    int row = blockIdx.x;
    const float* xr = x + (size_t)row * Cd;
    float s = 0.f;
    for (int c = threadIdx.x; c < Cd; c += 256) s += xr[c];
    float mean = blockReduceSum256(s) * (1.0f / Cd);
    float vs = 0.f;
    for (int c = threadIdx.x; c < Cd; c += 256) {
        float d = xr[c] - mean;
        vs += d * d;
    }
    float var = blockReduceSum256(vs) * (1.0f / Cd);
    float rstd = rsqrtf(var + 1e-5f);
    float* orow = out + (size_t)row * Cd;
    for (int c = threadIdx.x; c < Cd; c += 256)
        orow[c] = f2tf((xr[c] - mean) * rstd * g[c] + b[c]);
}

// ---------------- SIMT SGEMM (loss-only fallback path) ----------------
template<bool BIAS, bool RELU, bool RES>
__global__ __launch_bounds__(256) void sgemm_kernel(
    const float* __restrict__ A, const float* __restrict__ W,
    const float* __restrict__ bias, const float* __restrict__ res,
    float* __restrict__ Cout, int M, int Nn, int K, int ldw) {
    __shared__ float As[16][132];
    __shared__ float Bs[16][64];
    int tid = threadIdx.x;
    int m0 = blockIdx.x * 128;
    int n0 = blockIdx.y * 64;
    int tx = tid & 15, ty = tid >> 4;
    float acc[8][4];
#pragma unroll
    for (int i = 0; i < 8; i++)
#pragma unroll
        for (int j = 0; j < 4; j++) acc[i][j] = 0.f;
    int am = tid >> 1;
    int ak = (tid & 1) * 8;
    int bk = tid >> 4;
    int bn = (tid & 15) * 4;
    for (int k0 = 0; k0 < K; k0 += 16) {
        const float* Ap = A + (size_t)(m0 + am) * K + k0 + ak;
        float4 a0 = *(const float4*)Ap;
        float4 a1 = *(const float4*)(Ap + 4);
        As[ak + 0][am] = a0.x; As[ak + 1][am] = a0.y;
        As[ak + 2][am] = a0.z; As[ak + 3][am] = a0.w;
        As[ak + 4][am] = a1.x; As[ak + 5][am] = a1.y;
        As[ak + 6][am] = a1.z; As[ak + 7][am] = a1.w;
        int gn = n0 + bn;
        const float* Wp = W + (size_t)(k0 + bk) * ldw + gn;
        float4 bv;
        bv.x = (gn + 0 < Nn) ? Wp[0] : 0.f;
        bv.y = (gn + 1 < Nn) ? Wp[1] : 0.f;
        bv.z = (gn + 2 < Nn) ? Wp[2] : 0.f;
        bv.w = (gn + 3 < Nn) ? Wp[3] : 0.f;
        *(float4*)&Bs[bk][bn] = bv;
        __syncthreads();
#pragma unroll
        for (int kk = 0; kk < 16; kk++) {
            float4 a04 = *(const float4*)&As[kk][ty * 8];
            float4 a14 = *(const float4*)&As[kk][ty * 8 + 4];
            float4 b4  = *(const float4*)&Bs[kk][tx * 4];
            float a[8] = {a04.x, a04.y, a04.z, a04.w, a14.x, a14.y, a14.z, a14.w};
            float bb[4] = {b4.x, b4.y, b4.z, b4.w};
#pragma unroll
            for (int i = 0; i < 8; i++)
#pragma unroll
                for (int j = 0; j < 4; j++)
                    acc[i][j] += a[i] * bb[j];
        }
        __syncthreads();
    }
    int nbase = n0 + tx * 4;
#pragma unroll
    for (int i = 0; i < 8; i++) {
        size_t rowoff = (size_t)(m0 + ty * 8 + i) * Nn;
#pragma unroll
        for (int j = 0; j < 4; j++) {
            int n = nbase + j;
            if (n < Nn) {
                float v = acc[i][j];
                if (BIAS) v += bias[n];
                if (RELU) v = fmaxf(v, 0.f);
                if (RES) v += res[rowoff + n];
                Cout[rowoff + n] = v;
            }
        }
    }
}

// ---------------- flash attention (fp32, causal, smem score cache) -------
// grid: (T/64, B*H), block: 64 threads, one query per thread
// dyn smem: Ks 16KB | Vs 16KB | scores 64*65*4
#define ATTN_SMEM (16384 + 16384 + 64 * 65 * 4)
__global__ __launch_bounds__(64) void attn_kernel(const float* __restrict__ QKV,
                                                  float* __restrict__ O) {
    extern __shared__ float asmem[];
    float4* Ks = (float4*)asmem;
    float4* Vs = Ks + 1024;
    float* sc = (float*)(Vs + 1024);

    int qt = gridDim.x - 1 - blockIdx.x;   // big tiles first (tail balance)
    int bh = blockIdx.y;
    int b = bh / Hh, h = bh % Hh;
    int tid = threadIdx.x;
    int t = qt * 64 + tid;
    const float scale = 0.125f;

    float4 qreg[16];
    const float4* qp = (const float4*)(QKV + (size_t)(b * Tt + t) * QKVS + h * HSd);
#pragma unroll
    for (int d = 0; d < 16; d++) qreg[d] = qp[d];

    float o[64];
#pragma unroll
    for (int d = 0; d < 64; d++) o[d] = 0.f;
    float mM = -1e30f, lS = 0.f;

    for (int kt = 0; kt <= qt; kt++) {
        int j0 = kt * 64;
        __syncthreads();
#pragma unroll
        for (int it = 0; it < 16; it++) {
            int r = it * 4 + (tid >> 4);
            int c4 = tid & 15;
            size_t goff = (size_t)(b * Tt + j0 + r) * QKVS + h * HSd;
            Ks[r * 16 + c4] = *(const float4*)(QKV + goff + Cd + c4 * 4);
            Vs[r * 16 + c4] = *(const float4*)(QKV + goff + 2 * Cd + c4 * 4);
        }
        __syncthreads();
        int jmax = (kt == qt) ? (tid + 1) : 64;

        float mNew = mM;
        for (int j = 0; j < jmax; j++) {
            float s = 0.f;
#pragma unroll
            for (int d = 0; d < 16; d++) {
                float4 kk = Ks[j * 16 + d];
                float4 qq = qreg[d];
                s += qq.x * kk.x + qq.y * kk.y + qq.z * kk.z + qq.w * kk.w;
            }
            s *= scale;
            sc[tid * 65 + j] = s;
            mNew = fmaxf(mNew, s);
        }
        float alpha = __expf(mM - mNew);
        lS *= alpha;
#pragma unroll
        for (int d = 0; d < 64; d++) o[d] *= alpha;
        mM = mNew;

        for (int j = 0; j < jmax; j++) {
            float p = __expf(sc[tid * 65 + j] - mM);
            lS += p;
#pragma unroll
            for (int d = 0; d < 16; d++) {
                float4 vv = Vs[j * 16 + d];
                o[d * 4 + 0] += p * vv.x;
                o[d * 4 + 1] += p * vv.y;
                o[d * 4 + 2] += p * vv.z;
                o[d * 4 + 3] += p * vv.w;
            }
        }
    }
    float inv = 1.f / lS;
    float* op = O + (size_t)(b * Tt + t) * Cd + h * HSd;
#pragma unroll
    for (int d = 0; d < 64; d++) op[d] = f2tf(o[d] * inv);   // rounded: feeds proj GEMM
}

// ---------------- loss kernels ----------------
__global__ __launch_bounds__(256) void rowloss_kernel(const float* __restrict__ logits,
                                                      const int* __restrict__ tgt,
                                                      float* __restrict__ rl) {
    int r = blockIdx.x;
    const float* lr = logits + (size_t)r * Vv;
    float m = -1e30f;
    for (int c = threadIdx.x; c < Vv; c += 256) m = fmaxf(m, lr[c]);
    m = blockReduceMax256(m);
    float s = 0.f;
    for (int c = threadIdx.x; c < Vv; c += 256) s += __expf(lr[c] - m);
    s = blockReduceSum256(s);
    if (threadIdx.x == 0) rl[r] = m + logf(s) - lr[tgt[r]];
}

__global__ __launch_bounds__(256) void lossreduce_kernel(const float* __restrict__ rl,
                                                         float* __restrict__ out) {
    float s = 0.f;
    for (int i = threadIdx.x; i < NT; i += 256) s += rl[i];
    s = blockReduceSum256(s);
    if (threadIdx.x == 0) out[0] = s * (1.0f / NT);
}

__global__ void lse_init_kernel(float* lm, float* ls, float* lt) {
    int i = blockIdx.x * blockDim.x + threadIdx.x;
    if (i < NT) { lm[i] = -1e30f; ls[i] = 0.f; lt[i] = 0.f; }
}

__global__ __launch_bounds__(256) void chunkloss_kernel(const float* __restrict__ chunk,
                                                        int width, int col0,
                                                        const int* __restrict__ tgt,
                                                        float* __restrict__ lm,
                                                        float* __restrict__ ls,
                                                        float* __restrict__ lt) {
    int r = blockIdx.x;
    const float* cr = chunk + (size_t)r * width;
    float m = -1e30f;
    for (int c = threadIdx.x; c < width; c += 256) m = fmaxf(m, cr[c]);
    m = blockReduceMax256(m);
    float s = 0.f;
    for (int c = threadIdx.x; c < width; c += 256) s += __expf(cr[c] - m);
    s = blockReduceSum256(s);
    if (threadIdx.x == 0) {
        float mOld = lm[r];
        float mNew = fmaxf(mOld, m);
        ls[r] = ls[r] * __expf(mOld - mNew) + s * __expf(m - mNew);
        lm[r] = mNew;
        int tg = tgt[r] - col0;
        if (tg >= 0 && tg < width) lt[r] = cr[tg];
    }
}

__global__ void chunkfinal_kernel(const float* lm, const float* ls, const float* lt,
                                  float* rl) {
    int i = blockIdx.x * blockDim.x + threadIdx.x;
    if (i < NT) rl[i] = lm[i] + logf(ls[i]) - lt[i];
}

// ---------------- host driver ----------------
static float* devptr(const void* sym) {
    void* p = nullptr;
    cudaGetSymbolAddress(&p, sym);
    return (float*)p;
}

extern "C" void kernel_launch(void* const* d_in, const int* in_sizes, int n_in,
                              void* d_out, int out_size) {
    const int* inputs    = (const int*)d_in[0];
    const int* targets   = (const int*)d_in[1];
    const float* tok     = (const float*)d_in[2];
    const float* pos     = (const float*)d_in[3];
    const float* ln1g    = (const float*)d_in[4];
    const float* ln1b    = (const float*)d_in[5];
    const float* ln2g    = (const float*)d_in[6];
    const float* ln2b    = (const float*)d_in[7];
    const float* wq      = (const float*)d_in[8];
    const float* wk      = (const float*)d_in[9];
    const float* wv      = (const float*)d_in[10];
    const float* wo      = (const float*)d_in[11];
    const float* bo      = (const float*)d_in[12];
    const float* w1      = (const float*)d_in[13];
    const float* b1      = (const float*)d_in[14];
    const float* w2      = (const float*)d_in[15];
    const float* b2      = (const float*)d_in[16];
    const float* lnfg    = (const float*)d_in[17];
    const float* lnfb    = (const float*)d_in[18];
    const float* whead   = (const float*)d_in[19];
    const float* bhead   = (const float*)d_in[20];

    float* x   = devptr(g_x);
    float* h   = devptr(g_h);
    float* qkv = devptr(g_qkv);
    float* ob  = devptr(g_ob);
    float* fb  = devptr(g_f);
    float* rl  = devptr(g_rowloss);
    float* lm  = devptr(g_lm);
    float* ls  = devptr(g_ls);
    float* lt  = devptr(g_lt);
    float* wt  = devptr(g_wt);

    cudaFuncSetAttribute(mma_gemm<false, false, false, false, false>, cudaFuncAttributeMaxDynamicSharedMemorySize, GEMM_SMEM);
    cudaFuncSetAttribute(mma_gemm<true, false, true, false, false>,   cudaFuncAttributeMaxDynamicSharedMemorySize, GEMM_SMEM);
    cudaFuncSetAttribute(mma_gemm<true, true, false, false, true>,    cudaFuncAttributeMaxDynamicSharedMemorySize, GEMM_SMEM);
    cudaFuncSetAttribute(mma_gemm<true, false, false, true, false>,   cudaFuncAttributeMaxDynamicSharedMemorySize, GEMM_SMEM);
    cudaFuncSetAttribute(attn_kernel, cudaFuncAttributeMaxDynamicSharedMemorySize, ATTN_SMEM);

    // ---- weight prep: tf32-round (and pack/pad) once per launch ----
    qkvpack_kernel<<<2048, 256>>>(wq, wt + OFF_QKV, 0);
    qkvpack_kernel<<<2048, 256>>>(wk, wt + OFF_QKV, 1);
    qkvpack_kernel<<<2048, 256>>>(wv, wt + OFF_QKV, 2);
    roundcopy_kernel<<<2048, 256>>>(wo, wt + OFF_WO, (size_t)Ll * Cd * Cd);
    roundcopy_kernel<<<4096, 256>>>(w1, wt + OFF_W1, (size_t)Ll * Cd * Fd);
    roundcopy_kernel<<<4096, 256>>>(w2, wt + OFF_W2, (size_t)Ll * Fd * Cd);
    {
        dim3 gHp((VPAD + 255) / 256, Cd);
        headpad_kernel<<<gHp, 256>>>(whead, wt + OFF_HD);
    }

    dim3 gQKV(NT / 128, QKVS / 128);             // 64 x 18
    dim3 gC(NT / 128, Cd / 128);                 // 64 x 6
    dim3 gF(NT / 128, Fd / 128);                 // 64 x 24
    dim3 gV(NT / 128, (Vv + 127) / 128);         // 64 x 393
    dim3 gAttn(Tt / 64, Bq * Hh);

    embed_kernel<<<NT, 256>>>(inputs, tok, pos, x);

    for (int l = 0; l < Ll; l++) {
        const float* wqkv = wt + OFF_QKV + (size_t)l * Cd * QKVS;
        const float* wot  = wt + OFF_WO + (size_t)l * Cd * Cd;
        const float* w1t  = wt + OFF_W1 + (size_t)l * Cd * Fd;
        const float* w2t  = wt + OFF_W2 + (size_t)l * Fd * Cd;

        ln_kernel<<<NT, 256>>>(x, ln1g + l * Cd, ln1b + l * Cd, h);
        mma_gemm<false, false, false, false, false><<<gQKV, 256, GEMM_SMEM>>>(
            h, wqkv, nullptr, nullptr, qkv, NT, QKVS, Cd, QKVS);
        attn_kernel<<<gAttn, 64, ATTN_SMEM>>>(qkv, ob);
        mma_gemm<true, false, true, false, false><<<gC, 256, GEMM_SMEM>>>(
            ob, wot, bo + l * Cd, x, x, NT, Cd, Cd, Cd);
        ln_kernel<<<NT, 256>>>(x, ln2g + l * Cd, ln2b + l * Cd, h);
        mma_gemm<true, true, false, false, true><<<gF, 256, GEMM_SMEM>>>(
            h, w1t, b1 + (size_t)l * Fd, nullptr, fb, NT, Fd, Cd, Fd);
        mma_gemm<true, false, true, false, false><<<gC, 256, GEMM_SMEM>>>(
            fb, w2t, b2 + l * Cd, x, x, NT, Cd, Fd, Cd);
    }

    ln_kernel<<<NT, 256>>>(x, lnfg, lnfb, h);

    const long long NV = (long long)NT * Vv;
    if ((long long)out_size >= NV) {
        float* logits = (float*)d_out;
        mma_gemm<true, false, false, true, false><<<gV, 256, GEMM_SMEM>>>(
            h, wt + OFF_HD, bhead, nullptr, logits, NT, Vv, Cd, VPAD);
        if ((long long)out_size > NV) {
            rowloss_kernel<<<NT, 256>>>(logits, targets, rl);
            lossreduce_kernel<<<1, 256>>>(rl, (float*)d_out + NV);
        }
    } else {
        // loss-only fallback: chunked logsumexp through g_f (SIMT path)
        lse_init_kernel<<<(NT + 255) / 256, 256>>>(lm, ls, lt);
        const int CW = 3072;
        for (int col0 = 0; col0 < Vv; col0 += CW) {
            int width = (Vv - col0 < CW) ? (Vv - col0) : CW;
            dim3 gCk(NT / 128, (width + 63) / 64);
            sgemm_kernel<true, false, false><<<gCk, 256>>>(h, whead + col0, bhead + col0,
                                                           nullptr, fb, NT, width, Cd, Vv);
            chunkloss_kernel<<<NT, 256>>>(fb, width, col0, targets, lm, ls, lt);
        }
        chunkfinal_kernel<<<(NT + 255) / 256, 256>>>(lm, ls, lt, rl);
        lossreduce_kernel<<<1, 256>>>(rl, (float*)d_out);
    }
}

// round 5
// speedup vs baseline: 3.5172x; 1.2998x over previous
#include <cuda_runtime.h>
#include <cuda_bf16.h>
#include <math.h>
#include <stdint.h>

// ---------------- problem constants (GPT-2 small forward) ----------------
#define Bq   8
#define Tt   1024
#define NT   8192          // B*T tokens
#define Cd   768
#define Hh   12
#define HSd  64
#define Fd   3072
#define Ll   12
#define Vv   50257
#define VPAD 50304         // multiple of 128
#define QKVS 2304          // fused qkv width

// ---------------- scratch (device globals: allocation-free) --------------
__device__ float g_x[(size_t)NT * Cd];       // residual stream
__device__ float g_h[(size_t)NT * Cd];       // LN output (tf32-rounded)
__device__ float g_qkv[(size_t)NT * QKVS];   // fused q|k|v
__device__ float g_ob[(size_t)NT * Cd];
__device__ float g_f[(size_t)NT * Fd];       // MLP hidden / logits chunks
__device__ float g_rowloss[NT];
__device__ float g_lm[NT];
__device__ float g_ls[NT];
__device__ float g_lt[NT];

// pre-rounded (tf32) weights
#define OFF_QKV ((size_t)0)                    // [L][768][2304]
#define OFF_WO  ((size_t)21233664)             // [L][768][768]
#define OFF_W1  ((size_t)28311552)             // [L][768][3072]
#define OFF_W2  ((size_t)56623104)             // [L][3072][768]
#define OFF_HD  ((size_t)84934656)             // [768][VPAD]
#define WT_TOTAL ((size_t)84934656 + (size_t)Cd * VPAD)
__device__ float g_wt[WT_TOTAL];

// ---------------- helpers ----------------
__device__ __forceinline__ float f2tf(float x) {
    uint32_t u;
    asm("cvt.rna.tf32.f32 %0, %1;" : "=r"(u) : "f"(x));
    return __uint_as_float(u);
}

__device__ __forceinline__ uint32_t smem_u32(const void* p) {
    uint32_t a;
    asm("{ .reg .u64 t; cvta.to.shared.u64 t, %1; cvt.u32.u64 %0, t; }" : "=r"(a) : "l"(p));
    return a;
}

__device__ __forceinline__ void cp16(uint32_t saddr, const void* gaddr) {
    asm volatile("cp.async.cg.shared.global [%0], [%1], 16;" :: "r"(saddr), "l"(gaddr));
}
#define CP_COMMIT() asm volatile("cp.async.commit_group;" ::: "memory")
#define CP_WAIT1()  asm volatile("cp.async.wait_group 1;" ::: "memory")
#define CP_WAIT0()  asm volatile("cp.async.wait_group 0;" ::: "memory")

__device__ __forceinline__ void mma8(float* c, const uint32_t* a, const uint32_t* b) {
    asm volatile(
        "mma.sync.aligned.m16n8k8.row.col.f32.tf32.tf32.f32 "
        "{%0,%1,%2,%3}, {%4,%5,%6,%7}, {%8,%9}, {%0,%1,%2,%3};\n"
        : "+f"(c[0]), "+f"(c[1]), "+f"(c[2]), "+f"(c[3])
        : "r"(a[0]), "r"(a[1]), "r"(a[2]), "r"(a[3]), "r"(b[0]), "r"(b[1]));
}

// ---------------- block reduce helpers ----------------
__device__ __forceinline__ float blockReduceSum256(float v) {
    __shared__ float sh[8];
    int lane = threadIdx.x & 31, w = threadIdx.x >> 5;
#pragma unroll
    for (int o = 16; o; o >>= 1) v += __shfl_xor_sync(0xffffffffu, v, o);
    if (lane == 0) sh[w] = v;
    __syncthreads();
    float r = (threadIdx.x < 8) ? sh[threadIdx.x] : 0.f;
    if (w == 0) {
#pragma unroll
        for (int o = 4; o; o >>= 1) r += __shfl_xor_sync(0xffffffffu, r, o);
    }
    __syncthreads();
    if (threadIdx.x == 0) sh[0] = r;
    __syncthreads();
    return sh[0];
}

__device__ __forceinline__ float blockReduceMax256(float v) {
    __shared__ float sh[8];
    int lane = threadIdx.x & 31, w = threadIdx.x >> 5;
#pragma unroll
    for (int o = 16; o; o >>= 1) v = fmaxf(v, __shfl_xor_sync(0xffffffffu, v, o));
    if (lane == 0) sh[w] = v;
    __syncthreads();
    float r = (threadIdx.x < 8) ? sh[threadIdx.x] : -1e30f;
    if (w == 0) {
#pragma unroll
        for (int o = 4; o; o >>= 1) r = fmaxf(r, __shfl_xor_sync(0xffffffffu, r, o));
    }
    __syncthreads();
    if (threadIdx.x == 0) sh[0] = r;
    __syncthreads();
    return sh[0];
}

// ---------------- weight prep (per-launch, deterministic) ----------------
__global__ void qkvpack_kernel(const float* __restrict__ src, float* __restrict__ dst, int sel) {
    size_t n = (size_t)Ll * Cd * Cd;
    for (size_t i = (size_t)blockIdx.x * blockDim.x + threadIdx.x; i < n;
         i += (size_t)gridDim.x * blockDim.x) {
        size_t l = i / ((size_t)Cd * Cd);
        size_t rem = i - l * (size_t)Cd * Cd;
        size_t k = rem / Cd, nn = rem - k * Cd;
        dst[l * ((size_t)Cd * QKVS) + k * QKVS + (size_t)sel * Cd + nn] = f2tf(src[i]);
    }
}

__global__ void roundcopy_kernel(const float* __restrict__ src, float* __restrict__ dst, size_t n) {
    for (size_t i = (size_t)blockIdx.x * blockDim.x + threadIdx.x; i < n;
         i += (size_t)gridDim.x * blockDim.x)
        dst[i] = f2tf(src[i]);
}

__global__ void headpad_kernel(const float* __restrict__ src, float* __restrict__ dst) {
    int k = blockIdx.y;
    int n = blockIdx.x * 256 + threadIdx.x;
    if (n < VPAD)
        dst[(size_t)k * VPAD + n] = (n < Vv) ? f2tf(src[(size_t)k * Vv + n]) : 0.f;
}

// =====================================================================
// tf32 mma.sync GEMM: C[M,Nn] = A[M,K] @ W[K,ldw slice]
// BM=128, BN=128, BK=32, 256 threads, cp.async double-buffered
// =====================================================================
#define ASTR 36
#define BSTR 136
#define ATILE_F (128 * ASTR)
#define BTILE_F (32 * BSTR)
#define STG_F   (ATILE_F + BTILE_F)
#define GEMM_SMEM (2 * STG_F * 4)

template<bool BIAS, bool RELU, bool RES, bool NBOUND, bool RND>
__global__ __launch_bounds__(256, 2) void mma_gemm(
    const float* __restrict__ A, const float* __restrict__ W,
    const float* __restrict__ bias, const float* __restrict__ res,
    float* __restrict__ C, int M, int Nn, int K, int ldw) {
    extern __shared__ float sm[];
    const uint32_t su = smem_u32(sm);
    const int tid = threadIdx.x;
    const int warp = tid >> 5, lane = tid & 31;
    const int g = lane >> 2, t4 = lane & 3;
    const int wm = warp >> 2, wn = warp & 3;
    const int warp_m0 = wm * 64, warp_n0 = wn * 32;
    const int m0 = blockIdx.x * 128;
    const int n0 = blockIdx.y * 128;

    float acc[4][4][4];
#pragma unroll
    for (int mt = 0; mt < 4; mt++)
#pragma unroll
        for (int nt = 0; nt < 4; nt++)
#pragma unroll
            for (int j = 0; j < 4; j++) acc[mt][nt][j] = 0.f;

    const int nk = K >> 5;

    auto load_stage = [&](int s, int kb) {
        uint32_t sa = su + (uint32_t)s * STG_F * 4;
#pragma unroll
        for (int i = 0; i < 4; i++) {
            int ch = tid + i * 256;
            int r = ch >> 3, c = ch & 7;
            cp16(sa + (uint32_t)(r * ASTR + c * 4) * 4,
                 A + (size_t)(m0 + r) * K + kb + c * 4);
        }
        uint32_t sb = sa + ATILE_F * 4;
#pragma unroll
        for (int i = 0; i < 4; i++) {
            int ch = tid + i * 256;
            int r = ch >> 5, c = ch & 31;
            cp16(sb + (uint32_t)(r * BSTR + c * 4) * 4,
                 W + (size_t)(kb + r) * ldw + n0 + c * 4);
        }
        CP_COMMIT();
    };

    load_stage(0, 0);
    load_stage(1, 32);

    for (int kc = 0; kc < nk; kc++) {
        const int s = kc & 1;
        if (kc == nk - 1) CP_WAIT0(); else CP_WAIT1();
        __syncthreads();

        const float* sA = sm + s * STG_F;
        const float* sB = sA + ATILE_F;
#pragma unroll
        for (int ks = 0; ks < 4; ks++) {
            const int k0 = ks * 8;
            uint32_t af[4][4], bf[4][2];
#pragma unroll
            for (int mt = 0; mt < 4; mt++) {
                int r0 = warp_m0 + mt * 16 + g;
                af[mt][0] = __float_as_uint(sA[r0 * ASTR + k0 + t4]);
                af[mt][1] = __float_as_uint(sA[(r0 + 8) * ASTR + k0 + t4]);
                af[mt][2] = __float_as_uint(sA[r0 * ASTR + k0 + t4 + 4]);
                af[mt][3] = __float_as_uint(sA[(r0 + 8) * ASTR + k0 + t4 + 4]);
            }
#pragma unroll
            for (int nt = 0; nt < 4; nt++) {
                int cn = warp_n0 + nt * 8 + g;
                bf[nt][0] = __float_as_uint(sB[(k0 + t4) * BSTR + cn]);
                bf[nt][1] = __float_as_uint(sB[(k0 + t4 + 4) * BSTR + cn]);
            }
#pragma unroll
            for (int mt = 0; mt < 4; mt++)
#pragma unroll
                for (int nt = 0; nt < 4; nt++)
                    mma8(acc[mt][nt], af[mt], bf[nt]);
        }

        if (kc + 2 < nk) {
            __syncthreads();
            load_stage(s, (kc + 2) * 32);
        }
    }

#pragma unroll
    for (int mt = 0; mt < 4; mt++) {
        int r0 = m0 + warp_m0 + mt * 16 + g;
#pragma unroll
        for (int nt = 0; nt < 4; nt++) {
            int cn = n0 + warp_n0 + nt * 8 + t4 * 2;
            float* a4 = acc[mt][nt];
            float b0 = 0.f, b1 = 0.f;
            if (BIAS) {
                if (!NBOUND) { b0 = bias[cn]; b1 = bias[cn + 1]; }
                else {
                    b0 = (cn < Nn) ? bias[cn] : 0.f;
                    b1 = (cn + 1 < Nn) ? bias[cn + 1] : 0.f;
                }
            }
#pragma unroll
            for (int half = 0; half < 2; half++) {
                int r = r0 + half * 8;
                float v0 = a4[half * 2 + 0] + b0;
                float v1 = a4[half * 2 + 1] + b1;
                if (RELU) { v0 = fmaxf(v0, 0.f); v1 = fmaxf(v1, 0.f); }
                size_t off = (size_t)r * Nn + cn;
                if (!NBOUND) {
                    if (RES) { v0 += res[off]; v1 += res[off + 1]; }
                    if (RND) { v0 = f2tf(v0); v1 = f2tf(v1); }
                    float2 o = make_float2(v0, v1);
                    *(float2*)(C + off) = o;
                } else {
                    if (cn < Nn) {
                        if (RES) v0 += res[off];
                        if (RND) v0 = f2tf(v0);
                        C[off] = v0;
                    }
                    if (cn + 1 < Nn) {
                        if (RES) v1 += res[off + 1];
                        if (RND) v1 = f2tf(v1);
                        C[off + 1] = v1;
                    }
                }
            }
        }
    }
}

// ---------------- embedding ----------------
__global__ void embed_kernel(const int* __restrict__ inp,
                             const float* __restrict__ tok,
                             const float* __restrict__ pos,
                             float* __restrict__ x) {
    int i = blockIdx.x;
    int t = i & (Tt - 1);
    int v = inp[i];
    const float* te = tok + (size_t)v * Cd;
    const float* pe = pos + (size_t)t * Cd;
    float* xo = x + (size_t)i * Cd;
    for (int c = threadIdx.x; c < Cd; c += blockDim.x)
        xo[c] = te[c] + pe[c];
}

// ---------------- layernorm (emits tf32-rounded output) ----------------
__global__ __launch_bounds__(256) void ln_kernel(const float* __restrict__ x,
                                                 const float* __restrict__ g,
                                                 const float* __restrict__ b,
                                                 float* __restrict__ out) {
    int row = blockIdx.x;
    const float* xr = x + (size_t)row * Cd;
    float s = 0.f;
    for (int c = threadIdx.x; c < Cd; c += 256) s += xr[c];
    float mean = blockReduceSum256(s) * (1.0f / Cd);
    float vs = 0.f;
    for (int c = threadIdx.x; c < Cd; c += 256) {
        float d = xr[c] - mean;
        vs += d * d;
    }
    float var = blockReduceSum256(vs) * (1.0f / Cd);
    float rstd = rsqrtf(var + 1e-5f);
    float* orow = out + (size_t)row * Cd;
    for (int c = threadIdx.x; c < Cd; c += 256)
        orow[c] = f2tf((xr[c] - mean) * rstd * g[c] + b[c]);
}

// ---------------- SIMT SGEMM (loss-only fallback path) ----------------
template<bool BIAS, bool RELU, bool RES>
__global__ __launch_bounds__(256) void sgemm_kernel(
    const float* __restrict__ A, const float* __restrict__ W,
    const float* __restrict__ bias, const float* __restrict__ res,
    float* __restrict__ Cout, int M, int Nn, int K, int ldw) {
    __shared__ float As[16][132];
    __shared__ float Bs[16][64];
    int tid = threadIdx.x;
    int m0 = blockIdx.x * 128;
    int n0 = blockIdx.y * 64;
    int tx = tid & 15, ty = tid >> 4;
    float acc[8][4];
#pragma unroll
    for (int i = 0; i < 8; i++)
#pragma unroll
        for (int j = 0; j < 4; j++) acc[i][j] = 0.f;
    int am = tid >> 1;
    int ak = (tid & 1) * 8;
    int bk = tid >> 4;
    int bn = (tid & 15) * 4;
    for (int k0 = 0; k0 < K; k0 += 16) {
        const float* Ap = A + (size_t)(m0 + am) * K + k0 + ak;
        float4 a0 = *(const float4*)Ap;
        float4 a1 = *(const float4*)(Ap + 4);
        As[ak + 0][am] = a0.x; As[ak + 1][am] = a0.y;
        As[ak + 2][am] = a0.z; As[ak + 3][am] = a0.w;
        As[ak + 4][am] = a1.x; As[ak + 5][am] = a1.y;
        As[ak + 6][am] = a1.z; As[ak + 7][am] = a1.w;
        int gn = n0 + bn;
        const float* Wp = W + (size_t)(k0 + bk) * ldw + gn;
        float4 bv;
        bv.x = (gn + 0 < Nn) ? Wp[0] : 0.f;
        bv.y = (gn + 1 < Nn) ? Wp[1] : 0.f;
        bv.z = (gn + 2 < Nn) ? Wp[2] : 0.f;
        bv.w = (gn + 3 < Nn) ? Wp[3] : 0.f;
        *(float4*)&Bs[bk][bn] = bv;
        __syncthreads();
#pragma unroll
        for (int kk = 0; kk < 16; kk++) {
            float4 a04 = *(const float4*)&As[kk][ty * 8];
            float4 a14 = *(const float4*)&As[kk][ty * 8 + 4];
            float4 b4  = *(const float4*)&Bs[kk][tx * 4];
            float a[8] = {a04.x, a04.y, a04.z, a04.w, a14.x, a14.y, a14.z, a14.w};
            float bb[4] = {b4.x, b4.y, b4.z, b4.w};
#pragma unroll
            for (int i = 0; i < 8; i++)
#pragma unroll
                for (int j = 0; j < 4; j++)
                    acc[i][j] += a[i] * bb[j];
        }
        __syncthreads();
    }
    int nbase = n0 + tx * 4;
#pragma unroll
    for (int i = 0; i < 8; i++) {
        size_t rowoff = (size_t)(m0 + ty * 8 + i) * Nn;
#pragma unroll
        for (int j = 0; j < 4; j++) {
            int n = nbase + j;
            if (n < Nn) {
                float v = acc[i][j];
                if (BIAS) v += bias[n];
                if (RELU) v = fmaxf(v, 0.f);
                if (RES) v += res[rowoff + n];
                Cout[rowoff + n] = v;
            }
        }
    }
}

// =====================================================================
// tensor-core flash attention (tf32 split => ~fp32 accuracy)
// grid (T/64, B*H), 128 threads (4 warps x 16 query rows)
// smem: Kh,Kl,Vh,Vl,Ph,Pl each [64][68]
// =====================================================================
#define AST 68
#define ATTN_SMEM (6 * 64 * AST * 4)

__global__ __launch_bounds__(128, 2) void attn_tc_kernel(const float* __restrict__ QKV,
                                                         float* __restrict__ O) {
    extern __shared__ float sme[];
    float* Kh = sme;
    float* Kl = Kh + 64 * AST;
    float* Vh = Kl + 64 * AST;
    float* Vl = Vh + 64 * AST;
    float* Ph = Vl + 64 * AST;
    float* Pl = Ph + 64 * AST;

    const int qt = gridDim.x - 1 - blockIdx.x;   // big tiles first
    const int bh = blockIdx.y;
    const int b = bh / Hh, h = bh % Hh;
    const int tid = threadIdx.x;
    const int warp = tid >> 5, lane = tid & 31;
    const int g = lane >> 2, t4 = lane & 3;
    const int r0l = warp * 16 + g;        // local query rows of this thread
    const int r1l = r0l + 8;

    // ---- stage Q tile (scaled by 1/8) into Ph, then load split fragments ----
#pragma unroll
    for (int i = 0; i < 8; i++) {
        int ch = tid + i * 128;
        int r = ch >> 4, c4 = ch & 15;
        float4 v = *(const float4*)(QKV + (size_t)(b * Tt + qt * 64 + r) * QKVS + h * HSd + c4 * 4);
        v.x *= 0.125f; v.y *= 0.125f; v.z *= 0.125f; v.w *= 0.125f;
        *(float4*)(Ph + r * AST + c4 * 4) = v;
    }
    __syncthreads();

    uint32_t qh[8][4], ql[8][4];
#pragma unroll
    for (int ks = 0; ks < 8; ks++) {
        int k0 = ks * 8;
        float v[4];
        v[0] = Ph[r0l * AST + k0 + t4];
        v[1] = Ph[r1l * AST + k0 + t4];
        v[2] = Ph[r0l * AST + k0 + t4 + 4];
        v[3] = Ph[r1l * AST + k0 + t4 + 4];
#pragma unroll
        for (int j = 0; j < 4; j++) {
            float hi = f2tf(v[j]);
            qh[ks][j] = __float_as_uint(hi);
            ql[ks][j] = __float_as_uint(f2tf(v[j] - hi));
        }
    }

    float o[8][4];
#pragma unroll
    for (int nt = 0; nt < 8; nt++)
#pragma unroll
        for (int j = 0; j < 4; j++) o[nt][j] = 0.f;
    float m0 = -1e30f, m1 = -1e30f, l0 = 0.f, l1 = 0.f;

    for (int kt = 0; kt <= qt; kt++) {
        __syncthreads();   // previous tile fully consumed (also covers Q staging in Ph)
        // ---- load K,V tile, split hi/lo ----
#pragma unroll
        for (int i = 0; i < 8; i++) {
            int ch = tid + i * 128;
            int r = ch >> 4, c4 = ch & 15;
            size_t go = (size_t)(b * Tt + kt * 64 + r) * QKVS + h * HSd;
            float4 kv = *(const float4*)(QKV + go + Cd + c4 * 4);
            float4 vv = *(const float4*)(QKV + go + 2 * Cd + c4 * 4);
            float4 khv, klv, vhv, vlv;
            khv.x = f2tf(kv.x); klv.x = f2tf(kv.x - khv.x);
            khv.y = f2tf(kv.y); klv.y = f2tf(kv.y - khv.y);
            khv.z = f2tf(kv.z); klv.z = f2tf(kv.z - khv.z);
            khv.w = f2tf(kv.w); klv.w = f2tf(kv.w - khv.w);
            vhv.x = f2tf(vv.x); vlv.x = f2tf(vv.x - vhv.x);
            vhv.y = f2tf(vv.y); vlv.y = f2tf(vv.y - vhv.y);
            vhv.z = f2tf(vv.z); vlv.z = f2tf(vv.z - vhv.z);
            vhv.w = f2tf(vv.w); vlv.w = f2tf(vv.w - vhv.w);
            *(float4*)(Kh + r * AST + c4 * 4) = khv;
            *(float4*)(Kl + r * AST + c4 * 4) = klv;
            *(float4*)(Vh + r * AST + c4 * 4) = vhv;
            *(float4*)(Vl + r * AST + c4 * 4) = vlv;
        }
        __syncthreads();

        // ---- S = Q K^T (3-term tf32 split; Q prescaled) ----
        float sacc[8][4];
#pragma unroll
        for (int nt = 0; nt < 8; nt++)
#pragma unroll
            for (int j = 0; j < 4; j++) sacc[nt][j] = 0.f;
#pragma unroll
        for (int ks = 0; ks < 8; ks++) {
            int k0 = ks * 8;
#pragma unroll
            for (int nt = 0; nt < 8; nt++) {
                int j = nt * 8 + g;
                uint32_t bh_[2], bl_[2];
                bh_[0] = __float_as_uint(Kh[j * AST + k0 + t4]);
                bh_[1] = __float_as_uint(Kh[j * AST + k0 + t4 + 4]);
                bl_[0] = __float_as_uint(Kl[j * AST + k0 + t4]);
                bl_[1] = __float_as_uint(Kl[j * AST + k0 + t4 + 4]);
                mma8(sacc[nt], qh[ks], bh_);
                mma8(sacc[nt], qh[ks], bl_);
                mma8(sacc[nt], ql[ks], bh_);
            }
        }

        // ---- causal mask on diagonal tile ----
        if (kt == qt) {
#pragma unroll
            for (int nt = 0; nt < 8; nt++) {
                int c0 = nt * 8 + 2 * t4;
                if (c0     > r0l) sacc[nt][0] = -1e30f;
                if (c0 + 1 > r0l) sacc[nt][1] = -1e30f;
                if (c0     > r1l) sacc[nt][2] = -1e30f;
                if (c0 + 1 > r1l) sacc[nt][3] = -1e30f;
            }
        }

        // ---- online softmax ----
        float tm0 = -1e30f, tm1 = -1e30f;
#pragma unroll
        for (int nt = 0; nt < 8; nt++) {
            tm0 = fmaxf(tm0, fmaxf(sacc[nt][0], sacc[nt][1]));
            tm1 = fmaxf(tm1, fmaxf(sacc[nt][2], sacc[nt][3]));
        }
        tm0 = fmaxf(tm0, __shfl_xor_sync(0xffffffffu, tm0, 1));
        tm0 = fmaxf(tm0, __shfl_xor_sync(0xffffffffu, tm0, 2));
        tm1 = fmaxf(tm1, __shfl_xor_sync(0xffffffffu, tm1, 1));
        tm1 = fmaxf(tm1, __shfl_xor_sync(0xffffffffu, tm1, 2));
        float mN0 = fmaxf(m0, tm0), mN1 = fmaxf(m1, tm1);
        float a0 = __expf(m0 - mN0), a1 = __expf(m1 - mN1);
        m0 = mN0; m1 = mN1;

        float sum0 = 0.f, sum1 = 0.f;
#pragma unroll
        for (int nt = 0; nt < 8; nt++) {
            float p0 = __expf(sacc[nt][0] - mN0);
            float p1 = __expf(sacc[nt][1] - mN0);
            float p2 = __expf(sacc[nt][2] - mN1);
            float p3 = __expf(sacc[nt][3] - mN1);
            sum0 += p0 + p1;
            sum1 += p2 + p3;
            int c0 = nt * 8 + 2 * t4;
            float h0 = f2tf(p0), h1 = f2tf(p1), h2 = f2tf(p2), h3 = f2tf(p3);
            *(float2*)(Ph + r0l * AST + c0) = make_float2(h0, h1);
            *(float2*)(Pl + r0l * AST + c0) = make_float2(f2tf(p0 - h0), f2tf(p1 - h1));
            *(float2*)(Ph + r1l * AST + c0) = make_float2(h2, h3);
            *(float2*)(Pl + r1l * AST + c0) = make_float2(f2tf(p2 - h2), f2tf(p3 - h3));
        }
        sum0 += __shfl_xor_sync(0xffffffffu, sum0, 1);
        sum0 += __shfl_xor_sync(0xffffffffu, sum0, 2);
        sum1 += __shfl_xor_sync(0xffffffffu, sum1, 1);
        sum1 += __shfl_xor_sync(0xffffffffu, sum1, 2);
        l0 = l0 * a0 + sum0;
        l1 = l1 * a1 + sum1;
#pragma unroll
        for (int nt = 0; nt < 8; nt++) {
            o[nt][0] *= a0; o[nt][1] *= a0;
            o[nt][2] *= a1; o[nt][3] *= a1;
        }
        __syncwarp();

        // ---- O += P V (3-term split) ----
#pragma unroll
        for (int ks = 0; ks < 8; ks++) {
            int k0 = ks * 8;
            uint32_t ah[4], al[4];
            ah[0] = __float_as_uint(Ph[r0l * AST + k0 + t4]);
            ah[1] = __float_as_uint(Ph[r1l * AST + k0 + t4]);
            ah[2] = __float_as_uint(Ph[r0l * AST + k0 + t4 + 4]);
            ah[3] = __float_as_uint(Ph[r1l * AST + k0 + t4 + 4]);
            al[0] = __float_as_uint(Pl[r0l * AST + k0 + t4]);
            al[1] = __float_as_uint(Pl[r1l * AST + k0 + t4]);
            al[2] = __float_as_uint(Pl[r0l * AST + k0 + t4 + 4]);
            al[3] = __float_as_uint(Pl[r1l * AST + k0 + t4 + 4]);
#pragma unroll
            for (int nt = 0; nt < 8; nt++) {
                int d = nt * 8 + g;
                uint32_t bh_[2], bl_[2];
                bh_[0] = __float_as_uint(Vh[(k0 + t4) * AST + d]);
                bh_[1] = __float_as_uint(Vh[(k0 + t4 + 4) * AST + d]);
                bl_[0] = __float_as_uint(Vl[(k0 + t4) * AST + d]);
                bl_[1] = __float_as_uint(Vl[(k0 + t4 + 4) * AST + d]);
                mma8(o[nt], ah, bh_);
                mma8(o[nt], ah, bl_);
                mma8(o[nt], al, bh_);
            }
        }
    }

    // ---- epilogue: normalize, round, store ----
    float i0 = 1.f / l0, i1 = 1.f / l1;
    size_t row0 = (size_t)(b * Tt + qt * 64 + r0l) * Cd + h * HSd;
    size_t row1 = (size_t)(b * Tt + qt * 64 + r1l) * Cd + h * HSd;
#pragma unroll
    for (int nt = 0; nt < 8; nt++) {
        int c0 = nt * 8 + 2 * t4;
        *(float2*)(O + row0 + c0) = make_float2(f2tf(o[nt][0] * i0), f2tf(o[nt][1] * i0));
        *(float2*)(O + row1 + c0) = make_float2(f2tf(o[nt][2] * i1), f2tf(o[nt][3] * i1));
    }
}

// ---------------- loss kernels ----------------
__global__ __launch_bounds__(256) void rowloss_kernel(const float* __restrict__ logits,
                                                      const int* __restrict__ tgt,
                                                      float* __restrict__ rl) {
    int r = blockIdx.x;
    const float* lr = logits + (size_t)r * Vv;
    float m = -1e30f;
    for (int c = threadIdx.x; c < Vv; c += 256) m = fmaxf(m, lr[c]);
    m = blockReduceMax256(m);
    float s = 0.f;
    for (int c = threadIdx.x; c < Vv; c += 256) s += __expf(lr[c] - m);
    s = blockReduceSum256(s);
    if (threadIdx.x == 0) rl[r] = m + logf(s) - lr[tgt[r]];
}

__global__ __launch_bounds__(256) void lossreduce_kernel(const float* __restrict__ rl,
                                                         float* __restrict__ out) {
    float s = 0.f;
    for (int i = threadIdx.x; i < NT; i += 256) s += rl[i];
    s = blockReduceSum256(s);
    if (threadIdx.x == 0) out[0] = s * (1.0f / NT);
}

__global__ void lse_init_kernel(float* lm, float* ls, float* lt) {
    int i = blockIdx.x * blockDim.x + threadIdx.x;
    if (i < NT) { lm[i] = -1e30f; ls[i] = 0.f; lt[i] = 0.f; }
}

__global__ __launch_bounds__(256) void chunkloss_kernel(const float* __restrict__ chunk,
                                                        int width, int col0,
                                                        const int* __restrict__ tgt,
                                                        float* __restrict__ lm,
                                                        float* __restrict__ ls,
                                                        float* __restrict__ lt) {
    int r = blockIdx.x;
    const float* cr = chunk + (size_t)r * width;
    float m = -1e30f;
    for (int c = threadIdx.x; c < width; c += 256) m = fmaxf(m, cr[c]);
    m = blockReduceMax256(m);
    float s = 0.f;
    for (int c = threadIdx.x; c < width; c += 256) s += __expf(cr[c] - m);
    s = blockReduceSum256(s);
    if (threadIdx.x == 0) {
        float mOld = lm[r];
        float mNew = fmaxf(mOld, m);
        ls[r] = ls[r] * __expf(mOld - mNew) + s * __expf(m - mNew);
        lm[r] = mNew;
        int tg = tgt[r] - col0;
        if (tg >= 0 && tg < width) lt[r] = cr[tg];
    }
}

__global__ void chunkfinal_kernel(const float* lm, const float* ls, const float* lt,
                                  float* rl) {
    int i = blockIdx.x * blockDim.x + threadIdx.x;
    if (i < NT) rl[i] = lm[i] + logf(ls[i]) - lt[i];
}

// ---------------- host driver ----------------
static float* devptr(const void* sym) {
    void* p = nullptr;
    cudaGetSymbolAddress(&p, sym);
    return (float*)p;
}

extern "C" void kernel_launch(void* const* d_in, const int* in_sizes, int n_in,
                              void* d_out, int out_size) {
    const int* inputs    = (const int*)d_in[0];
    const int* targets   = (const int*)d_in[1];
    const float* tok     = (const float*)d_in[2];
    const float* pos     = (const float*)d_in[3];
    const float* ln1g    = (const float*)d_in[4];
    const float* ln1b    = (const float*)d_in[5];
    const float* ln2g    = (const float*)d_in[6];
    const float* ln2b    = (const float*)d_in[7];
    const float* wq      = (const float*)d_in[8];
    const float* wk      = (const float*)d_in[9];
    const float* wv      = (const float*)d_in[10];
    const float* wo      = (const float*)d_in[11];
    const float* bo      = (const float*)d_in[12];
    const float* w1      = (const float*)d_in[13];
    const float* b1      = (const float*)d_in[14];
    const float* w2      = (const float*)d_in[15];
    const float* b2      = (const float*)d_in[16];
    const float* lnfg    = (const float*)d_in[17];
    const float* lnfb    = (const float*)d_in[18];
    const float* whead   = (const float*)d_in[19];
    const float* bhead   = (const float*)d_in[20];

    float* x   = devptr(g_x);
    float* h   = devptr(g_h);
    float* qkv = devptr(g_qkv);
    float* ob  = devptr(g_ob);
    float* fb  = devptr(g_f);
    float* rl  = devptr(g_rowloss);
    float* lm  = devptr(g_lm);
    float* ls  = devptr(g_ls);
    float* lt  = devptr(g_lt);
    float* wt  = devptr(g_wt);

    cudaFuncSetAttribute(mma_gemm<false, false, false, false, false>, cudaFuncAttributeMaxDynamicSharedMemorySize, GEMM_SMEM);
    cudaFuncSetAttribute(mma_gemm<true, false, true, false, false>,   cudaFuncAttributeMaxDynamicSharedMemorySize, GEMM_SMEM);
    cudaFuncSetAttribute(mma_gemm<true, true, false, false, true>,    cudaFuncAttributeMaxDynamicSharedMemorySize, GEMM_SMEM);
    cudaFuncSetAttribute(mma_gemm<true, false, false, true, false>,   cudaFuncAttributeMaxDynamicSharedMemorySize, GEMM_SMEM);
    cudaFuncSetAttribute(attn_tc_kernel, cudaFuncAttributeMaxDynamicSharedMemorySize, ATTN_SMEM);

    // ---- weight prep: tf32-round (and pack/pad) once per launch ----
    qkvpack_kernel<<<2048, 256>>>(wq, wt + OFF_QKV, 0);
    qkvpack_kernel<<<2048, 256>>>(wk, wt + OFF_QKV, 1);
    qkvpack_kernel<<<2048, 256>>>(wv, wt + OFF_QKV, 2);
    roundcopy_kernel<<<2048, 256>>>(wo, wt + OFF_WO, (size_t)Ll * Cd * Cd);
    roundcopy_kernel<<<4096, 256>>>(w1, wt + OFF_W1, (size_t)Ll * Cd * Fd);
    roundcopy_kernel<<<4096, 256>>>(w2, wt + OFF_W2, (size_t)Ll * Fd * Cd);
    {
        dim3 gHp((VPAD + 255) / 256, Cd);
        headpad_kernel<<<gHp, 256>>>(whead, wt + OFF_HD);
    }

    dim3 gQKV(NT / 128, QKVS / 128);
    dim3 gC(NT / 128, Cd / 128);
    dim3 gF(NT / 128, Fd / 128);
    dim3 gV(NT / 128, (Vv + 127) / 128);
    dim3 gAttn(Tt / 64, Bq * Hh);

    embed_kernel<<<NT, 256>>>(inputs, tok, pos, x);

    for (int l = 0; l < Ll; l++) {
        const float* wqkv = wt + OFF_QKV + (size_t)l * Cd * QKVS;
        const float* wot  = wt + OFF_WO + (size_t)l * Cd * Cd;
        const float* w1t  = wt + OFF_W1 + (size_t)l * Cd * Fd;
        const float* w2t  = wt + OFF_W2 + (size_t)l * Fd * Cd;

        ln_kernel<<<NT, 256>>>(x, ln1g + l * Cd, ln1b + l * Cd, h);
        mma_gemm<false, false, false, false, false><<<gQKV, 256, GEMM_SMEM>>>(
            h, wqkv, nullptr, nullptr, qkv, NT, QKVS, Cd, QKVS);
        attn_tc_kernel<<<gAttn, 128, ATTN_SMEM>>>(qkv, ob);
        mma_gemm<true, false, true, false, false><<<gC, 256, GEMM_SMEM>>>(
            ob, wot, bo + l * Cd, x, x, NT, Cd, Cd, Cd);
        ln_kernel<<<NT, 256>>>(x, ln2g + l * Cd, ln2b + l * Cd, h);
        mma_gemm<true, true, false, false, true><<<gF, 256, GEMM_SMEM>>>(
            h, w1t, b1 + (size_t)l * Fd, nullptr, fb, NT, Fd, Cd, Fd);
        mma_gemm<true, false, true, false, false><<<gC, 256, GEMM_SMEM>>>(
            fb, w2t, b2 + l * Cd, x, x, NT, Cd, Fd, Cd);
    }

    ln_kernel<<<NT, 256>>>(x, lnfg, lnfb, h);

    const long long NV = (long long)NT * Vv;
    if ((long long)out_size >= NV) {
        float* logits = (float*)d_out;
        mma_gemm<true, false, false, true, false><<<gV, 256, GEMM_SMEM>>>(
            h, wt + OFF_HD, bhead, nullptr, logits, NT, Vv, Cd, VPAD);
        if ((long long)out_size > NV) {
            rowloss_kernel<<<NT, 256>>>(logits, targets, rl);
            lossreduce_kernel<<<1, 256>>>(rl, (float*)d_out + NV);
        }
    } else {
        // loss-only fallback: chunked logsumexp through g_f (SIMT path)
        lse_init_kernel<<<(NT + 255) / 256, 256>>>(lm, ls, lt);
        const int CW = 3072;
        for (int col0 = 0; col0 < Vv; col0 += CW) {
            int width = (Vv - col0 < CW) ? (Vv - col0) : CW;
            dim3 gCk(NT / 128, (width + 63) / 64);
            sgemm_kernel<true, false, false><<<gCk, 256>>>(h, whead + col0, bhead + col0,
                                                           nullptr, fb, NT, width, Cd, Vv);
            chunkloss_kernel<<<NT, 256>>>(fb, width, col0, targets, lm, ls, lt);
        }
        chunkfinal_kernel<<<(NT + 255) / 256, 256>>>(lm, ls, lt, rl);
        lossreduce_kernel<<<1, 256>>>(rl, (float*)d_out);
    }
}

// round 6
// speedup vs baseline: 3.7017x; 1.0525x over previous
#include <cuda_runtime.h>
#include <cuda_bf16.h>
#include <math.h>
#include <stdint.h>

// ---------------- problem constants (GPT-2 small forward) ----------------
#define Bq   8
#define Tt   1024
#define NT   8192          // B*T tokens
#define Cd   768
#define Hh   12
#define HSd  64
#define Fd   3072
#define Ll   12
#define Vv   50257
#define VPAD 50304         // multiple of 128
#define QKVS 2304          // fused qkv width

// ---------------- scratch (device globals: allocation-free) --------------
__device__ float g_x[(size_t)NT * Cd];       // residual stream
__device__ float g_h[(size_t)NT * Cd];       // LN output (tf32-rounded)
__device__ float g_qkv[(size_t)NT * QKVS];   // fused q|k|v
__device__ float g_ob[(size_t)NT * Cd];
__device__ float g_f[(size_t)NT * Fd];       // MLP hidden / logits chunks
__device__ float g_rowloss[NT];
__device__ float g_lm[NT];
__device__ float g_ls[NT];
__device__ float g_lt[NT];

// pre-rounded (tf32) weights
#define OFF_QKV ((size_t)0)                    // [L][768][2304]
#define OFF_WO  ((size_t)21233664)             // [L][768][768]
#define OFF_W1  ((size_t)28311552)             // [L][768][3072]
#define OFF_W2  ((size_t)56623104)             // [L][3072][768]
#define OFF_HD  ((size_t)84934656)             // [768][VPAD]
#define WT_TOTAL ((size_t)84934656 + (size_t)Cd * VPAD)
__device__ float g_wt[WT_TOTAL];

// ---------------- helpers ----------------
__device__ __forceinline__ float f2tf(float x) {
    uint32_t u;
    asm("cvt.rna.tf32.f32 %0, %1;" : "=r"(u) : "f"(x));
    return __uint_as_float(u);
}

__device__ __forceinline__ uint32_t smem_u32(const void* p) {
    uint32_t a;
    asm("{ .reg .u64 t; cvta.to.shared.u64 t, %1; cvt.u32.u64 %0, t; }" : "=r"(a) : "l"(p));
    return a;
}

__device__ __forceinline__ void cp16(uint32_t saddr, const void* gaddr) {
    asm volatile("cp.async.cg.shared.global [%0], [%1], 16;" :: "r"(saddr), "l"(gaddr));
}
#define CP_COMMIT() asm volatile("cp.async.commit_group;" ::: "memory")
#define CP_WAIT1()  asm volatile("cp.async.wait_group 1;" ::: "memory")
#define CP_WAIT0()  asm volatile("cp.async.wait_group 0;" ::: "memory")

__device__ __forceinline__ void mma8(float* c, const uint32_t* a, const uint32_t* b) {
    asm volatile(
        "mma.sync.aligned.m16n8k8.row.col.f32.tf32.tf32.f32 "
        "{%0,%1,%2,%3}, {%4,%5,%6,%7}, {%8,%9}, {%0,%1,%2,%3};\n"
        : "+f"(c[0]), "+f"(c[1]), "+f"(c[2]), "+f"(c[3])
        : "r"(a[0]), "r"(a[1]), "r"(a[2]), "r"(a[3]), "r"(b[0]), "r"(b[1]));
}

// ---------------- block reduce helpers ----------------
__device__ __forceinline__ float blockReduceSum256(float v) {
    __shared__ float sh[8];
    int lane = threadIdx.x & 31, w = threadIdx.x >> 5;
#pragma unroll
    for (int o = 16; o; o >>= 1) v += __shfl_xor_sync(0xffffffffu, v, o);
    if (lane == 0) sh[w] = v;
    __syncthreads();
    float r = (threadIdx.x < 8) ? sh[threadIdx.x] : 0.f;
    if (w == 0) {
#pragma unroll
        for (int o = 4; o; o >>= 1) r += __shfl_xor_sync(0xffffffffu, r, o);
    }
    __syncthreads();
    if (threadIdx.x == 0) sh[0] = r;
    __syncthreads();
    return sh[0];
}

__device__ __forceinline__ float blockReduceMax256(float v) {
    __shared__ float sh[8];
    int lane = threadIdx.x & 31, w = threadIdx.x >> 5;
#pragma unroll
    for (int o = 16; o; o >>= 1) v = fmaxf(v, __shfl_xor_sync(0xffffffffu, v, o));
    if (lane == 0) sh[w] = v;
    __syncthreads();
    float r = (threadIdx.x < 8) ? sh[threadIdx.x] : -1e30f;
    if (w == 0) {
#pragma unroll
        for (int o = 4; o; o >>= 1) r = fmaxf(r, __shfl_xor_sync(0xffffffffu, r, o));
    }
    __syncthreads();
    if (threadIdx.x == 0) sh[0] = r;
    __syncthreads();
    return sh[0];
}

// ---------------- weight prep (per-launch, deterministic) ----------------
__global__ void qkvpack_kernel(const float* __restrict__ src, float* __restrict__ dst, int sel) {
    size_t n = (size_t)Ll * Cd * Cd;
    for (size_t i = (size_t)blockIdx.x * blockDim.x + threadIdx.x; i < n;
         i += (size_t)gridDim.x * blockDim.x) {
        size_t l = i / ((size_t)Cd * Cd);
        size_t rem = i - l * (size_t)Cd * Cd;
        size_t k = rem / Cd, nn = rem - k * Cd;
        dst[l * ((size_t)Cd * QKVS) + k * QKVS + (size_t)sel * Cd + nn] = f2tf(src[i]);
    }
}

__global__ void roundcopy_kernel(const float* __restrict__ src, float* __restrict__ dst, size_t n) {
    for (size_t i = (size_t)blockIdx.x * blockDim.x + threadIdx.x; i < n;
         i += (size_t)gridDim.x * blockDim.x)
        dst[i] = f2tf(src[i]);
}

__global__ void headpad_kernel(const float* __restrict__ src, float* __restrict__ dst) {
    int k = blockIdx.y;
    int n = blockIdx.x * 256 + threadIdx.x;
    if (n < VPAD)
        dst[(size_t)k * VPAD + n] = (n < Vv) ? f2tf(src[(size_t)k * Vv + n]) : 0.f;
}

// =====================================================================
// tf32 mma.sync GEMM: C[M,Nn] = A[M,K] @ W[K,ldw slice]
// BM=128, BN=128, BK=32, 256 threads, cp.async 3-stage pipeline
// =====================================================================
#define ASTR 36
#define BSTR 136
#define ATILE_F (128 * ASTR)
#define BTILE_F (32 * BSTR)
#define STG_F   (ATILE_F + BTILE_F)
#define NSTG    3
#define GEMM_SMEM (NSTG * STG_F * 4)   // 107520 bytes

template<bool BIAS, bool RELU, bool RES, bool NBOUND, bool RND>
__global__ __launch_bounds__(256, 2) void mma_gemm(
    const float* __restrict__ A, const float* __restrict__ W,
    const float* __restrict__ bias, const float* __restrict__ res,
    float* __restrict__ C, int M, int Nn, int K, int ldw) {
    extern __shared__ float sm[];
    const uint32_t su = smem_u32(sm);
    const int tid = threadIdx.x;
    const int warp = tid >> 5, lane = tid & 31;
    const int g = lane >> 2, t4 = lane & 3;
    const int wm = warp >> 2, wn = warp & 3;
    const int warp_m0 = wm * 64, warp_n0 = wn * 32;
    const int m0 = blockIdx.x * 128;
    const int n0 = blockIdx.y * 128;

    float acc[4][4][4];
#pragma unroll
    for (int mt = 0; mt < 4; mt++)
#pragma unroll
        for (int nt = 0; nt < 4; nt++)
#pragma unroll
            for (int j = 0; j < 4; j++) acc[mt][nt][j] = 0.f;

    const int nk = K >> 5;

    auto load_stage = [&](int s, int kb) {
        uint32_t sa = su + (uint32_t)s * STG_F * 4;
#pragma unroll
        for (int i = 0; i < 4; i++) {
            int ch = tid + i * 256;
            int r = ch >> 3, c = ch & 7;
            cp16(sa + (uint32_t)(r * ASTR + c * 4) * 4,
                 A + (size_t)(m0 + r) * K + kb + c * 4);
        }
        uint32_t sb = sa + ATILE_F * 4;
#pragma unroll
        for (int i = 0; i < 4; i++) {
            int ch = tid + i * 256;
            int r = ch >> 5, c = ch & 31;
            cp16(sb + (uint32_t)(r * BSTR + c * 4) * 4,
                 W + (size_t)(kb + r) * ldw + n0 + c * 4);
        }
        CP_COMMIT();
    };

    load_stage(0, 0);
    load_stage(1, 32);

    int s = 0;
    for (int kc = 0; kc < nk; kc++) {
        if (kc + 1 < nk) CP_WAIT1(); else CP_WAIT0();
        __syncthreads();

        const float* sA = sm + s * STG_F;
        const float* sB = sA + ATILE_F;
#pragma unroll
        for (int ks = 0; ks < 4; ks++) {
            const int k0 = ks * 8;
            uint32_t af[4][4], bf[4][2];
#pragma unroll
            for (int mt = 0; mt < 4; mt++) {
                int r0 = warp_m0 + mt * 16 + g;
                af[mt][0] = __float_as_uint(sA[r0 * ASTR + k0 + t4]);
                af[mt][1] = __float_as_uint(sA[(r0 + 8) * ASTR + k0 + t4]);
                af[mt][2] = __float_as_uint(sA[r0 * ASTR + k0 + t4 + 4]);
                af[mt][3] = __float_as_uint(sA[(r0 + 8) * ASTR + k0 + t4 + 4]);
            }
#pragma unroll
            for (int nt = 0; nt < 4; nt++) {
                int cn = warp_n0 + nt * 8 + g;
                bf[nt][0] = __float_as_uint(sB[(k0 + t4) * BSTR + cn]);
                bf[nt][1] = __float_as_uint(sB[(k0 + t4 + 4) * BSTR + cn]);
            }
#pragma unroll
            for (int mt = 0; mt < 4; mt++)
#pragma unroll
                for (int nt = 0; nt < 4; nt++)
                    mma8(acc[mt][nt], af[mt], bf[nt]);
        }

        // write target (kc+2)%3: last read at iter kc-1, all threads past this
        // iteration's barrier -> safe, no second barrier needed.
        if (kc + 2 < nk) {
            int sw = s + 2; if (sw >= NSTG) sw -= NSTG;
            load_stage(sw, (kc + 2) * 32);
        }
        if (++s == NSTG) s = 0;
    }

#pragma unroll
    for (int mt = 0; mt < 4; mt++) {
        int r0 = m0 + warp_m0 + mt * 16 + g;
#pragma unroll
        for (int nt = 0; nt < 4; nt++) {
            int cn = n0 + warp_n0 + nt * 8 + t4 * 2;
            float* a4 = acc[mt][nt];
            float b0 = 0.f, b1 = 0.f;
            if (BIAS) {
                if (!NBOUND) { b0 = bias[cn]; b1 = bias[cn + 1]; }
                else {
                    b0 = (cn < Nn) ? bias[cn] : 0.f;
                    b1 = (cn + 1 < Nn) ? bias[cn + 1] : 0.f;
                }
            }
#pragma unroll
            for (int half = 0; half < 2; half++) {
                int r = r0 + half * 8;
                float v0 = a4[half * 2 + 0] + b0;
                float v1 = a4[half * 2 + 1] + b1;
                if (RELU) { v0 = fmaxf(v0, 0.f); v1 = fmaxf(v1, 0.f); }
                size_t off = (size_t)r * Nn + cn;
                if (!NBOUND) {
                    if (RES) { v0 += res[off]; v1 += res[off + 1]; }
                    if (RND) { v0 = f2tf(v0); v1 = f2tf(v1); }
                    float2 o = make_float2(v0, v1);
                    *(float2*)(C + off) = o;
                } else {
                    if (cn < Nn) {
                        if (RES) v0 += res[off];
                        if (RND) v0 = f2tf(v0);
                        C[off] = v0;
                    }
                    if (cn + 1 < Nn) {
                        if (RES) v1 += res[off + 1];
                        if (RND) v1 = f2tf(v1);
                        C[off + 1] = v1;
                    }
                }
            }
        }
    }
}

// ---------------- embedding ----------------
__global__ void embed_kernel(const int* __restrict__ inp,
                             const float* __restrict__ tok,
                             const float* __restrict__ pos,
                             float* __restrict__ x) {
    int i = blockIdx.x;
    int t = i & (Tt - 1);
    int v = inp[i];
    const float* te = tok + (size_t)v * Cd;
    const float* pe = pos + (size_t)t * Cd;
    float* xo = x + (size_t)i * Cd;
    for (int c = threadIdx.x; c < Cd; c += blockDim.x)
        xo[c] = te[c] + pe[c];
}

// ---------------- layernorm: warp per row, shuffle-only reductions -------
// block = 256 (8 warps = 8 rows), grid = NT/8. Emits tf32-rounded output.
__global__ __launch_bounds__(256) void ln_kernel(const float* __restrict__ x,
                                                 const float* __restrict__ g,
                                                 const float* __restrict__ b,
                                                 float* __restrict__ out) {
    const int warp = threadIdx.x >> 5, lane = threadIdx.x & 31;
    const int row = blockIdx.x * 8 + warp;
    const float4* xr = (const float4*)(x + (size_t)row * Cd);
    const float4* gp = (const float4*)g;
    const float4* bp = (const float4*)b;
    float4* orow = (float4*)(out + (size_t)row * Cd);

    float4 v[6];
    float s = 0.f;
#pragma unroll
    for (int i = 0; i < 6; i++) {
        v[i] = xr[lane + i * 32];
        s += v[i].x + v[i].y + v[i].z + v[i].w;
    }
#pragma unroll
    for (int o = 16; o; o >>= 1) s += __shfl_xor_sync(0xffffffffu, s, o);
    float mean = s * (1.0f / Cd);

    float vs = 0.f;
#pragma unroll
    for (int i = 0; i < 6; i++) {
        float dx = v[i].x - mean, dy = v[i].y - mean,
              dz = v[i].z - mean, dw = v[i].w - mean;
        vs += dx * dx + dy * dy + dz * dz + dw * dw;
    }
#pragma unroll
    for (int o = 16; o; o >>= 1) vs += __shfl_xor_sync(0xffffffffu, vs, o);
    float rstd = rsqrtf(vs * (1.0f / Cd) + 1e-5f);

#pragma unroll
    for (int i = 0; i < 6; i++) {
        float4 gg = gp[lane + i * 32];
        float4 bb = bp[lane + i * 32];
        float4 o4;
        o4.x = f2tf((v[i].x - mean) * rstd * gg.x + bb.x);
        o4.y = f2tf((v[i].y - mean) * rstd * gg.y + bb.y);
        o4.z = f2tf((v[i].z - mean) * rstd * gg.z + bb.z);
        o4.w = f2tf((v[i].w - mean) * rstd * gg.w + bb.w);
        orow[lane + i * 32] = o4;
    }
}

// ---------------- SIMT SGEMM (loss-only fallback path) ----------------
template<bool BIAS, bool RELU, bool RES>
__global__ __launch_bounds__(256) void sgemm_kernel(
    const float* __restrict__ A, const float* __restrict__ W,
    const float* __restrict__ bias, const float* __restrict__ res,
    float* __restrict__ Cout, int M, int Nn, int K, int ldw) {
    __shared__ float As[16][132];
    __shared__ float Bs[16][64];
    int tid = threadIdx.x;
    int m0 = blockIdx.x * 128;
    int n0 = blockIdx.y * 64;
    int tx = tid & 15, ty = tid >> 4;
    float acc[8][4];
#pragma unroll
    for (int i = 0; i < 8; i++)
#pragma unroll
        for (int j = 0; j < 4; j++) acc[i][j] = 0.f;
    int am = tid >> 1;
    int ak = (tid & 1) * 8;
    int bk = tid >> 4;
    int bn = (tid & 15) * 4;
    for (int k0 = 0; k0 < K; k0 += 16) {
        const float* Ap = A + (size_t)(m0 + am) * K + k0 + ak;
        float4 a0 = *(const float4*)Ap;
        float4 a1 = *(const float4*)(Ap + 4);
        As[ak + 0][am] = a0.x; As[ak + 1][am] = a0.y;
        As[ak + 2][am] = a0.z; As[ak + 3][am] = a0.w;
        As[ak + 4][am] = a1.x; As[ak + 5][am] = a1.y;
        As[ak + 6][am] = a1.z; As[ak + 7][am] = a1.w;
        int gn = n0 + bn;
        const float* Wp = W + (size_t)(k0 + bk) * ldw + gn;
        float4 bv;
        bv.x = (gn + 0 < Nn) ? Wp[0] : 0.f;
        bv.y = (gn + 1 < Nn) ? Wp[1] : 0.f;
        bv.z = (gn + 2 < Nn) ? Wp[2] : 0.f;
        bv.w = (gn + 3 < Nn) ? Wp[3] : 0.f;
        *(float4*)&Bs[bk][bn] = bv;
        __syncthreads();
#pragma unroll
        for (int kk = 0; kk < 16; kk++) {
            float4 a04 = *(const float4*)&As[kk][ty * 8];
            float4 a14 = *(const float4*)&As[kk][ty * 8 + 4];
            float4 b4  = *(const float4*)&Bs[kk][tx * 4];
            float a[8] = {a04.x, a04.y, a04.z, a04.w, a14.x, a14.y, a14.z, a14.w};
            float bb[4] = {b4.x, b4.y, b4.z, b4.w};
#pragma unroll
            for (int i = 0; i < 8; i++)
#pragma unroll
                for (int j = 0; j < 4; j++)
                    acc[i][j] += a[i] * bb[j];
        }
        __syncthreads();
    }
    int nbase = n0 + tx * 4;
#pragma unroll
    for (int i = 0; i < 8; i++) {
        size_t rowoff = (size_t)(m0 + ty * 8 + i) * Nn;
#pragma unroll
        for (int j = 0; j < 4; j++) {
            int n = nbase + j;
            if (n < Nn) {
                float v = acc[i][j];
                if (BIAS) v += bias[n];
                if (RELU) v = fmaxf(v, 0.f);
                if (RES) v += res[rowoff + n];
                Cout[rowoff + n] = v;
            }
        }
    }
}

// =====================================================================
// tensor-core flash attention (tf32 split => ~fp32 accuracy)
// grid (T/64, B*H), 128 threads (4 warps x 16 query rows)
// =====================================================================
#define AST 68
#define ATTN_SMEM (6 * 64 * AST * 4)

__global__ __launch_bounds__(128, 2) void attn_tc_kernel(const float* __restrict__ QKV,
                                                         float* __restrict__ O) {
    extern __shared__ float sme[];
    float* Kh = sme;
    float* Kl = Kh + 64 * AST;
    float* Vh = Kl + 64 * AST;
    float* Vl = Vh + 64 * AST;
    float* Ph = Vl + 64 * AST;
    float* Pl = Ph + 64 * AST;

    const int qt = gridDim.x - 1 - blockIdx.x;
    const int bh = blockIdx.y;
    const int b = bh / Hh, h = bh % Hh;
    const int tid = threadIdx.x;
    const int warp = tid >> 5, lane = tid & 31;
    const int g = lane >> 2, t4 = lane & 3;
    const int r0l = warp * 16 + g;
    const int r1l = r0l + 8;

#pragma unroll
    for (int i = 0; i < 8; i++) {
        int ch = tid + i * 128;
        int r = ch >> 4, c4 = ch & 15;
        float4 v = *(const float4*)(QKV + (size_t)(b * Tt + qt * 64 + r) * QKVS + h * HSd + c4 * 4);
        v.x *= 0.125f; v.y *= 0.125f; v.z *= 0.125f; v.w *= 0.125f;
        *(float4*)(Ph + r * AST + c4 * 4) = v;
    }
    __syncthreads();

    uint32_t qh[8][4], ql[8][4];
#pragma unroll
    for (int ks = 0; ks < 8; ks++) {
        int k0 = ks * 8;
        float v[4];
        v[0] = Ph[r0l * AST + k0 + t4];
        v[1] = Ph[r1l * AST + k0 + t4];
        v[2] = Ph[r0l * AST + k0 + t4 + 4];
        v[3] = Ph[r1l * AST + k0 + t4 + 4];
#pragma unroll
        for (int j = 0; j < 4; j++) {
            float hi = f2tf(v[j]);
            qh[ks][j] = __float_as_uint(hi);
            ql[ks][j] = __float_as_uint(f2tf(v[j] - hi));
        }
    }

    float o[8][4];
#pragma unroll
    for (int nt = 0; nt < 8; nt++)
#pragma unroll
        for (int j = 0; j < 4; j++) o[nt][j] = 0.f;
    float m0 = -1e30f, m1 = -1e30f, l0 = 0.f, l1 = 0.f;

    for (int kt = 0; kt <= qt; kt++) {
        __syncthreads();
#pragma unroll
        for (int i = 0; i < 8; i++) {
            int ch = tid + i * 128;
            int r = ch >> 4, c4 = ch & 15;
            size_t go = (size_t)(b * Tt + kt * 64 + r) * QKVS + h * HSd;
            float4 kv = *(const float4*)(QKV + go + Cd + c4 * 4);
            float4 vv = *(const float4*)(QKV + go + 2 * Cd + c4 * 4);
            float4 khv, klv, vhv, vlv;
            khv.x = f2tf(kv.x); klv.x = f2tf(kv.x - khv.x);
            khv.y = f2tf(kv.y); klv.y = f2tf(kv.y - khv.y);
            khv.z = f2tf(kv.z); klv.z = f2tf(kv.z - khv.z);
            khv.w = f2tf(kv.w); klv.w = f2tf(kv.w - khv.w);
            vhv.x = f2tf(vv.x); vlv.x = f2tf(vv.x - vhv.x);
            vhv.y = f2tf(vv.y); vlv.y = f2tf(vv.y - vhv.y);
            vhv.z = f2tf(vv.z); vlv.z = f2tf(vv.z - vhv.z);
            vhv.w = f2tf(vv.w); vlv.w = f2tf(vv.w - vhv.w);
            *(float4*)(Kh + r * AST + c4 * 4) = khv;
            *(float4*)(Kl + r * AST + c4 * 4) = klv;
            *(float4*)(Vh + r * AST + c4 * 4) = vhv;
            *(float4*)(Vl + r * AST + c4 * 4) = vlv;
        }
        __syncthreads();

        float sacc[8][4];
#pragma unroll
        for (int nt = 0; nt < 8; nt++)
#pragma unroll
            for (int j = 0; j < 4; j++) sacc[nt][j] = 0.f;
#pragma unroll
        for (int ks = 0; ks < 8; ks++) {
            int k0 = ks * 8;
#pragma unroll
            for (int nt = 0; nt < 8; nt++) {
                int j = nt * 8 + g;
                uint32_t bh_[2], bl_[2];
                bh_[0] = __float_as_uint(Kh[j * AST + k0 + t4]);
                bh_[1] = __float_as_uint(Kh[j * AST + k0 + t4 + 4]);
                bl_[0] = __float_as_uint(Kl[j * AST + k0 + t4]);
                bl_[1] = __float_as_uint(Kl[j * AST + k0 + t4 + 4]);
                mma8(sacc[nt], qh[ks], bh_);
                mma8(sacc[nt], qh[ks], bl_);
                mma8(sacc[nt], ql[ks], bh_);
            }
        }

        if (kt == qt) {
#pragma unroll
            for (int nt = 0; nt < 8; nt++) {
                int c0 = nt * 8 + 2 * t4;
                if (c0     > r0l) sacc[nt][0] = -1e30f;
                if (c0 + 1 > r0l) sacc[nt][1] = -1e30f;
                if (c0     > r1l) sacc[nt][2] = -1e30f;
                if (c0 + 1 > r1l) sacc[nt][3] = -1e30f;
            }
        }

        float tm0 = -1e30f, tm1 = -1e30f;
#pragma unroll
        for (int nt = 0; nt < 8; nt++) {
            tm0 = fmaxf(tm0, fmaxf(sacc[nt][0], sacc[nt][1]));
            tm1 = fmaxf(tm1, fmaxf(sacc[nt][2], sacc[nt][3]));
        }
        tm0 = fmaxf(tm0, __shfl_xor_sync(0xffffffffu, tm0, 1));
        tm0 = fmaxf(tm0, __shfl_xor_sync(0xffffffffu, tm0, 2));
        tm1 = fmaxf(tm1, __shfl_xor_sync(0xffffffffu, tm1, 1));
        tm1 = fmaxf(tm1, __shfl_xor_sync(0xffffffffu, tm1, 2));
        float mN0 = fmaxf(m0, tm0), mN1 = fmaxf(m1, tm1);
        float a0 = __expf(m0 - mN0), a1 = __expf(m1 - mN1);
        m0 = mN0; m1 = mN1;

        float sum0 = 0.f, sum1 = 0.f;
#pragma unroll
        for (int nt = 0; nt < 8; nt++) {
            float p0 = __expf(sacc[nt][0] - mN0);
            float p1 = __expf(sacc[nt][1] - mN0);
            float p2 = __expf(sacc[nt][2] - mN1);
            float p3 = __expf(sacc[nt][3] - mN1);
            sum0 += p0 + p1;
            sum1 += p2 + p3;
            int c0 = nt * 8 + 2 * t4;
            float h0 = f2tf(p0), h1 = f2tf(p1), h2 = f2tf(p2), h3 = f2tf(p3);
            *(float2*)(Ph + r0l * AST + c0) = make_float2(h0, h1);
            *(float2*)(Pl + r0l * AST + c0) = make_float2(f2tf(p0 - h0), f2tf(p1 - h1));
            *(float2*)(Ph + r1l * AST + c0) = make_float2(h2, h3);
            *(float2*)(Pl + r1l * AST + c0) = make_float2(f2tf(p2 - h2), f2tf(p3 - h3));
        }
        sum0 += __shfl_xor_sync(0xffffffffu, sum0, 1);
        sum0 += __shfl_xor_sync(0xffffffffu, sum0, 2);
        sum1 += __shfl_xor_sync(0xffffffffu, sum1, 1);
        sum1 += __shfl_xor_sync(0xffffffffu, sum1, 2);
        l0 = l0 * a0 + sum0;
        l1 = l1 * a1 + sum1;
#pragma unroll
        for (int nt = 0; nt < 8; nt++) {
            o[nt][0] *= a0; o[nt][1] *= a0;
            o[nt][2] *= a1; o[nt][3] *= a1;
        }
        __syncwarp();

#pragma unroll
        for (int ks = 0; ks < 8; ks++) {
            int k0 = ks * 8;
            uint32_t ah[4], al[4];
            ah[0] = __float_as_uint(Ph[r0l * AST + k0 + t4]);
            ah[1] = __float_as_uint(Ph[r1l * AST + k0 + t4]);
            ah[2] = __float_as_uint(Ph[r0l * AST + k0 + t4 + 4]);
            ah[3] = __float_as_uint(Ph[r1l * AST + k0 + t4 + 4]);
            al[0] = __float_as_uint(Pl[r0l * AST + k0 + t4]);
            al[1] = __float_as_uint(Pl[r1l * AST + k0 + t4]);
            al[2] = __float_as_uint(Pl[r0l * AST + k0 + t4 + 4]);
            al[3] = __float_as_uint(Pl[r1l * AST + k0 + t4 + 4]);
#pragma unroll
            for (int nt = 0; nt < 8; nt++) {
                int d = nt * 8 + g;
                uint32_t bh_[2], bl_[2];
                bh_[0] = __float_as_uint(Vh[(k0 + t4) * AST + d]);
                bh_[1] = __float_as_uint(Vh[(k0 + t4 + 4) * AST + d]);
                bl_[0] = __float_as_uint(Vl[(k0 + t4) * AST + d]);
                bl_[1] = __float_as_uint(Vl[(k0 + t4 + 4) * AST + d]);
                mma8(o[nt], ah, bh_);
                mma8(o[nt], ah, bl_);
                mma8(o[nt], al, bh_);
            }
        }
    }

    float i0 = 1.f / l0, i1 = 1.f / l1;
    size_t row0 = (size_t)(b * Tt + qt * 64 + r0l) * Cd + h * HSd;
    size_t row1 = (size_t)(b * Tt + qt * 64 + r1l) * Cd + h * HSd;
#pragma unroll
    for (int nt = 0; nt < 8; nt++) {
        int c0 = nt * 8 + 2 * t4;
        *(float2*)(O + row0 + c0) = make_float2(f2tf(o[nt][0] * i0), f2tf(o[nt][1] * i0));
        *(float2*)(O + row1 + c0) = make_float2(f2tf(o[nt][2] * i1), f2tf(o[nt][3] * i1));
    }
}

// ---------------- loss kernels ----------------
__global__ __launch_bounds__(256) void rowloss_kernel(const float* __restrict__ logits,
                                                      const int* __restrict__ tgt,
                                                      float* __restrict__ rl) {
    int r = blockIdx.x;
    const float* lr = logits + (size_t)r * Vv;
    float m = -1e30f;
    for (int c = threadIdx.x; c < Vv; c += 256) m = fmaxf(m, lr[c]);
    m = blockReduceMax256(m);
    float s = 0.f;
    for (int c = threadIdx.x; c < Vv; c += 256) s += __expf(lr[c] - m);
    s = blockReduceSum256(s);
    if (threadIdx.x == 0) rl[r] = m + logf(s) - lr[tgt[r]];
}

__global__ __launch_bounds__(256) void lossreduce_kernel(const float* __restrict__ rl,
                                                         float* __restrict__ out) {
    float s = 0.f;
    for (int i = threadIdx.x; i < NT; i += 256) s += rl[i];
    s = blockReduceSum256(s);
    if (threadIdx.x == 0) out[0] = s * (1.0f / NT);
}

__global__ void lse_init_kernel(float* lm, float* ls, float* lt) {
    int i = blockIdx.x * blockDim.x + threadIdx.x;
    if (i < NT) { lm[i] = -1e30f; ls[i] = 0.f; lt[i] = 0.f; }
}

__global__ __launch_bounds__(256) void chunkloss_kernel(const float* __restrict__ chunk,
                                                        int width, int col0,
                                                        const int* __restrict__ tgt,
                                                        float* __restrict__ lm,
                                                        float* __restrict__ ls,
                                                        float* __restrict__ lt) {
    int r = blockIdx.x;
    const float* cr = chunk + (size_t)r * width;
    float m = -1e30f;
    for (int c = threadIdx.x; c < width; c += 256) m = fmaxf(m, cr[c]);
    m = blockReduceMax256(m);
    float s = 0.f;
    for (int c = threadIdx.x; c < width; c += 256) s += __expf(cr[c] - m);
    s = blockReduceSum256(s);
    if (threadIdx.x == 0) {
        float mOld = lm[r];
        float mNew = fmaxf(mOld, m);
        ls[r] = ls[r] * __expf(mOld - mNew) + s * __expf(m - mNew);
        lm[r] = mNew;
        int tg = tgt[r] - col0;
        if (tg >= 0 && tg < width) lt[r] = cr[tg];
    }
}

__global__ void chunkfinal_kernel(const float* lm, const float* ls, const float* lt,
                                  float* rl) {
    int i = blockIdx.x * blockDim.x + threadIdx.x;
    if (i < NT) rl[i] = lm[i] + logf(ls[i]) - lt[i];
}

// ---------------- host driver ----------------
static float* devptr(const void* sym) {
    void* p = nullptr;
    cudaGetSymbolAddress(&p, sym);
    return (float*)p;
}

extern "C" void kernel_launch(void* const* d_in, const int* in_sizes, int n_in,
                              void* d_out, int out_size) {
    const int* inputs    = (const int*)d_in[0];
    const int* targets   = (const int*)d_in[1];
    const float* tok     = (const float*)d_in[2];
    const float* pos     = (const float*)d_in[3];
    const float* ln1g    = (const float*)d_in[4];
    const float* ln1b    = (const float*)d_in[5];
    const float* ln2g    = (const float*)d_in[6];
    const float* ln2b    = (const float*)d_in[7];
    const float* wq      = (const float*)d_in[8];
    const float* wk      = (const float*)d_in[9];
    const float* wv      = (const float*)d_in[10];
    const float* wo      = (const float*)d_in[11];
    const float* bo      = (const float*)d_in[12];
    const float* w1      = (const float*)d_in[13];
    const float* b1      = (const float*)d_in[14];
    const float* w2      = (const float*)d_in[15];
    const float* b2      = (const float*)d_in[16];
    const float* lnfg    = (const float*)d_in[17];
    const float* lnfb    = (const float*)d_in[18];
    const float* whead   = (const float*)d_in[19];
    const float* bhead   = (const float*)d_in[20];

    float* x   = devptr(g_x);
    float* h   = devptr(g_h);
    float* qkv = devptr(g_qkv);
    float* ob  = devptr(g_ob);
    float* fb  = devptr(g_f);
    float* rl  = devptr(g_rowloss);
    float* lm  = devptr(g_lm);
    float* ls  = devptr(g_ls);
    float* lt  = devptr(g_lt);
    float* wt  = devptr(g_wt);

    cudaFuncSetAttribute(mma_gemm<false, false, false, false, false>, cudaFuncAttributeMaxDynamicSharedMemorySize, GEMM_SMEM);
    cudaFuncSetAttribute(mma_gemm<true, false, true, false, false>,   cudaFuncAttributeMaxDynamicSharedMemorySize, GEMM_SMEM);
    cudaFuncSetAttribute(mma_gemm<true, true, false, false, true>,    cudaFuncAttributeMaxDynamicSharedMemorySize, GEMM_SMEM);
    cudaFuncSetAttribute(mma_gemm<true, false, false, true, false>,   cudaFuncAttributeMaxDynamicSharedMemorySize, GEMM_SMEM);
    cudaFuncSetAttribute(attn_tc_kernel, cudaFuncAttributeMaxDynamicSharedMemorySize, ATTN_SMEM);

    // ---- weight prep: tf32-round (and pack/pad) once per launch ----
    qkvpack_kernel<<<2048, 256>>>(wq, wt + OFF_QKV, 0);
    qkvpack_kernel<<<2048, 256>>>(wk, wt + OFF_QKV, 1);
    qkvpack_kernel<<<2048, 256>>>(wv, wt + OFF_QKV, 2);
    roundcopy_kernel<<<2048, 256>>>(wo, wt + OFF_WO, (size_t)Ll * Cd * Cd);
    roundcopy_kernel<<<4096, 256>>>(w1, wt + OFF_W1, (size_t)Ll * Cd * Fd);
    roundcopy_kernel<<<4096, 256>>>(w2, wt + OFF_W2, (size_t)Ll * Fd * Cd);
    {
        dim3 gHp((VPAD + 255) / 256, Cd);
        headpad_kernel<<<gHp, 256>>>(whead, wt + OFF_HD);
    }

    dim3 gQKV(NT / 128, QKVS / 128);
    dim3 gC(NT / 128, Cd / 128);
    dim3 gF(NT / 128, Fd / 128);
    dim3 gV(NT / 128, (Vv + 127) / 128);
    dim3 gAttn(Tt / 64, Bq * Hh);

    embed_kernel<<<NT, 256>>>(inputs, tok, pos, x);

    for (int l = 0; l < Ll; l++) {
        const float* wqkv = wt + OFF_QKV + (size_t)l * Cd * QKVS;
        const float* wot  = wt + OFF_WO + (size_t)l * Cd * Cd;
        const float* w1t  = wt + OFF_W1 + (size_t)l * Cd * Fd;
        const float* w2t  = wt + OFF_W2 + (size_t)l * Fd * Cd;

        ln_kernel<<<NT / 8, 256>>>(x, ln1g + l * Cd, ln1b + l * Cd, h);
        mma_gemm<false, false, false, false, false><<<gQKV, 256, GEMM_SMEM>>>(
            h, wqkv, nullptr, nullptr, qkv, NT, QKVS, Cd, QKVS);
        attn_tc_kernel<<<gAttn, 128, ATTN_SMEM>>>(qkv, ob);
        mma_gemm<true, false, true, false, false><<<gC, 256, GEMM_SMEM>>>(
            ob, wot, bo + l * Cd, x, x, NT, Cd, Cd, Cd);
        ln_kernel<<<NT / 8, 256>>>(x, ln2g + l * Cd, ln2b + l * Cd, h);
        mma_gemm<true, true, false, false, true><<<gF, 256, GEMM_SMEM>>>(
            h, w1t, b1 + (size_t)l * Fd, nullptr, fb, NT, Fd, Cd, Fd);
        mma_gemm<true, false, true, false, false><<<gC, 256, GEMM_SMEM>>>(
            fb, w2t, b2 + l * Cd, x, x, NT, Cd, Fd, Cd);
    }

    ln_kernel<<<NT / 8, 256>>>(x, lnfg, lnfb, h);

    const long long NV = (long long)NT * Vv;
    if ((long long)out_size >= NV) {
        float* logits = (float*)d_out;
        mma_gemm<true, false, false, true, false><<<gV, 256, GEMM_SMEM>>>(
            h, wt + OFF_HD, bhead, nullptr, logits, NT, Vv, Cd, VPAD);
        if ((long long)out_size > NV) {
            rowloss_kernel<<<NT, 256>>>(logits, targets, rl);
            lossreduce_kernel<<<1, 256>>>(rl, (float*)d_out + NV);
        }
    } else {
        lse_init_kernel<<<(NT + 255) / 256, 256>>>(lm, ls, lt);
        const int CW = 3072;
        for (int col0 = 0; col0 < Vv; col0 += CW) {
            int width = (Vv - col0 < CW) ? (Vv - col0) : CW;
            dim3 gCk(NT / 128, (width + 63) / 64);
            sgemm_kernel<true, false, false><<<gCk, 256>>>(h, whead + col0, bhead + col0,
                                                           nullptr, fb, NT, width, Cd, Vv);
            chunkloss_kernel<<<NT, 256>>>(fb, width, col0, targets, lm, ls, lt);
        }
        chunkfinal_kernel<<<(NT + 255) / 256, 256>>>(lm, ls, lt, rl);
        lossreduce_kernel<<<1, 256>>>(rl, (float*)d_out);
    }
}

// round 7
// speedup vs baseline: 6.9726x; 1.8836x over previous
#include <cuda_runtime.h>
#include <cuda_fp16.h>
#include <math.h>
#include <stdint.h>

// ---------------- problem constants (GPT-2 small forward) ----------------
#define Bq   8
#define Tt   1024
#define NT   8192          // B*T tokens
#define Cd   768
#define Hh   12
#define HSd  64
#define Fd   3072
#define Ll   12
#define Vv   50257
#define VPAD 50304         // multiple of 128
#define QKVS 2304          // fused qkv width

// ---------------- scratch (device globals: allocation-free) --------------
__device__ float  g_x[(size_t)NT * Cd];        // residual stream (fp32)
__device__ __half g_h[(size_t)NT * Cd];        // LN output (fp16)
__device__ __half g_qkv[(size_t)NT * QKVS];    // fused q|k|v (fp16)
__device__ __half g_ob[(size_t)NT * Cd];       // attention out (fp16)
__device__ __half g_f[(size_t)NT * Fd];        // MLP hidden (fp16)
__device__ float  g_rowloss[NT];
__device__ float  g_lm[NT];
__device__ float  g_ls[NT];
__device__ float  g_lt[NT];

// fp16 weights, pre-transposed to [N][K] (K-contiguous)
#define OFF_QKV ((size_t)0)                        // [L][2304][768]
#define OFF_WO  ((size_t)21233664)                 // [L][768][768]
#define OFF_W1  ((size_t)28311552)                 // [L][3072][768]
#define OFF_W2  ((size_t)56623104)                 // [L][768][3072]
#define OFF_HD  ((size_t)84934656)                 // [VPAD][768]
#define WTH_TOTAL ((size_t)84934656 + (size_t)VPAD * Cd)
__device__ __half g_wth[WTH_TOTAL];

// ---------------- helpers ----------------
__device__ __forceinline__ uint32_t smem_u32(const void* p) {
    uint32_t a;
    asm("{ .reg .u64 t; cvta.to.shared.u64 t, %1; cvt.u32.u64 %0, t; }" : "=r"(a) : "l"(p));
    return a;
}

__device__ __forceinline__ void cp16(uint32_t saddr, const void* gaddr) {
    asm volatile("cp.async.cg.shared.global [%0], [%1], 16;" :: "r"(saddr), "l"(gaddr));
}
#define CP_COMMIT() asm volatile("cp.async.commit_group;" ::: "memory")
#define CP_WAIT1()  asm volatile("cp.async.wait_group 1;" ::: "memory")
#define CP_WAIT0()  asm volatile("cp.async.wait_group 0;" ::: "memory")

__device__ __forceinline__ void mma16(float* c, const uint32_t* a, const uint32_t* b) {
    asm volatile(
        "mma.sync.aligned.m16n8k16.row.col.f32.f16.f16.f32 "
        "{%0,%1,%2,%3}, {%4,%5,%6,%7}, {%8,%9}, {%0,%1,%2,%3};\n"
        : "+f"(c[0]), "+f"(c[1]), "+f"(c[2]), "+f"(c[3])
        : "r"(a[0]), "r"(a[1]), "r"(a[2]), "r"(a[3]), "r"(b[0]), "r"(b[1]));
}

// ---------------- block reduce helpers ----------------
__device__ __forceinline__ float blockReduceSum256(float v) {
    __shared__ float sh[8];
    int lane = threadIdx.x & 31, w = threadIdx.x >> 5;
#pragma unroll
    for (int o = 16; o; o >>= 1) v += __shfl_xor_sync(0xffffffffu, v, o);
    if (lane == 0) sh[w] = v;
    __syncthreads();
    float r = (threadIdx.x < 8) ? sh[threadIdx.x] : 0.f;
    if (w == 0) {
#pragma unroll
        for (int o = 4; o; o >>= 1) r += __shfl_xor_sync(0xffffffffu, r, o);
    }
    __syncthreads();
    if (threadIdx.x == 0) sh[0] = r;
    __syncthreads();
    return sh[0];
}

__device__ __forceinline__ float blockReduceMax256(float v) {
    __shared__ float sh[8];
    int lane = threadIdx.x & 31, w = threadIdx.x >> 5;
#pragma unroll
    for (int o = 16; o; o >>= 1) v = fmaxf(v, __shfl_xor_sync(0xffffffffu, v, o));
    if (lane == 0) sh[w] = v;
    __syncthreads();
    float r = (threadIdx.x < 8) ? sh[threadIdx.x] : -1e30f;
    if (w == 0) {
#pragma unroll
        for (int o = 4; o; o >>= 1) r = fmaxf(r, __shfl_xor_sync(0xffffffffu, r, o));
    }
    __syncthreads();
    if (threadIdx.x == 0) sh[0] = r;
    __syncthreads();
    return sh[0];
}

// ---------------- weight prep: transpose f32 [K][N] -> fp16 [Npad][K] -----
__global__ void transpose_h_kernel(const float* __restrict__ src, __half* __restrict__ dst,
                                   int K, int N, int Npad,
                                   size_t sstride, size_t dstride) {
    src += (size_t)blockIdx.z * sstride;
    dst += (size_t)blockIdx.z * dstride;
    __shared__ float t[32][33];
    int kb = blockIdx.y * 32, nb = blockIdx.x * 32;
    int tx = threadIdx.x, ty = threadIdx.y;
    for (int i = ty; i < 32; i += 8) {
        int k = kb + i, n = nb + tx;
        t[i][tx] = (k < K && n < N) ? src[(size_t)k * N + n] : 0.f;
    }
    __syncthreads();
    for (int i = ty; i < 32; i += 8) {
        int n = nb + i, k = kb + tx;
        if (n < Npad && k < K) dst[(size_t)n * K + k] = __float2half_rn(t[tx][i]);
    }
}

// =====================================================================
// fp16 mma.sync GEMM: C[M,Nn] = A[M,K](fp16) @ Wt[N][K](fp16)^T
// BM=128, BN=128, BK=64, 256 threads (8 warps, warp tile 64x32)
// cp.async 3-stage pipeline; tiles [128][72] halfs (pad, conflict-free)
// =====================================================================
#define ASTH 72
#define HTILE_H (128 * ASTH)            // 9216 halfs
#define HSTG_H  (2 * HTILE_H)           // A + B
#define NSTG 3
#define GEMM_SMEM (NSTG * HSTG_H * 2)   // 110592 bytes

template<bool BIAS, bool RELU, bool RES, bool NBOUND, bool OUTH>
__global__ __launch_bounds__(256, 2) void mma_gemm(
    const __half* __restrict__ A, const __half* __restrict__ Wt,
    const float* __restrict__ bias, const float* __restrict__ res,
    void* __restrict__ Cv, int M, int Nn, int K) {
    extern __shared__ __half smh[];
    const uint32_t su = smem_u32(smh);
    const int tid = threadIdx.x;
    const int warp = tid >> 5, lane = tid & 31;
    const int g = lane >> 2, t4 = lane & 3;
    const int wm = warp >> 2, wn = warp & 3;
    const int warp_m0 = wm * 64, warp_n0 = wn * 32;
    const int m0 = blockIdx.x * 128;
    const int n0 = blockIdx.y * 128;

    float acc[4][4][4];
#pragma unroll
    for (int mt = 0; mt < 4; mt++)
#pragma unroll
        for (int nt = 0; nt < 4; nt++)
#pragma unroll
            for (int j = 0; j < 4; j++) acc[mt][nt][j] = 0.f;

    const int nk = K >> 6;

    auto load_stage = [&](int s, int kb) {
        uint32_t sa = su + (uint32_t)s * HSTG_H * 2;
#pragma unroll
        for (int i = 0; i < 4; i++) {
            int ch = tid + i * 256;
            int r = ch >> 3, c = ch & 7;
            cp16(sa + (uint32_t)(r * ASTH + c * 8) * 2,
                 A + (size_t)(m0 + r) * K + kb + c * 8);
        }
        uint32_t sb = sa + HTILE_H * 2;
#pragma unroll
        for (int i = 0; i < 4; i++) {
            int ch = tid + i * 256;
            int r = ch >> 3, c = ch & 7;
            cp16(sb + (uint32_t)(r * ASTH + c * 8) * 2,
                 Wt + (size_t)(n0 + r) * K + kb + c * 8);
        }
        CP_COMMIT();
    };

    load_stage(0, 0);
    load_stage(1, 64);

    int s = 0;
    for (int kc = 0; kc < nk; kc++) {
        if (kc + 1 < nk) CP_WAIT1(); else CP_WAIT0();
        __syncthreads();

        const __half* sA = smh + s * HSTG_H;
        const __half* sB = sA + HTILE_H;
#pragma unroll
        for (int ks = 0; ks < 4; ks++) {
            const int kk = ks * 16;
            uint32_t af[4][4], bf[4][2];
#pragma unroll
            for (int mt = 0; mt < 4; mt++) {
                int r0 = warp_m0 + mt * 16 + g;
                af[mt][0] = *(const uint32_t*)(sA + r0 * ASTH + kk + 2 * t4);
                af[mt][1] = *(const uint32_t*)(sA + (r0 + 8) * ASTH + kk + 2 * t4);
                af[mt][2] = *(const uint32_t*)(sA + r0 * ASTH + kk + 2 * t4 + 8);
                af[mt][3] = *(const uint32_t*)(sA + (r0 + 8) * ASTH + kk + 2 * t4 + 8);
            }
#pragma unroll
            for (int nt = 0; nt < 4; nt++) {
                int cn = warp_n0 + nt * 8 + g;
                bf[nt][0] = *(const uint32_t*)(sB + cn * ASTH + kk + 2 * t4);
                bf[nt][1] = *(const uint32_t*)(sB + cn * ASTH + kk + 2 * t4 + 8);
            }
#pragma unroll
            for (int mt = 0; mt < 4; mt++)
#pragma unroll
                for (int nt = 0; nt < 4; nt++)
                    mma16(acc[mt][nt], af[mt], bf[nt]);
        }

        if (kc + 2 < nk) {
            int sw = s + 2; if (sw >= NSTG) sw -= NSTG;
            load_stage(sw, (kc + 2) * 64);
        }
        if (++s == NSTG) s = 0;
    }

    // ---- epilogue ----
#pragma unroll
    for (int mt = 0; mt < 4; mt++) {
        int r0 = m0 + warp_m0 + mt * 16 + g;
#pragma unroll
        for (int nt = 0; nt < 4; nt++) {
            int cn = n0 + warp_n0 + nt * 8 + t4 * 2;
            float* a4 = acc[mt][nt];
            float b0 = 0.f, b1 = 0.f;
            if (BIAS) {
                if (!NBOUND) { b0 = bias[cn]; b1 = bias[cn + 1]; }
                else {
                    b0 = (cn < Nn) ? bias[cn] : 0.f;
                    b1 = (cn + 1 < Nn) ? bias[cn + 1] : 0.f;
                }
            }
#pragma unroll
            for (int half_ = 0; half_ < 2; half_++) {
                int r = r0 + half_ * 8;
                float v0 = a4[half_ * 2 + 0] + b0;
                float v1 = a4[half_ * 2 + 1] + b1;
                if (RELU) { v0 = fmaxf(v0, 0.f); v1 = fmaxf(v1, 0.f); }
                size_t off = (size_t)r * Nn + cn;
                if (!NBOUND) {
                    if (RES) { v0 += res[off]; v1 += res[off + 1]; }
                    if (OUTH) {
                        *(__half2*)((__half*)Cv + off) = __floats2half2_rn(v0, v1);
                    } else {
                        *(float2*)((float*)Cv + off) = make_float2(v0, v1);
                    }
                } else {
                    float* C = (float*)Cv;
                    if (cn < Nn) {
                        if (RES) v0 += res[off];
                        C[off] = v0;
                    }
                    if (cn + 1 < Nn) {
                        if (RES) v1 += res[off + 1];
                        C[off + 1] = v1;
                    }
                }
            }
        }
    }
}

// ---------------- embedding ----------------
__global__ void embed_kernel(const int* __restrict__ inp,
                             const float* __restrict__ tok,
                             const float* __restrict__ pos,
                             float* __restrict__ x) {
    int i = blockIdx.x;
    int t = i & (Tt - 1);
    int v = inp[i];
    const float* te = tok + (size_t)v * Cd;
    const float* pe = pos + (size_t)t * Cd;
    float* xo = x + (size_t)i * Cd;
    for (int c = threadIdx.x; c < Cd; c += blockDim.x)
        xo[c] = te[c] + pe[c];
}

// ---------------- layernorm: warp per row, fp16 output ----------------
__global__ __launch_bounds__(256) void ln_kernel(const float* __restrict__ x,
                                                 const float* __restrict__ g,
                                                 const float* __restrict__ b,
                                                 __half* __restrict__ out) {
    const int warp = threadIdx.x >> 5, lane = threadIdx.x & 31;
    const int row = blockIdx.x * 8 + warp;
    const float4* xr = (const float4*)(x + (size_t)row * Cd);
    const float4* gp = (const float4*)g;
    const float4* bp = (const float4*)b;
    __half* orow = out + (size_t)row * Cd;

    float4 v[6];
    float s = 0.f;
#pragma unroll
    for (int i = 0; i < 6; i++) {
        v[i] = xr[lane + i * 32];
        s += v[i].x + v[i].y + v[i].z + v[i].w;
    }
#pragma unroll
    for (int o = 16; o; o >>= 1) s += __shfl_xor_sync(0xffffffffu, s, o);
    float mean = s * (1.0f / Cd);

    float vs = 0.f;
#pragma unroll
    for (int i = 0; i < 6; i++) {
        float dx = v[i].x - mean, dy = v[i].y - mean,
              dz = v[i].z - mean, dw = v[i].w - mean;
        vs += dx * dx + dy * dy + dz * dz + dw * dw;
    }
#pragma unroll
    for (int o = 16; o; o >>= 1) vs += __shfl_xor_sync(0xffffffffu, vs, o);
    float rstd = rsqrtf(vs * (1.0f / Cd) + 1e-5f);

#pragma unroll
    for (int i = 0; i < 6; i++) {
        float4 gg = gp[lane + i * 32];
        float4 bb = bp[lane + i * 32];
        __half2 h01 = __floats2half2_rn((v[i].x - mean) * rstd * gg.x + bb.x,
                                        (v[i].y - mean) * rstd * gg.y + bb.y);
        __half2 h23 = __floats2half2_rn((v[i].z - mean) * rstd * gg.z + bb.z,
                                        (v[i].w - mean) * rstd * gg.w + bb.w);
        uint2 pk = make_uint2(*(uint32_t*)&h01, *(uint32_t*)&h23);
        *(uint2*)(orow + (lane + i * 32) * 4) = pk;
    }
}

// ---------------- fp16 -> fp32 convert (fallback path) ----------------
__global__ void h2f_kernel(const __half* __restrict__ src, float* __restrict__ dst, size_t n) {
    for (size_t i = (size_t)blockIdx.x * blockDim.x + threadIdx.x; i < n;
         i += (size_t)gridDim.x * blockDim.x)
        dst[i] = __half2float(src[i]);
}

// ---------------- SIMT SGEMM (loss-only fallback path) ----------------
template<bool BIAS, bool RELU, bool RES>
__global__ __launch_bounds__(256) void sgemm_kernel(
    const float* __restrict__ A, const float* __restrict__ W,
    const float* __restrict__ bias, const float* __restrict__ res,
    float* __restrict__ Cout, int M, int Nn, int K, int ldw) {
    __shared__ float As[16][132];
    __shared__ float Bs[16][64];
    int tid = threadIdx.x;
    int m0 = blockIdx.x * 128;
    int n0 = blockIdx.y * 64;
    int tx = tid & 15, ty = tid >> 4;
    float acc[8][4];
#pragma unroll
    for (int i = 0; i < 8; i++)
#pragma unroll
        for (int j = 0; j < 4; j++) acc[i][j] = 0.f;
    int am = tid >> 1;
    int ak = (tid & 1) * 8;
    int bk = tid >> 4;
    int bn = (tid & 15) * 4;
    for (int k0 = 0; k0 < K; k0 += 16) {
        const float* Ap = A + (size_t)(m0 + am) * K + k0 + ak;
        float4 a0 = *(const float4*)Ap;
        float4 a1 = *(const float4*)(Ap + 4);
        As[ak + 0][am] = a0.x; As[ak + 1][am] = a0.y;
        As[ak + 2][am] = a0.z; As[ak + 3][am] = a0.w;
        As[ak + 4][am] = a1.x; As[ak + 5][am] = a1.y;
        As[ak + 6][am] = a1.z; As[ak + 7][am] = a1.w;
        int gn = n0 + bn;
        const float* Wp = W + (size_t)(k0 + bk) * ldw + gn;
        float4 bv;
        bv.x = (gn + 0 < Nn) ? Wp[0] : 0.f;
        bv.y = (gn + 1 < Nn) ? Wp[1] : 0.f;
        bv.z = (gn + 2 < Nn) ? Wp[2] : 0.f;
        bv.w = (gn + 3 < Nn) ? Wp[3] : 0.f;
        *(float4*)&Bs[bk][bn] = bv;
        __syncthreads();
#pragma unroll
        for (int kk = 0; kk < 16; kk++) {
            float4 a04 = *(const float4*)&As[kk][ty * 8];
            float4 a14 = *(const float4*)&As[kk][ty * 8 + 4];
            float4 b4  = *(const float4*)&Bs[kk][tx * 4];
            float a[8] = {a04.x, a04.y, a04.z, a04.w, a14.x, a14.y, a14.z, a14.w};
            float bb[4] = {b4.x, b4.y, b4.z, b4.w};
#pragma unroll
            for (int i = 0; i < 8; i++)
#pragma unroll
                for (int j = 0; j < 4; j++)
                    acc[i][j] += a[i] * bb[j];
        }
        __syncthreads();
    }
    int nbase = n0 + tx * 4;
#pragma unroll
    for (int i = 0; i < 8; i++) {
        size_t rowoff = (size_t)(m0 + ty * 8 + i) * Nn;
#pragma unroll
        for (int j = 0; j < 4; j++) {
            int n = nbase + j;
            if (n < Nn) {
                float v = acc[i][j];
                if (BIAS) v += bias[n];
                if (RELU) v = fmaxf(v, 0.f);
                if (RES) v += res[rowoff + n];
                Cout[rowoff + n] = v;
            }
        }
    }
}

// =====================================================================
// fp16 tensor-core flash attention (S exact; P split hi/lo fp16)
// grid (T/64, B*H), 128 threads (4 warps x 16 query rows)
// smem: Ks[64][72], Vs(transposed,swizzled)[64][72], Ph[64][72], Pl[64][72]
// =====================================================================
#define AST2 72
#define ATTN_SMEM (4 * 64 * AST2 * 2)   // 36864 bytes

__global__ __launch_bounds__(128, 4) void attn_tc_kernel(const __half* __restrict__ QKV,
                                                         __half* __restrict__ O) {
    extern __shared__ __half sme[];
    __half* Ks = sme;
    __half* Vs = Ks + 64 * AST2;
    __half* Ph = Vs + 64 * AST2;
    __half* Pl = Ph + 64 * AST2;

    const int qt = gridDim.x - 1 - blockIdx.x;
    const int bh = blockIdx.y;
    const int b = bh / Hh, h = bh % Hh;
    const int tid = threadIdx.x;
    const int warp = tid >> 5, lane = tid & 31;
    const int g = lane >> 2, t4 = lane & 3;
    const int r0l = warp * 16 + g;
    const int r1l = r0l + 8;

    // ---- stage Q tile (fp16, unscaled) into Ph; load fragments ----
#pragma unroll
    for (int i = 0; i < 4; i++) {
        int ch = tid + i * 128;
        int r = ch >> 3, c8 = (ch & 7) * 8;
        float4 v = *(const float4*)(QKV + (size_t)(b * Tt + qt * 64 + r) * QKVS + h * HSd + c8);
        *(float4*)(Ph + r * AST2 + c8) = v;
    }
    __syncthreads();

    uint32_t qf[4][4];
#pragma unroll
    for (int ks = 0; ks < 4; ks++) {
        int kk = ks * 16;
        qf[ks][0] = *(const uint32_t*)(Ph + r0l * AST2 + kk + 2 * t4);
        qf[ks][1] = *(const uint32_t*)(Ph + r1l * AST2 + kk + 2 * t4);
        qf[ks][2] = *(const uint32_t*)(Ph + r0l * AST2 + kk + 2 * t4 + 8);
        qf[ks][3] = *(const uint32_t*)(Ph + r1l * AST2 + kk + 2 * t4 + 8);
    }

    float o[8][4];
#pragma unroll
    for (int nt = 0; nt < 8; nt++)
#pragma unroll
        for (int j = 0; j < 4; j++) o[nt][j] = 0.f;
    float m0 = -1e30f, m1 = -1e30f, l0 = 0.f, l1 = 0.f;

    for (int kt = 0; kt <= qt; kt++) {
        __syncthreads();
        // ---- load K tile [j][d]; V tile transposed+swizzled [d][j^( (d>>3)<<3 )] ----
#pragma unroll
        for (int i = 0; i < 4; i++) {
            int ch = tid + i * 128;
            int r = ch >> 3, c8 = (ch & 7) * 8;
            size_t go = (size_t)(b * Tt + kt * 64 + r) * QKVS + h * HSd + c8;
            float4 kv = *(const float4*)(QKV + Cd + go);
            *(float4*)(Ks + r * AST2 + c8) = kv;
            float4 vv = *(const float4*)(QKV + 2 * Cd + go);
            const __half* hv = (const __half*)&vv;
            int rs = r ^ c8;   // (d>>3)<<3 == c8 for d in [c8, c8+8)
#pragma unroll
            for (int dd = 0; dd < 8; dd++)
                Vs[(c8 + dd) * AST2 + rs] = hv[dd];
        }
        __syncthreads();

        // ---- S = Q K^T (exact fp16 mma), then scale in fp32 ----
        float sacc[8][4];
#pragma unroll
        for (int nt = 0; nt < 8; nt++)
#pragma unroll
            for (int j = 0; j < 4; j++) sacc[nt][j] = 0.f;
#pragma unroll
        for (int ks = 0; ks < 4; ks++) {
            int kk = ks * 16;
#pragma unroll
            for (int nt = 0; nt < 8; nt++) {
                int j = nt * 8 + g;
                uint32_t bf[2];
                bf[0] = *(const uint32_t*)(Ks + j * AST2 + kk + 2 * t4);
                bf[1] = *(const uint32_t*)(Ks + j * AST2 + kk + 2 * t4 + 8);
                mma16(sacc[nt], qf[ks], bf);
            }
        }
#pragma unroll
        for (int nt = 0; nt < 8; nt++)
#pragma unroll
            for (int j = 0; j < 4; j++) sacc[nt][j] *= 0.125f;

        // ---- causal mask on diagonal tile ----
        if (kt == qt) {
#pragma unroll
            for (int nt = 0; nt < 8; nt++) {
                int c0 = nt * 8 + 2 * t4;
                if (c0     > r0l) sacc[nt][0] = -1e30f;
                if (c0 + 1 > r0l) sacc[nt][1] = -1e30f;
                if (c0     > r1l) sacc[nt][2] = -1e30f;
                if (c0 + 1 > r1l) sacc[nt][3] = -1e30f;
            }
        }

        // ---- online softmax ----
        float tm0 = -1e30f, tm1 = -1e30f;
#pragma unroll
        for (int nt = 0; nt < 8; nt++) {
            tm0 = fmaxf(tm0, fmaxf(sacc[nt][0], sacc[nt][1]));
            tm1 = fmaxf(tm1, fmaxf(sacc[nt][2], sacc[nt][3]));
        }
        tm0 = fmaxf(tm0, __shfl_xor_sync(0xffffffffu, tm0, 1));
        tm0 = fmaxf(tm0, __shfl_xor_sync(0xffffffffu, tm0, 2));
        tm1 = fmaxf(tm1, __shfl_xor_sync(0xffffffffu, tm1, 1));
        tm1 = fmaxf(tm1, __shfl_xor_sync(0xffffffffu, tm1, 2));
        float mN0 = fmaxf(m0, tm0), mN1 = fmaxf(m1, tm1);
        float a0 = __expf(m0 - mN0), a1 = __expf(m1 - mN1);
        m0 = mN0; m1 = mN1;

        float sum0 = 0.f, sum1 = 0.f;
#pragma unroll
        for (int nt = 0; nt < 8; nt++) {
            float p0 = __expf(sacc[nt][0] - mN0);
            float p1 = __expf(sacc[nt][1] - mN0);
            float p2 = __expf(sacc[nt][2] - mN1);
            float p3 = __expf(sacc[nt][3] - mN1);
            sum0 += p0 + p1;
            sum1 += p2 + p3;
            int c0 = nt * 8 + 2 * t4;
            __half2 h01 = __floats2half2_rn(p0, p1);
            __half2 h23 = __floats2half2_rn(p2, p3);
            *(__half2*)(Ph + r0l * AST2 + c0) = h01;
            *(__half2*)(Ph + r1l * AST2 + c0) = h23;
            *(__half2*)(Pl + r0l * AST2 + c0) =
                __floats2half2_rn(p0 - __half2float(__low2half(h01)),
                                  p1 - __half2float(__high2half(h01)));
            *(__half2*)(Pl + r1l * AST2 + c0) =
                __floats2half2_rn(p2 - __half2float(__low2half(h23)),
                                  p3 - __half2float(__high2half(h23)));
        }
        sum0 += __shfl_xor_sync(0xffffffffu, sum0, 1);
        sum0 += __shfl_xor_sync(0xffffffffu, sum0, 2);
        sum1 += __shfl_xor_sync(0xffffffffu, sum1, 1);
        sum1 += __shfl_xor_sync(0xffffffffu, sum1, 2);
        l0 = l0 * a0 + sum0;
        l1 = l1 * a1 + sum1;
#pragma unroll
        for (int nt = 0; nt < 8; nt++) {
            o[nt][0] *= a0; o[nt][1] *= a0;
            o[nt][2] *= a1; o[nt][3] *= a1;
        }
        __syncwarp();

        // ---- O += P V (P hi+lo, V exact) ----
#pragma unroll
        for (int ks = 0; ks < 4; ks++) {
            int kk = ks * 16;
            uint32_t ah[4], al[4];
            ah[0] = *(const uint32_t*)(Ph + r0l * AST2 + kk + 2 * t4);
            ah[1] = *(const uint32_t*)(Ph + r1l * AST2 + kk + 2 * t4);
            ah[2] = *(const uint32_t*)(Ph + r0l * AST2 + kk + 2 * t4 + 8);
            ah[3] = *(const uint32_t*)(Ph + r1l * AST2 + kk + 2 * t4 + 8);
            al[0] = *(const uint32_t*)(Pl + r0l * AST2 + kk + 2 * t4);
            al[1] = *(const uint32_t*)(Pl + r1l * AST2 + kk + 2 * t4);
            al[2] = *(const uint32_t*)(Pl + r0l * AST2 + kk + 2 * t4 + 8);
            al[3] = *(const uint32_t*)(Pl + r1l * AST2 + kk + 2 * t4 + 8);
#pragma unroll
            for (int nt = 0; nt < 8; nt++) {
                int d = nt * 8 + g;
                int swz = nt * 8;
                uint32_t bf[2];
                bf[0] = *(const uint32_t*)(Vs + d * AST2 + ((kk + 2 * t4) ^ swz));
                bf[1] = *(const uint32_t*)(Vs + d * AST2 + ((kk + 2 * t4 + 8) ^ swz));
                mma16(o[nt], ah, bf);
                mma16(o[nt], al, bf);
            }
        }
    }

    // ---- epilogue: normalize, store fp16 ----
    float i0 = 1.f / l0, i1 = 1.f / l1;
    size_t row0 = (size_t)(b * Tt + qt * 64 + r0l) * Cd + h * HSd;
    size_t row1 = (size_t)(b * Tt + qt * 64 + r1l) * Cd + h * HSd;
#pragma unroll
    for (int nt = 0; nt < 8; nt++) {
        int c0 = nt * 8 + 2 * t4;
        *(__half2*)(O + row0 + c0) = __floats2half2_rn(o[nt][0] * i0, o[nt][1] * i0);
        *(__half2*)(O + row1 + c0) = __floats2half2_rn(o[nt][2] * i1, o[nt][3] * i1);
    }
}

// ---------------- loss kernels ----------------
__global__ __launch_bounds__(256) void rowloss_kernel(const float* __restrict__ logits,
                                                      const int* __restrict__ tgt,
                                                      float* __restrict__ rl) {
    int r = blockIdx.x;
    const float* lr = logits + (size_t)r * Vv;
    float m = -1e30f;
    for (int c = threadIdx.x; c < Vv; c += 256) m = fmaxf(m, lr[c]);
    m = blockReduceMax256(m);
    float s = 0.f;
    for (int c = threadIdx.x; c < Vv; c += 256) s += __expf(lr[c] - m);
    s = blockReduceSum256(s);
    if (threadIdx.x == 0) rl[r] = m + logf(s) - lr[tgt[r]];
}

__global__ __launch_bounds__(256) void lossreduce_kernel(const float* __restrict__ rl,
                                                         float* __restrict__ out) {
    float s = 0.f;
    for (int i = threadIdx.x; i < NT; i += 256) s += rl[i];
    s = blockReduceSum256(s);
    if (threadIdx.x == 0) out[0] = s * (1.0f / NT);
}

__global__ void lse_init_kernel(float* lm, float* ls, float* lt) {
    int i = blockIdx.x * blockDim.x + threadIdx.x;
    if (i < NT) { lm[i] = -1e30f; ls[i] = 0.f; lt[i] = 0.f; }
}

__global__ __launch_bounds__(256) void chunkloss_kernel(const float* __restrict__ chunk,
                                                        int width, int col0,
                                                        const int* __restrict__ tgt,
                                                        float* __restrict__ lm,
                                                        float* __restrict__ ls,
                                                        float* __restrict__ lt) {
    int r = blockIdx.x;
    const float* cr = chunk + (size_t)r * width;
    float m = -1e30f;
    for (int c = threadIdx.x; c < width; c += 256) m = fmaxf(m, cr[c]);
    m = blockReduceMax256(m);
    float s = 0.f;
    for (int c = threadIdx.x; c < width; c += 256) s += __expf(cr[c] - m);
    s = blockReduceSum256(s);
    if (threadIdx.x == 0) {
        float mOld = lm[r];
        float mNew = fmaxf(mOld, m);
        ls[r] = ls[r] * __expf(mOld - mNew) + s * __expf(m - mNew);
        lm[r] = mNew;
        int tg = tgt[r] - col0;
        if (tg >= 0 && tg < width) lt[r] = cr[tg];
    }
}

__global__ void chunkfinal_kernel(const float* lm, const float* ls, const float* lt,
                                  float* rl) {
    int i = blockIdx.x * blockDim.x + threadIdx.x;
    if (i < NT) rl[i] = lm[i] + logf(ls[i]) - lt[i];
}

// ---------------- host driver ----------------
static void* devptr(const void* sym) {
    void* p = nullptr;
    cudaGetSymbolAddress(&p, sym);
    return p;
}

extern "C" void kernel_launch(void* const* d_in, const int* in_sizes, int n_in,
                              void* d_out, int out_size) {
    const int* inputs    = (const int*)d_in[0];
    const int* targets   = (const int*)d_in[1];
    const float* tok     = (const float*)d_in[2];
    const float* pos     = (const float*)d_in[3];
    const float* ln1g    = (const float*)d_in[4];
    const float* ln1b    = (const float*)d_in[5];
    const float* ln2g    = (const float*)d_in[6];
    const float* ln2b    = (const float*)d_in[7];
    const float* wq      = (const float*)d_in[8];
    const float* wk      = (const float*)d_in[9];
    const float* wv      = (const float*)d_in[10];
    const float* wo      = (const float*)d_in[11];
    const float* bo      = (const float*)d_in[12];
    const float* w1      = (const float*)d_in[13];
    const float* b1      = (const float*)d_in[14];
    const float* w2      = (const float*)d_in[15];
    const float* b2      = (const float*)d_in[16];
    const float* lnfg    = (const float*)d_in[17];
    const float* lnfb    = (const float*)d_in[18];
    const float* whead   = (const float*)d_in[19];
    const float* bhead   = (const float*)d_in[20];

    float*  x   = (float*)devptr(g_x);
    __half* h   = (__half*)devptr(g_h);
    __half* qkv = (__half*)devptr(g_qkv);
    __half* ob  = (__half*)devptr(g_ob);
    __half* fb  = (__half*)devptr(g_f);
    float*  rl  = (float*)devptr(g_rowloss);
    float*  lm  = (float*)devptr(g_lm);
    float*  ls  = (float*)devptr(g_ls);
    float*  lt  = (float*)devptr(g_lt);
    __half* wth = (__half*)devptr(g_wth);

    cudaFuncSetAttribute(mma_gemm<false, false, false, false, true>, cudaFuncAttributeMaxDynamicSharedMemorySize, GEMM_SMEM);
    cudaFuncSetAttribute(mma_gemm<true, false, true, false, false>,  cudaFuncAttributeMaxDynamicSharedMemorySize, GEMM_SMEM);
    cudaFuncSetAttribute(mma_gemm<true, true, false, false, true>,   cudaFuncAttributeMaxDynamicSharedMemorySize, GEMM_SMEM);
    cudaFuncSetAttribute(mma_gemm<true, false, false, true, false>,  cudaFuncAttributeMaxDynamicSharedMemorySize, GEMM_SMEM);
    cudaFuncSetAttribute(attn_tc_kernel, cudaFuncAttributeMaxDynamicSharedMemorySize, ATTN_SMEM);

    // ---- weight prep: fp16 convert + transpose to [N][K], once per launch ----
    {
        dim3 blk(32, 8);
        size_t cc = (size_t)Cd * Cd, cf = (size_t)Cd * Fd;
        dim3 gCC(Cd / 32, Cd / 32, Ll);
        transpose_h_kernel<<<gCC, blk>>>(wq, wth + OFF_QKV + (size_t)0 * cc, Cd, Cd, Cd, cc, (size_t)QKVS * Cd);
        transpose_h_kernel<<<gCC, blk>>>(wk, wth + OFF_QKV + (size_t)1 * cc, Cd, Cd, Cd, cc, (size_t)QKVS * Cd);
        transpose_h_kernel<<<gCC, blk>>>(wv, wth + OFF_QKV + (size_t)2 * cc, Cd, Cd, Cd, cc, (size_t)QKVS * Cd);
        transpose_h_kernel<<<gCC, blk>>>(wo, wth + OFF_WO, Cd, Cd, Cd, cc, cc);
        dim3 gW1(Fd / 32, Cd / 32, Ll);
        transpose_h_kernel<<<gW1, blk>>>(w1, wth + OFF_W1, Cd, Fd, Fd, cf, cf);
        dim3 gW2(Cd / 32, Fd / 32, Ll);
        transpose_h_kernel<<<gW2, blk>>>(w2, wth + OFF_W2, Fd, Cd, Cd, cf, cf);
        dim3 gHd(VPAD / 32, Cd / 32, 1);
        transpose_h_kernel<<<gHd, blk>>>(whead, wth + OFF_HD, Cd, Vv, VPAD, 0, 0);
    }

    dim3 gQKV(NT / 128, QKVS / 128);
    dim3 gC(NT / 128, Cd / 128);
    dim3 gF(NT / 128, Fd / 128);
    dim3 gV(NT / 128, VPAD / 128);
    dim3 gAttn(Tt / 64, Bq * Hh);

    embed_kernel<<<NT, 256>>>(inputs, tok, pos, x);

    for (int l = 0; l < Ll; l++) {
        const __half* wqkv = wth + OFF_QKV + (size_t)l * Cd * QKVS;
        const __half* wot  = wth + OFF_WO + (size_t)l * Cd * Cd;
        const __half* w1t  = wth + OFF_W1 + (size_t)l * Cd * Fd;
        const __half* w2t  = wth + OFF_W2 + (size_t)l * Fd * Cd;

        ln_kernel<<<NT / 8, 256>>>(x, ln1g + l * Cd, ln1b + l * Cd, h);
        mma_gemm<false, false, false, false, true><<<gQKV, 256, GEMM_SMEM>>>(
            h, wqkv, nullptr, nullptr, qkv, NT, QKVS, Cd);
        attn_tc_kernel<<<gAttn, 128, ATTN_SMEM>>>(qkv, ob);
        mma_gemm<true, false, true, false, false><<<gC, 256, GEMM_SMEM>>>(
            ob, wot, bo + l * Cd, x, x, NT, Cd, Cd);
        ln_kernel<<<NT / 8, 256>>>(x, ln2g + l * Cd, ln2b + l * Cd, h);
        mma_gemm<true, true, false, false, true><<<gF, 256, GEMM_SMEM>>>(
            h, w1t, b1 + (size_t)l * Fd, nullptr, fb, NT, Fd, Cd);
        mma_gemm<true, false, true, false, false><<<gC, 256, GEMM_SMEM>>>(
            fb, w2t, b2 + l * Cd, x, x, NT, Cd, Fd);
    }

    ln_kernel<<<NT / 8, 256>>>(x, lnfg, lnfb, h);

    const long long NV = (long long)NT * Vv;
    if ((long long)out_size >= NV) {
        float* logits = (float*)d_out;
        mma_gemm<true, false, false, true, false><<<gV, 256, GEMM_SMEM>>>(
            h, wth + OFF_HD, bhead, nullptr, logits, NT, Vv, Cd);
        if ((long long)out_size > NV) {
            rowloss_kernel<<<NT, 256>>>(logits, targets, rl);
            lossreduce_kernel<<<1, 256>>>(rl, (float*)d_out + NV);
        }
    } else {
        // loss-only fallback: convert h to fp32 (x is free) then chunked lse
        h2f_kernel<<<2048, 256>>>(h, x, (size_t)NT * Cd);
        lse_init_kernel<<<(NT + 255) / 256, 256>>>(lm, ls, lt);
        const int CW = 3072;
        float* fbuf = (float*)devptr(g_f);   // reuse as fp32 scratch (big enough)
        for (int col0 = 0; col0 < Vv; col0 += CW) {
            int width = (Vv - col0 < CW) ? (Vv - col0) : CW;
            dim3 gCk(NT / 128, (width + 63) / 64);
            sgemm_kernel<true, false, false><<<gCk, 256>>>(x, whead + col0, bhead + col0,
                                                           nullptr, fbuf, NT, width, Cd, Vv);
            chunkloss_kernel<<<NT, 256>>>(fbuf, width, col0, targets, lm, ls, lt);
        }
        chunkfinal_kernel<<<(NT + 255) / 256, 256>>>(lm, ls, lt, rl);
        lossreduce_kernel<<<1, 256>>>(rl, (float*)d_out);
    }
}

// round 8
// speedup vs baseline: 7.1675x; 1.0280x over previous
#include <cuda_runtime.h>
#include <cuda_fp16.h>
#include <math.h>
#include <stdint.h>

// ---------------- problem constants (GPT-2 small forward) ----------------
#define Bq   8
#define Tt   1024
#define NT   8192          // B*T tokens
#define Cd   768
#define Hh   12
#define HSd  64
#define Fd   3072
#define Ll   12
#define Vv   50257
#define VPAD 50304         // multiple of 128
#define QKVS 2304          // fused qkv width
#define GEMM_GRID 304      // ~2 CTAs/SM on 152 SMs

// ---------------- scratch (device globals: allocation-free) --------------
__device__ float  g_x[(size_t)NT * Cd];        // residual stream (fp32)
__device__ __half g_h[(size_t)NT * Cd];        // LN output (fp16)
__device__ __half g_qkv[(size_t)NT * QKVS];    // fused q|k|v (fp16)
__device__ __half g_ob[(size_t)NT * Cd];       // attention out (fp16)
__device__ __half g_f[(size_t)NT * Fd];        // MLP hidden (fp16)
__device__ float  g_rowloss[NT];
__device__ float  g_lm[NT];
__device__ float  g_ls[NT];
__device__ float  g_lt[NT];

// fp16 weights, pre-transposed to [N][K] (K-contiguous)
#define OFF_QKV ((size_t)0)                        // [L][2304][768]
#define OFF_WO  ((size_t)21233664)                 // [L][768][768]
#define OFF_W1  ((size_t)28311552)                 // [L][3072][768]
#define OFF_W2  ((size_t)56623104)                 // [L][768][3072]
#define OFF_HD  ((size_t)84934656)                 // [VPAD][768]
#define WTH_TOTAL ((size_t)84934656 + (size_t)VPAD * Cd)
__device__ __half g_wth[WTH_TOTAL];

// ---------------- helpers ----------------
__device__ __forceinline__ uint32_t smem_u32(const void* p) {
    uint32_t a;
    asm("{ .reg .u64 t; cvta.to.shared.u64 t, %1; cvt.u32.u64 %0, t; }" : "=r"(a) : "l"(p));
    return a;
}

__device__ __forceinline__ void cp16(uint32_t saddr, const void* gaddr) {
    asm volatile("cp.async.cg.shared.global [%0], [%1], 16;" :: "r"(saddr), "l"(gaddr));
}
#define CP_COMMIT() asm volatile("cp.async.commit_group;" ::: "memory")
#define CP_WAIT1()  asm volatile("cp.async.wait_group 1;" ::: "memory")
#define CP_WAIT0()  asm volatile("cp.async.wait_group 0;" ::: "memory")

__device__ __forceinline__ void mma16(float* c, const uint32_t* a, const uint32_t* b) {
    asm volatile(
        "mma.sync.aligned.m16n8k16.row.col.f32.f16.f16.f32 "
        "{%0,%1,%2,%3}, {%4,%5,%6,%7}, {%8,%9}, {%0,%1,%2,%3};\n"
        : "+f"(c[0]), "+f"(c[1]), "+f"(c[2]), "+f"(c[3])
        : "r"(a[0]), "r"(a[1]), "r"(a[2]), "r"(a[3]), "r"(b[0]), "r"(b[1]));
}

__device__ __forceinline__ void ldsm_x4(uint32_t* r, uint32_t saddr) {
    asm volatile("ldmatrix.sync.aligned.m8n8.x4.shared.b16 {%0,%1,%2,%3}, [%4];"
                 : "=r"(r[0]), "=r"(r[1]), "=r"(r[2]), "=r"(r[3]) : "r"(saddr));
}
__device__ __forceinline__ void ldsm_x2(uint32_t* r, uint32_t saddr) {
    asm volatile("ldmatrix.sync.aligned.m8n8.x2.shared.b16 {%0,%1}, [%2];"
                 : "=r"(r[0]), "=r"(r[1]) : "r"(saddr));
}

// ---------------- block reduce helpers ----------------
__device__ __forceinline__ float blockReduceSum256(float v) {
    __shared__ float sh[8];
    int lane = threadIdx.x & 31, w = threadIdx.x >> 5;
#pragma unroll
    for (int o = 16; o; o >>= 1) v += __shfl_xor_sync(0xffffffffu, v, o);
    if (lane == 0) sh[w] = v;
    __syncthreads();
    float r = (threadIdx.x < 8) ? sh[threadIdx.x] : 0.f;
    if (w == 0) {
#pragma unroll
        for (int o = 4; o; o >>= 1) r += __shfl_xor_sync(0xffffffffu, r, o);
    }
    __syncthreads();
    if (threadIdx.x == 0) sh[0] = r;
    __syncthreads();
    return sh[0];
}

__device__ __forceinline__ float blockReduceMax256(float v) {
    __shared__ float sh[8];
    int lane = threadIdx.x & 31, w = threadIdx.x >> 5;
#pragma unroll
    for (int o = 16; o; o >>= 1) v = fmaxf(v, __shfl_xor_sync(0xffffffffu, v, o));
    if (lane == 0) sh[w] = v;
    __syncthreads();
    float r = (threadIdx.x < 8) ? sh[threadIdx.x] : -1e30f;
    if (w == 0) {
#pragma unroll
        for (int o = 4; o; o >>= 1) r = fmaxf(r, __shfl_xor_sync(0xffffffffu, r, o));
    }
    __syncthreads();
    if (threadIdx.x == 0) sh[0] = r;
    __syncthreads();
    return sh[0];
}

// ---------------- weight prep: transpose f32 [K][N] -> fp16 [Npad][K] -----
__global__ void transpose_h_kernel(const float* __restrict__ src, __half* __restrict__ dst,
                                   int K, int N, int Npad,
                                   size_t sstride, size_t dstride) {
    src += (size_t)blockIdx.z * sstride;
    dst += (size_t)blockIdx.z * dstride;
    __shared__ float t[32][33];
    int kb = blockIdx.y * 32, nb = blockIdx.x * 32;
    int tx = threadIdx.x, ty = threadIdx.y;
    for (int i = ty; i < 32; i += 8) {
        int k = kb + i, n = nb + tx;
        t[i][tx] = (k < K && n < N) ? src[(size_t)k * N + n] : 0.f;
    }
    __syncthreads();
    for (int i = ty; i < 32; i += 8) {
        int n = nb + i, k = kb + tx;
        if (n < Npad && k < K) dst[(size_t)n * K + k] = __float2half_rn(t[tx][i]);
    }
}

// =====================================================================
// fp16 mma.sync GEMM (persistent): C[M,Nn] = A[M,K](fp16) @ Wt[N][K]^T
// BM=128, BN=128, BK=64, 256 threads (8 warps, warp tile 64x32)
// cp.async 3-stage pipeline; ldmatrix fragment loads
// =====================================================================
#define ASTH 72
#define HTILE_H (128 * ASTH)            // 9216 halfs
#define HSTG_H  (2 * HTILE_H)           // A + B
#define NSTG 3
#define GEMM_SMEM (NSTG * HSTG_H * 2)   // 110592 bytes

template<bool BIAS, bool RELU, bool RES, bool NBOUND, bool OUTH>
__global__ __launch_bounds__(256, 2) void mma_gemm(
    const __half* __restrict__ A, const __half* __restrict__ Wt,
    const float* __restrict__ bias, const float* __restrict__ res,
    void* __restrict__ Cv, int M, int Nn, int K, int ntn) {
    extern __shared__ __half smh[];
    const uint32_t su = smem_u32(smh);
    const int tid = threadIdx.x;
    const int warp = tid >> 5, lane = tid & 31;
    const int g = lane >> 2, t4 = lane & 3;
    const int wm = warp >> 2, wn = warp & 3;
    const int warp_m0 = wm * 64, warp_n0 = wn * 32;

    // ldmatrix per-lane element offsets (within a stage)
    const int mA = lane >> 3;
    const int aRow = (mA & 1) * 8 + (lane & 7);
    const int aCol = (mA >> 1) * 8;
    uint32_t offA[4];
#pragma unroll
    for (int mt = 0; mt < 4; mt++)
        offA[mt] = (uint32_t)((warp_m0 + mt * 16 + aRow) * ASTH + aCol);
    const int lb = lane & 15;
    const int bRow = lb & 7;
    const int bCol = (lb >> 3) * 8;
    uint32_t offB[4];
#pragma unroll
    for (int nt = 0; nt < 4; nt++)
        offB[nt] = (uint32_t)(HTILE_H + (warp_n0 + nt * 8 + bRow) * ASTH + bCol);

    const int nk = K >> 6;
    const int ntm = M >> 7;
    const int ntiles = ntm * ntn;

    for (int tile = blockIdx.x; tile < ntiles; tile += gridDim.x) {
        const int m0 = (tile % ntm) * 128;
        const int n0 = (tile / ntm) * 128;
        __syncthreads();   // guard smem reuse across tiles

        float acc[4][4][4];
#pragma unroll
        for (int mt = 0; mt < 4; mt++)
#pragma unroll
            for (int nt = 0; nt < 4; nt++)
#pragma unroll
                for (int j = 0; j < 4; j++) acc[mt][nt][j] = 0.f;

        auto load_stage = [&](int s, int kb) {
            uint32_t sa = su + (uint32_t)s * HSTG_H * 2;
#pragma unroll
            for (int i = 0; i < 4; i++) {
                int ch = tid + i * 256;
                int r = ch >> 3, c = ch & 7;
                cp16(sa + (uint32_t)(r * ASTH + c * 8) * 2,
                     A + (size_t)(m0 + r) * K + kb + c * 8);
            }
            uint32_t sb = sa + HTILE_H * 2;
#pragma unroll
            for (int i = 0; i < 4; i++) {
                int ch = tid + i * 256;
                int r = ch >> 3, c = ch & 7;
                cp16(sb + (uint32_t)(r * ASTH + c * 8) * 2,
                     Wt + (size_t)(n0 + r) * K + kb + c * 8);
            }
            CP_COMMIT();
        };

        load_stage(0, 0);
        load_stage(1, 64);

        int s = 0;
        for (int kc = 0; kc < nk; kc++) {
            if (kc + 1 < nk) CP_WAIT1(); else CP_WAIT0();
            __syncthreads();

            const uint32_t sbase = su + (uint32_t)s * HSTG_H * 2;
#pragma unroll
            for (int ks = 0; ks < 4; ks++) {
                const int kk = ks * 16;
                uint32_t af[4][4], bf[4][2];
#pragma unroll
                for (int mt = 0; mt < 4; mt++)
                    ldsm_x4(af[mt], sbase + (offA[mt] + kk) * 2);
#pragma unroll
                for (int nt = 0; nt < 4; nt++)
                    ldsm_x2(bf[nt], sbase + (offB[nt] + kk) * 2);
#pragma unroll
                for (int mt = 0; mt < 4; mt++)
#pragma unroll
                    for (int nt = 0; nt < 4; nt++)
                        mma16(acc[mt][nt], af[mt], bf[nt]);
            }

            if (kc + 2 < nk) {
                int sw = s + 2; if (sw >= NSTG) sw -= NSTG;
                load_stage(sw, (kc + 2) * 64);
            }
            if (++s == NSTG) s = 0;
        }

        // ---- epilogue ----
#pragma unroll
        for (int mt = 0; mt < 4; mt++) {
            int r0 = m0 + warp_m0 + mt * 16 + g;
#pragma unroll
            for (int nt = 0; nt < 4; nt++) {
                int cn = n0 + warp_n0 + nt * 8 + t4 * 2;
                float* a4 = acc[mt][nt];
                float b0 = 0.f, b1 = 0.f;
                if (BIAS) {
                    if (!NBOUND) { b0 = bias[cn]; b1 = bias[cn + 1]; }
                    else {
                        b0 = (cn < Nn) ? bias[cn] : 0.f;
                        b1 = (cn + 1 < Nn) ? bias[cn + 1] : 0.f;
                    }
                }
#pragma unroll
                for (int half_ = 0; half_ < 2; half_++) {
                    int r = r0 + half_ * 8;
                    float v0 = a4[half_ * 2 + 0] + b0;
                    float v1 = a4[half_ * 2 + 1] + b1;
                    if (RELU) { v0 = fmaxf(v0, 0.f); v1 = fmaxf(v1, 0.f); }
                    size_t off = (size_t)r * Nn + cn;
                    if (!NBOUND) {
                        if (RES) { v0 += res[off]; v1 += res[off + 1]; }
                        if (OUTH) {
                            *(__half2*)((__half*)Cv + off) = __floats2half2_rn(v0, v1);
                        } else {
                            *(float2*)((float*)Cv + off) = make_float2(v0, v1);
                        }
                    } else {
                        float* C = (float*)Cv;
                        if (cn < Nn) {
                            if (RES) v0 += res[off];
                            C[off] = v0;
                        }
                        if (cn + 1 < Nn) {
                            if (RES) v1 += res[off + 1];
                            C[off + 1] = v1;
                        }
                    }
                }
            }
        }
    }
}

// ---------------- embedding ----------------
__global__ void embed_kernel(const int* __restrict__ inp,
                             const float* __restrict__ tok,
                             const float* __restrict__ pos,
                             float* __restrict__ x) {
    int i = blockIdx.x;
    int t = i & (Tt - 1);
    int v = inp[i];
    const float* te = tok + (size_t)v * Cd;
    const float* pe = pos + (size_t)t * Cd;
    float* xo = x + (size_t)i * Cd;
    for (int c = threadIdx.x; c < Cd; c += blockDim.x)
        xo[c] = te[c] + pe[c];
}

// ---------------- layernorm: warp per row, fp16 output ----------------
__global__ __launch_bounds__(256) void ln_kernel(const float* __restrict__ x,
                                                 const float* __restrict__ g,
                                                 const float* __restrict__ b,
                                                 __half* __restrict__ out) {
    const int warp = threadIdx.x >> 5, lane = threadIdx.x & 31;
    const int row = blockIdx.x * 8 + warp;
    const float4* xr = (const float4*)(x + (size_t)row * Cd);
    const float4* gp = (const float4*)g;
    const float4* bp = (const float4*)b;
    __half* orow = out + (size_t)row * Cd;

    float4 v[6];
    float s = 0.f;
#pragma unroll
    for (int i = 0; i < 6; i++) {
        v[i] = xr[lane + i * 32];
        s += v[i].x + v[i].y + v[i].z + v[i].w;
    }
#pragma unroll
    for (int o = 16; o; o >>= 1) s += __shfl_xor_sync(0xffffffffu, s, o);
    float mean = s * (1.0f / Cd);

    float vs = 0.f;
#pragma unroll
    for (int i = 0; i < 6; i++) {
        float dx = v[i].x - mean, dy = v[i].y - mean,
              dz = v[i].z - mean, dw = v[i].w - mean;
        vs += dx * dx + dy * dy + dz * dz + dw * dw;
    }
#pragma unroll
    for (int o = 16; o; o >>= 1) vs += __shfl_xor_sync(0xffffffffu, vs, o);
    float rstd = rsqrtf(vs * (1.0f / Cd) + 1e-5f);

#pragma unroll
    for (int i = 0; i < 6; i++) {
        float4 gg = gp[lane + i * 32];
        float4 bb = bp[lane + i * 32];
        __half2 h01 = __floats2half2_rn((v[i].x - mean) * rstd * gg.x + bb.x,
                                        (v[i].y - mean) * rstd * gg.y + bb.y);
        __half2 h23 = __floats2half2_rn((v[i].z - mean) * rstd * gg.z + bb.z,
                                        (v[i].w - mean) * rstd * gg.w + bb.w);
        uint2 pk = make_uint2(*(uint32_t*)&h01, *(uint32_t*)&h23);
        *(uint2*)(orow + (lane + i * 32) * 4) = pk;
    }
}

// ---------------- fp16 -> fp32 convert (fallback path) ----------------
__global__ void h2f_kernel(const __half* __restrict__ src, float* __restrict__ dst, size_t n) {
    for (size_t i = (size_t)blockIdx.x * blockDim.x + threadIdx.x; i < n;
         i += (size_t)gridDim.x * blockDim.x)
        dst[i] = __half2float(src[i]);
}

// ---------------- SIMT SGEMM (loss-only fallback path) ----------------
template<bool BIAS, bool RELU, bool RES>
__global__ __launch_bounds__(256) void sgemm_kernel(
    const float* __restrict__ A, const float* __restrict__ W,
    const float* __restrict__ bias, const float* __restrict__ res,
    float* __restrict__ Cout, int M, int Nn, int K, int ldw) {
    __shared__ float As[16][132];
    __shared__ float Bs[16][64];
    int tid = threadIdx.x;
    int m0 = blockIdx.x * 128;
    int n0 = blockIdx.y * 64;
    int tx = tid & 15, ty = tid >> 4;
    float acc[8][4];
#pragma unroll
    for (int i = 0; i < 8; i++)
#pragma unroll
        for (int j = 0; j < 4; j++) acc[i][j] = 0.f;
    int am = tid >> 1;
    int ak = (tid & 1) * 8;
    int bk = tid >> 4;
    int bn = (tid & 15) * 4;
    for (int k0 = 0; k0 < K; k0 += 16) {
        const float* Ap = A + (size_t)(m0 + am) * K + k0 + ak;
        float4 a0 = *(const float4*)Ap;
        float4 a1 = *(const float4*)(Ap + 4);
        As[ak + 0][am] = a0.x; As[ak + 1][am] = a0.y;
        As[ak + 2][am] = a0.z; As[ak + 3][am] = a0.w;
        As[ak + 4][am] = a1.x; As[ak + 5][am] = a1.y;
        As[ak + 6][am] = a1.z; As[ak + 7][am] = a1.w;
        int gn = n0 + bn;
        const float* Wp = W + (size_t)(k0 + bk) * ldw + gn;
        float4 bv;
        bv.x = (gn + 0 < Nn) ? Wp[0] : 0.f;
        bv.y = (gn + 1 < Nn) ? Wp[1] : 0.f;
        bv.z = (gn + 2 < Nn) ? Wp[2] : 0.f;
        bv.w = (gn + 3 < Nn) ? Wp[3] : 0.f;
        *(float4*)&Bs[bk][bn] = bv;
        __syncthreads();
#pragma unroll
        for (int kk = 0; kk < 16; kk++) {
            float4 a04 = *(const float4*)&As[kk][ty * 8];
            float4 a14 = *(const float4*)&As[kk][ty * 8 + 4];
            float4 b4  = *(const float4*)&Bs[kk][tx * 4];
            float a[8] = {a04.x, a04.y, a04.z, a04.w, a14.x, a14.y, a14.z, a14.w};
            float bb[4] = {b4.x, b4.y, b4.z, b4.w};
#pragma unroll
            for (int i = 0; i < 8; i++)
#pragma unroll
                for (int j = 0; j < 4; j++)
                    acc[i][j] += a[i] * bb[j];
        }
        __syncthreads();
    }
    int nbase = n0 + tx * 4;
#pragma unroll
    for (int i = 0; i < 8; i++) {
        size_t rowoff = (size_t)(m0 + ty * 8 + i) * Nn;
#pragma unroll
        for (int j = 0; j < 4; j++) {
            int n = nbase + j;
            if (n < Nn) {
                float v = acc[i][j];
                if (BIAS) v += bias[n];
                if (RELU) v = fmaxf(v, 0.f);
                if (RES) v += res[rowoff + n];
                Cout[rowoff + n] = v;
            }
        }
    }
}

// =====================================================================
// fp16 tensor-core flash attention (S exact; P split hi/lo fp16)
// =====================================================================
#define AST2 72
#define ATTN_SMEM (4 * 64 * AST2 * 2)   // 36864 bytes

__global__ __launch_bounds__(128, 4) void attn_tc_kernel(const __half* __restrict__ QKV,
                                                         __half* __restrict__ O) {
    extern __shared__ __half sme[];
    __half* Ks = sme;
    __half* Vs = Ks + 64 * AST2;
    __half* Ph = Vs + 64 * AST2;
    __half* Pl = Ph + 64 * AST2;

    const int qt = gridDim.x - 1 - blockIdx.x;
    const int bh = blockIdx.y;
    const int b = bh / Hh, h = bh % Hh;
    const int tid = threadIdx.x;
    const int warp = tid >> 5, lane = tid & 31;
    const int g = lane >> 2, t4 = lane & 3;
    const int r0l = warp * 16 + g;
    const int r1l = r0l + 8;

#pragma unroll
    for (int i = 0; i < 4; i++) {
        int ch = tid + i * 128;
        int r = ch >> 3, c8 = (ch & 7) * 8;
        float4 v = *(const float4*)(QKV + (size_t)(b * Tt + qt * 64 + r) * QKVS + h * HSd + c8);
        *(float4*)(Ph + r * AST2 + c8) = v;
    }
    __syncthreads();

    uint32_t qf[4][4];
#pragma unroll
    for (int ks = 0; ks < 4; ks++) {
        int kk = ks * 16;
        qf[ks][0] = *(const uint32_t*)(Ph + r0l * AST2 + kk + 2 * t4);
        qf[ks][1] = *(const uint32_t*)(Ph + r1l * AST2 + kk + 2 * t4);
        qf[ks][2] = *(const uint32_t*)(Ph + r0l * AST2 + kk + 2 * t4 + 8);
        qf[ks][3] = *(const uint32_t*)(Ph + r1l * AST2 + kk + 2 * t4 + 8);
    }

    float o[8][4];
#pragma unroll
    for (int nt = 0; nt < 8; nt++)
#pragma unroll
        for (int j = 0; j < 4; j++) o[nt][j] = 0.f;
    float m0 = -1e30f, m1 = -1e30f, l0 = 0.f, l1 = 0.f;

    for (int kt = 0; kt <= qt; kt++) {
        __syncthreads();
#pragma unroll
        for (int i = 0; i < 4; i++) {
            int ch = tid + i * 128;
            int r = ch >> 3, c8 = (ch & 7) * 8;
            size_t go = (size_t)(b * Tt + kt * 64 + r) * QKVS + h * HSd + c8;
            float4 kv = *(const float4*)(QKV + Cd + go);
            *(float4*)(Ks + r * AST2 + c8) = kv;
            float4 vv = *(const float4*)(QKV + 2 * Cd + go);
            const __half* hv = (const __half*)&vv;
            int rs = r ^ c8;
#pragma unroll
            for (int dd = 0; dd < 8; dd++)
                Vs[(c8 + dd) * AST2 + rs] = hv[dd];
        }
        __syncthreads();

        float sacc[8][4];
#pragma unroll
        for (int nt = 0; nt < 8; nt++)
#pragma unroll
            for (int j = 0; j < 4; j++) sacc[nt][j] = 0.f;
#pragma unroll
        for (int ks = 0; ks < 4; ks++) {
            int kk = ks * 16;
#pragma unroll
            for (int nt = 0; nt < 8; nt++) {
                int j = nt * 8 + g;
                uint32_t bf[2];
                bf[0] = *(const uint32_t*)(Ks + j * AST2 + kk + 2 * t4);
                bf[1] = *(const uint32_t*)(Ks + j * AST2 + kk + 2 * t4 + 8);
                mma16(sacc[nt], qf[ks], bf);
            }
        }
#pragma unroll
        for (int nt = 0; nt < 8; nt++)
#pragma unroll
            for (int j = 0; j < 4; j++) sacc[nt][j] *= 0.125f;

        if (kt == qt) {
#pragma unroll
            for (int nt = 0; nt < 8; nt++) {
                int c0 = nt * 8 + 2 * t4;
                if (c0     > r0l) sacc[nt][0] = -1e30f;
                if (c0 + 1 > r0l) sacc[nt][1] = -1e30f;
                if (c0     > r1l) sacc[nt][2] = -1e30f;
                if (c0 + 1 > r1l) sacc[nt][3] = -1e30f;
            }
        }

        float tm0 = -1e30f, tm1 = -1e30f;
#pragma unroll
        for (int nt = 0; nt < 8; nt++) {
            tm0 = fmaxf(tm0, fmaxf(sacc[nt][0], sacc[nt][1]));
            tm1 = fmaxf(tm1, fmaxf(sacc[nt][2], sacc[nt][3]));
        }
        tm0 = fmaxf(tm0, __shfl_xor_sync(0xffffffffu, tm0, 1));
        tm0 = fmaxf(tm0, __shfl_xor_sync(0xffffffffu, tm0, 2));
        tm1 = fmaxf(tm1, __shfl_xor_sync(0xffffffffu, tm1, 1));
        tm1 = fmaxf(tm1, __shfl_xor_sync(0xffffffffu, tm1, 2));
        float mN0 = fmaxf(m0, tm0), mN1 = fmaxf(m1, tm1);
        float a0 = __expf(m0 - mN0), a1 = __expf(m1 - mN1);
        m0 = mN0; m1 = mN1;

        float sum0 = 0.f, sum1 = 0.f;
#pragma unroll
        for (int nt = 0; nt < 8; nt++) {
            float p0 = __expf(sacc[nt][0] - mN0);
            float p1 = __expf(sacc[nt][1] - mN0);
            float p2 = __expf(sacc[nt][2] - mN1);
            float p3 = __expf(sacc[nt][3] - mN1);
            sum0 += p0 + p1;
            sum1 += p2 + p3;
            int c0 = nt * 8 + 2 * t4;
            __half2 h01 = __floats2half2_rn(p0, p1);
            __half2 h23 = __floats2half2_rn(p2, p3);
            *(__half2*)(Ph + r0l * AST2 + c0) = h01;
            *(__half2*)(Ph + r1l * AST2 + c0) = h23;
            *(__half2*)(Pl + r0l * AST2 + c0) =
                __floats2half2_rn(p0 - __half2float(__low2half(h01)),
                                  p1 - __half2float(__high2half(h01)));
            *(__half2*)(Pl + r1l * AST2 + c0) =
                __floats2half2_rn(p2 - __half2float(__low2half(h23)),
                                  p3 - __half2float(__high2half(h23)));
        }
        sum0 += __shfl_xor_sync(0xffffffffu, sum0, 1);
        sum0 += __shfl_xor_sync(0xffffffffu, sum0, 2);
        sum1 += __shfl_xor_sync(0xffffffffu, sum1, 1);
        sum1 += __shfl_xor_sync(0xffffffffu, sum1, 2);
        l0 = l0 * a0 + sum0;
        l1 = l1 * a1 + sum1;
#pragma unroll
        for (int nt = 0; nt < 8; nt++) {
            o[nt][0] *= a0; o[nt][1] *= a0;
            o[nt][2] *= a1; o[nt][3] *= a1;
        }
        __syncwarp();

#pragma unroll
        for (int ks = 0; ks < 4; ks++) {
            int kk = ks * 16;
            uint32_t ah[4], al[4];
            ah[0] = *(const uint32_t*)(Ph + r0l * AST2 + kk + 2 * t4);
            ah[1] = *(const uint32_t*)(Ph + r1l * AST2 + kk + 2 * t4);
            ah[2] = *(const uint32_t*)(Ph + r0l * AST2 + kk + 2 * t4 + 8);
            ah[3] = *(const uint32_t*)(Ph + r1l * AST2 + kk + 2 * t4 + 8);
            al[0] = *(const uint32_t*)(Pl + r0l * AST2 + kk + 2 * t4);
            al[1] = *(const uint32_t*)(Pl + r1l * AST2 + kk + 2 * t4);
            al[2] = *(const uint32_t*)(Pl + r0l * AST2 + kk + 2 * t4 + 8);
            al[3] = *(const uint32_t*)(Pl + r1l * AST2 + kk + 2 * t4 + 8);
#pragma unroll
            for (int nt = 0; nt < 8; nt++) {
                int d = nt * 8 + g;
                int swz = nt * 8;
                uint32_t bf[2];
                bf[0] = *(const uint32_t*)(Vs + d * AST2 + ((kk + 2 * t4) ^ swz));
                bf[1] = *(const uint32_t*)(Vs + d * AST2 + ((kk + 2 * t4 + 8) ^ swz));
                mma16(o[nt], ah, bf);
                mma16(o[nt], al, bf);
            }
        }
    }

    float i0 = 1.f / l0, i1 = 1.f / l1;
    size_t row0 = (size_t)(b * Tt + qt * 64 + r0l) * Cd + h * HSd;
    size_t row1 = (size_t)(b * Tt + qt * 64 + r1l) * Cd + h * HSd;
#pragma unroll
    for (int nt = 0; nt < 8; nt++) {
        int c0 = nt * 8 + 2 * t4;
        *(__half2*)(O + row0 + c0) = __floats2half2_rn(o[nt][0] * i0, o[nt][1] * i0);
        *(__half2*)(O + row1 + c0) = __floats2half2_rn(o[nt][2] * i1, o[nt][3] * i1);
    }
}

// ---------------- loss kernels ----------------
__global__ __launch_bounds__(256) void rowloss_kernel(const float* __restrict__ logits,
                                                      const int* __restrict__ tgt,
                                                      float* __restrict__ rl) {
    int r = blockIdx.x;
    const float* lr = logits + (size_t)r * Vv;
    float m = -1e30f;
    for (int c = threadIdx.x; c < Vv; c += 256) m = fmaxf(m, lr[c]);
    m = blockReduceMax256(m);
    float s = 0.f;
    for (int c = threadIdx.x; c < Vv; c += 256) s += __expf(lr[c] - m);
    s = blockReduceSum256(s);
    if (threadIdx.x == 0) rl[r] = m + logf(s) - lr[tgt[r]];
}

__global__ __launch_bounds__(256) void lossreduce_kernel(const float* __restrict__ rl,
                                                         float* __restrict__ out) {
    float s = 0.f;
    for (int i = threadIdx.x; i < NT; i += 256) s += rl[i];
    s = blockReduceSum256(s);
    if (threadIdx.x == 0) out[0] = s * (1.0f / NT);
}

__global__ void lse_init_kernel(float* lm, float* ls, float* lt) {
    int i = blockIdx.x * blockDim.x + threadIdx.x;
    if (i < NT) { lm[i] = -1e30f; ls[i] = 0.f; lt[i] = 0.f; }
}

__global__ __launch_bounds__(256) void chunkloss_kernel(const float* __restrict__ chunk,
                                                        int width, int col0,
                                                        const int* __restrict__ tgt,
                                                        float* __restrict__ lm,
                                                        float* __restrict__ ls,
                                                        float* __restrict__ lt) {
    int r = blockIdx.x;
    const float* cr = chunk + (size_t)r * width;
    float m = -1e30f;
    for (int c = threadIdx.x; c < width; c += 256) m = fmaxf(m, cr[c]);
    m = blockReduceMax256(m);
    float s = 0.f;
    for (int c = threadIdx.x; c < width; c += 256) s += __expf(cr[c] - m);
    s = blockReduceSum256(s);
    if (threadIdx.x == 0) {
        float mOld = lm[r];
        float mNew = fmaxf(mOld, m);
        ls[r] = ls[r] * __expf(mOld - mNew) + s * __expf(m - mNew);
        lm[r] = mNew;
        int tg = tgt[r] - col0;
        if (tg >= 0 && tg < width) lt[r] = cr[tg];
    }
}

__global__ void chunkfinal_kernel(const float* lm, const float* ls, const float* lt,
                                  float* rl) {
    int i = blockIdx.x * blockDim.x + threadIdx.x;
    if (i < NT) rl[i] = lm[i] + logf(ls[i]) - lt[i];
}

// ---------------- host driver ----------------
static void* devptr(const void* sym) {
    void* p = nullptr;
    cudaGetSymbolAddress(&p, sym);
    return p;
}

extern "C" void kernel_launch(void* const* d_in, const int* in_sizes, int n_in,
                              void* d_out, int out_size) {
    const int* inputs    = (const int*)d_in[0];
    const int* targets   = (const int*)d_in[1];
    const float* tok     = (const float*)d_in[2];
    const float* pos     = (const float*)d_in[3];
    const float* ln1g    = (const float*)d_in[4];
    const float* ln1b    = (const float*)d_in[5];
    const float* ln2g    = (const float*)d_in[6];
    const float* ln2b    = (const float*)d_in[7];
    const float* wq      = (const float*)d_in[8];
    const float* wk      = (const float*)d_in[9];
    const float* wv      = (const float*)d_in[10];
    const float* wo      = (const float*)d_in[11];
    const float* bo      = (const float*)d_in[12];
    const float* w1      = (const float*)d_in[13];
    const float* b1      = (const float*)d_in[14];
    const float* w2      = (const float*)d_in[15];
    const float* b2      = (const float*)d_in[16];
    const float* lnfg    = (const float*)d_in[17];
    const float* lnfb    = (const float*)d_in[18];
    const float* whead   = (const float*)d_in[19];
    const float* bhead   = (const float*)d_in[20];

    float*  x   = (float*)devptr(g_x);
    __half* h   = (__half*)devptr(g_h);
    __half* qkv = (__half*)devptr(g_qkv);
    __half* ob  = (__half*)devptr(g_ob);
    __half* fb  = (__half*)devptr(g_f);
    float*  rl  = (float*)devptr(g_rowloss);
    float*  lm  = (float*)devptr(g_lm);
    float*  ls  = (float*)devptr(g_ls);
    float*  lt  = (float*)devptr(g_lt);
    __half* wth = (__half*)devptr(g_wth);

    cudaFuncSetAttribute(mma_gemm<false, false, false, false, true>, cudaFuncAttributeMaxDynamicSharedMemorySize, GEMM_SMEM);
    cudaFuncSetAttribute(mma_gemm<true, false, true, false, false>,  cudaFuncAttributeMaxDynamicSharedMemorySize, GEMM_SMEM);
    cudaFuncSetAttribute(mma_gemm<true, true, false, false, true>,   cudaFuncAttributeMaxDynamicSharedMemorySize, GEMM_SMEM);
    cudaFuncSetAttribute(mma_gemm<true, false, false, true, false>,  cudaFuncAttributeMaxDynamicSharedMemorySize, GEMM_SMEM);
    cudaFuncSetAttribute(attn_tc_kernel, cudaFuncAttributeMaxDynamicSharedMemorySize, ATTN_SMEM);

    // ---- weight prep: fp16 convert + transpose to [N][K], once per launch ----
    {
        dim3 blk(32, 8);
        size_t cc = (size_t)Cd * Cd, cf = (size_t)Cd * Fd;
        dim3 gCC(Cd / 32, Cd / 32, Ll);
        transpose_h_kernel<<<gCC, blk>>>(wq, wth + OFF_QKV + (size_t)0 * cc, Cd, Cd, Cd, cc, (size_t)QKVS * Cd);
        transpose_h_kernel<<<gCC, blk>>>(wk, wth + OFF_QKV + (size_t)1 * cc, Cd, Cd, Cd, cc, (size_t)QKVS * Cd);
        transpose_h_kernel<<<gCC, blk>>>(wv, wth + OFF_QKV + (size_t)2 * cc, Cd, Cd, Cd, cc, (size_t)QKVS * Cd);
        transpose_h_kernel<<<gCC, blk>>>(wo, wth + OFF_WO, Cd, Cd, Cd, cc, cc);
        dim3 gW1(Fd / 32, Cd / 32, Ll);
        transpose_h_kernel<<<gW1, blk>>>(w1, wth + OFF_W1, Cd, Fd, Fd, cf, cf);
        dim3 gW2(Cd / 32, Fd / 32, Ll);
        transpose_h_kernel<<<gW2, blk>>>(w2, wth + OFF_W2, Fd, Cd, Cd, cf, cf);
        dim3 gHd(VPAD / 32, Cd / 32, 1);
        transpose_h_kernel<<<gHd, blk>>>(whead, wth + OFF_HD, Cd, Vv, VPAD, 0, 0);
    }

    dim3 gAttn(Tt / 64, Bq * Hh);

    embed_kernel<<<NT, 256>>>(inputs, tok, pos, x);

    for (int l = 0; l < Ll; l++) {
        const __half* wqkv = wth + OFF_QKV + (size_t)l * Cd * QKVS;
        const __half* wot  = wth + OFF_WO + (size_t)l * Cd * Cd;
        const __half* w1t  = wth + OFF_W1 + (size_t)l * Cd * Fd;
        const __half* w2t  = wth + OFF_W2 + (size_t)l * Fd * Cd;

        ln_kernel<<<NT / 8, 256>>>(x, ln1g + l * Cd, ln1b + l * Cd, h);
        mma_gemm<false, false, false, false, true><<<GEMM_GRID, 256, GEMM_SMEM>>>(
            h, wqkv, nullptr, nullptr, qkv, NT, QKVS, Cd, QKVS / 128);
        attn_tc_kernel<<<gAttn, 128, ATTN_SMEM>>>(qkv, ob);
        mma_gemm<true, false, true, false, false><<<GEMM_GRID, 256, GEMM_SMEM>>>(
            ob, wot, bo + l * Cd, x, x, NT, Cd, Cd, Cd / 128);
        ln_kernel<<<NT / 8, 256>>>(x, ln2g + l * Cd, ln2b + l * Cd, h);
        mma_gemm<true, true, false, false, true><<<GEMM_GRID, 256, GEMM_SMEM>>>(
            h, w1t, b1 + (size_t)l * Fd, nullptr, fb, NT, Fd, Cd, Fd / 128);
        mma_gemm<true, false, true, false, false><<<GEMM_GRID, 256, GEMM_SMEM>>>(
            fb, w2t, b2 + l * Cd, x, x, NT, Cd, Fd, Cd / 128);
    }

    ln_kernel<<<NT / 8, 256>>>(x, lnfg, lnfb, h);

    const long long NV = (long long)NT * Vv;
    if ((long long)out_size >= NV) {
        float* logits = (float*)d_out;
        mma_gemm<true, false, false, true, false><<<GEMM_GRID, 256, GEMM_SMEM>>>(
            h, wth + OFF_HD, bhead, nullptr, logits, NT, Vv, Cd, VPAD / 128);
        if ((long long)out_size > NV) {
            rowloss_kernel<<<NT, 256>>>(logits, targets, rl);
            lossreduce_kernel<<<1, 256>>>(rl, (float*)d_out + NV);
        }
    } else {
        h2f_kernel<<<2048, 256>>>(h, x, (size_t)NT * Cd);
        lse_init_kernel<<<(NT + 255) / 256, 256>>>(lm, ls, lt);
        const int CW = 3072;
        float* fbuf = (float*)devptr(g_f);
        for (int col0 = 0; col0 < Vv; col0 += CW) {
            int width = (Vv - col0 < CW) ? (Vv - col0) : CW;
            dim3 gCk(NT / 128, (width + 63) / 64);
            sgemm_kernel<true, false, false><<<gCk, 256>>>(x, whead + col0, bhead + col0,
                                                           nullptr, fbuf, NT, width, Cd, Vv);
            chunkloss_kernel<<<NT, 256>>>(fbuf, width, col0, targets, lm, ls, lt);
        }
        chunkfinal_kernel<<<(NT + 255) / 256, 256>>>(lm, ls, lt, rl);
        lossreduce_kernel<<<1, 256>>>(rl, (float*)d_out);
    }
}

// round 9
// speedup vs baseline: 7.5828x; 1.0579x over previous
#include <cuda_runtime.h>
#include <cuda_fp16.h>
#include <math.h>
#include <stdint.h>

// ---------------- problem constants (GPT-2 small forward) ----------------
#define Bq   8
#define Tt   1024
#define NT   8192          // B*T tokens
#define Cd   768
#define Hh   12
#define HSd  64
#define Fd   3072
#define Ll   12
#define Vv   50257
#define VPAD 50304         // multiple of 128
#define QKVS 2304          // fused qkv width
#define GEMM_GRID 304      // ~2 CTAs/SM on 152 SMs

// ---------------- scratch (device globals: allocation-free) --------------
__device__ float  g_x[(size_t)NT * Cd];        // residual stream (fp32)
__device__ __half g_h[(size_t)NT * Cd];        // LN output (fp16)
__device__ __half g_qkv[(size_t)NT * QKVS];    // fused q|k|v (fp16)
__device__ __half g_ob[(size_t)NT * Cd];       // attention out (fp16)
__device__ __half g_f[(size_t)NT * Fd];        // MLP hidden (fp16)
__device__ float  g_rowloss[NT];
__device__ float  g_lm[NT];
__device__ float  g_ls[NT];
__device__ float  g_lt[NT];

// fp16 weights, pre-transposed to [N][K] (K-contiguous)
#define OFF_QKV ((size_t)0)                        // [L][2304][768]
#define OFF_WO  ((size_t)21233664)                 // [L][768][768]
#define OFF_W1  ((size_t)28311552)                 // [L][3072][768]
#define OFF_W2  ((size_t)56623104)                 // [L][768][3072]
#define OFF_HD  ((size_t)84934656)                 // [VPAD][768]
#define WTH_TOTAL ((size_t)84934656 + (size_t)VPAD * Cd)
__device__ __half g_wth[WTH_TOTAL];

// ---------------- helpers ----------------
__device__ __forceinline__ uint32_t smem_u32(const void* p) {
    uint32_t a;
    asm("{ .reg .u64 t; cvta.to.shared.u64 t, %1; cvt.u32.u64 %0, t; }" : "=r"(a) : "l"(p));
    return a;
}

__device__ __forceinline__ void cp16(uint32_t saddr, const void* gaddr) {
    asm volatile("cp.async.cg.shared.global [%0], [%1], 16;" :: "r"(saddr), "l"(gaddr));
}
#define CP_COMMIT() asm volatile("cp.async.commit_group;" ::: "memory")
#define CP_WAIT1()  asm volatile("cp.async.wait_group 1;" ::: "memory")
#define CP_WAIT0()  asm volatile("cp.async.wait_group 0;" ::: "memory")

__device__ __forceinline__ void mma16(float* c, const uint32_t* a, const uint32_t* b) {
    asm volatile(
        "mma.sync.aligned.m16n8k16.row.col.f32.f16.f16.f32 "
        "{%0,%1,%2,%3}, {%4,%5,%6,%7}, {%8,%9}, {%0,%1,%2,%3};\n"
        : "+f"(c[0]), "+f"(c[1]), "+f"(c[2]), "+f"(c[3])
        : "r"(a[0]), "r"(a[1]), "r"(a[2]), "r"(a[3]), "r"(b[0]), "r"(b[1]));
}

__device__ __forceinline__ void ldsm_x4(uint32_t* r, uint32_t saddr) {
    asm volatile("ldmatrix.sync.aligned.m8n8.x4.shared.b16 {%0,%1,%2,%3}, [%4];"
                 : "=r"(r[0]), "=r"(r[1]), "=r"(r[2]), "=r"(r[3]) : "r"(saddr));
}
__device__ __forceinline__ void ldsm_x2(uint32_t* r, uint32_t saddr) {
    asm volatile("ldmatrix.sync.aligned.m8n8.x2.shared.b16 {%0,%1}, [%2];"
                 : "=r"(r[0]), "=r"(r[1]) : "r"(saddr));
}

// ---------------- block reduce helpers ----------------
__device__ __forceinline__ float blockReduceSum256(float v) {
    __shared__ float sh[8];
    int lane = threadIdx.x & 31, w = threadIdx.x >> 5;
#pragma unroll
    for (int o = 16; o; o >>= 1) v += __shfl_xor_sync(0xffffffffu, v, o);
    if (lane == 0) sh[w] = v;
    __syncthreads();
    float r = (threadIdx.x < 8) ? sh[threadIdx.x] : 0.f;
    if (w == 0) {
#pragma unroll
        for (int o = 4; o; o >>= 1) r += __shfl_xor_sync(0xffffffffu, r, o);
    }
    __syncthreads();
    if (threadIdx.x == 0) sh[0] = r;
    __syncthreads();
    return sh[0];
}

__device__ __forceinline__ float blockReduceMax256(float v) {
    __shared__ float sh[8];
    int lane = threadIdx.x & 31, w = threadIdx.x >> 5;
#pragma unroll
    for (int o = 16; o; o >>= 1) v = fmaxf(v, __shfl_xor_sync(0xffffffffu, v, o));
    if (lane == 0) sh[w] = v;
    __syncthreads();
    float r = (threadIdx.x < 8) ? sh[threadIdx.x] : -1e30f;
    if (w == 0) {
#pragma unroll
        for (int o = 4; o; o >>= 1) r = fmaxf(r, __shfl_xor_sync(0xffffffffu, r, o));
    }
    __syncthreads();
    if (threadIdx.x == 0) sh[0] = r;
    __syncthreads();
    return sh[0];
}

// ---------------- weight prep: transpose f32 [K][N] -> fp16 [Npad][K] -----
__global__ void transpose_h_kernel(const float* __restrict__ src, __half* __restrict__ dst,
                                   int K, int N, int Npad,
                                   size_t sstride, size_t dstride) {
    src += (size_t)blockIdx.z * sstride;
    dst += (size_t)blockIdx.z * dstride;
    __shared__ float t[32][33];
    int kb = blockIdx.y * 32, nb = blockIdx.x * 32;
    int tx = threadIdx.x, ty = threadIdx.y;
    for (int i = ty; i < 32; i += 8) {
        int k = kb + i, n = nb + tx;
        t[i][tx] = (k < K && n < N) ? src[(size_t)k * N + n] : 0.f;
    }
    __syncthreads();
    for (int i = ty; i < 32; i += 8) {
        int n = nb + i, k = kb + tx;
        if (n < Npad && k < K) dst[(size_t)n * K + k] = __float2half_rn(t[tx][i]);
    }
}

// =====================================================================
// fp16 mma.sync GEMM (persistent): C[M,Nn] = A[M,K](fp16) @ Wt[N][K]^T
// BM=128, BN=128, BK=64, 256 threads; cp.async 3-stage; ldmatrix loads.
// LSE: accumulate per-row sum(exp(logit)) into lse[] via atomics.
// =====================================================================
#define ASTH 72
#define HTILE_H (128 * ASTH)            // 9216 halfs
#define HSTG_H  (2 * HTILE_H)           // A + B
#define NSTG 3
#define GEMM_SMEM (NSTG * HSTG_H * 2)   // 110592 bytes

template<bool BIAS, bool RELU, bool RES, bool NBOUND, bool OUTH, bool LSE>
__global__ __launch_bounds__(256, 2) void mma_gemm(
    const __half* __restrict__ A, const __half* __restrict__ Wt,
    const float* __restrict__ bias, const float* __restrict__ res,
    void* __restrict__ Cv, int M, int Nn, int K, int ntn,
    float* __restrict__ lse) {
    extern __shared__ __half smh[];
    const uint32_t su = smem_u32(smh);
    const int tid = threadIdx.x;
    const int warp = tid >> 5, lane = tid & 31;
    const int g = lane >> 2, t4 = lane & 3;
    const int wm = warp >> 2, wn = warp & 3;
    const int warp_m0 = wm * 64, warp_n0 = wn * 32;

    // ldmatrix per-lane element offsets (within a stage)
    const int mA = lane >> 3;
    const int aRow = (mA & 1) * 8 + (lane & 7);
    const int aCol = (mA >> 1) * 8;
    uint32_t offA[4];
#pragma unroll
    for (int mt = 0; mt < 4; mt++)
        offA[mt] = (uint32_t)((warp_m0 + mt * 16 + aRow) * ASTH + aCol);
    const int lb = lane & 15;
    const int bRow = lb & 7;
    const int bCol = (lb >> 3) * 8;
    uint32_t offB[4];
#pragma unroll
    for (int nt = 0; nt < 4; nt++)
        offB[nt] = (uint32_t)(HTILE_H + (warp_n0 + nt * 8 + bRow) * ASTH + bCol);

    const int nk = K >> 6;
    const int ntm = M >> 7;
    const int ntiles = ntm * ntn;

    for (int tile = blockIdx.x; tile < ntiles; tile += gridDim.x) {
        const int m0 = (tile % ntm) * 128;
        const int n0 = (tile / ntm) * 128;
        __syncthreads();   // guard smem reuse across tiles

        float acc[4][4][4];
#pragma unroll
        for (int mt = 0; mt < 4; mt++)
#pragma unroll
            for (int nt = 0; nt < 4; nt++)
#pragma unroll
                for (int j = 0; j < 4; j++) acc[mt][nt][j] = 0.f;

        auto load_stage = [&](int s, int kb) {
            uint32_t sa = su + (uint32_t)s * HSTG_H * 2;
#pragma unroll
            for (int i = 0; i < 4; i++) {
                int ch = tid + i * 256;
                int r = ch >> 3, c = ch & 7;
                cp16(sa + (uint32_t)(r * ASTH + c * 8) * 2,
                     A + (size_t)(m0 + r) * K + kb + c * 8);
            }
            uint32_t sb = sa + HTILE_H * 2;
#pragma unroll
            for (int i = 0; i < 4; i++) {
                int ch = tid + i * 256;
                int r = ch >> 3, c = ch & 7;
                cp16(sb + (uint32_t)(r * ASTH + c * 8) * 2,
                     Wt + (size_t)(n0 + r) * K + kb + c * 8);
            }
            CP_COMMIT();
        };

        load_stage(0, 0);
        load_stage(1, 64);

        int s = 0;
        for (int kc = 0; kc < nk; kc++) {
            if (kc + 1 < nk) CP_WAIT1(); else CP_WAIT0();
            __syncthreads();

            const uint32_t sbase = su + (uint32_t)s * HSTG_H * 2;
#pragma unroll
            for (int ks = 0; ks < 4; ks++) {
                const int kk = ks * 16;
                uint32_t af[4][4], bf[4][2];
#pragma unroll
                for (int mt = 0; mt < 4; mt++)
                    ldsm_x4(af[mt], sbase + (offA[mt] + kk) * 2);
#pragma unroll
                for (int nt = 0; nt < 4; nt++)
                    ldsm_x2(bf[nt], sbase + (offB[nt] + kk) * 2);
#pragma unroll
                for (int mt = 0; mt < 4; mt++)
#pragma unroll
                    for (int nt = 0; nt < 4; nt++)
                        mma16(acc[mt][nt], af[mt], bf[nt]);
            }

            if (kc + 2 < nk) {
                int sw = s + 2; if (sw >= NSTG) sw -= NSTG;
                load_stage(sw, (kc + 2) * 64);
            }
            if (++s == NSTG) s = 0;
        }

        // ---- epilogue ----
        float rowsum[4][2];
        if (LSE) {
#pragma unroll
            for (int mt = 0; mt < 4; mt++) { rowsum[mt][0] = 0.f; rowsum[mt][1] = 0.f; }
        }
#pragma unroll
        for (int mt = 0; mt < 4; mt++) {
            int r0 = m0 + warp_m0 + mt * 16 + g;
#pragma unroll
            for (int nt = 0; nt < 4; nt++) {
                int cn = n0 + warp_n0 + nt * 8 + t4 * 2;
                float* a4 = acc[mt][nt];
                float b0 = 0.f, b1 = 0.f;
                if (BIAS) {
                    if (!NBOUND) { b0 = bias[cn]; b1 = bias[cn + 1]; }
                    else {
                        b0 = (cn < Nn) ? bias[cn] : 0.f;
                        b1 = (cn + 1 < Nn) ? bias[cn + 1] : 0.f;
                    }
                }
#pragma unroll
                for (int half_ = 0; half_ < 2; half_++) {
                    int r = r0 + half_ * 8;
                    float v0 = a4[half_ * 2 + 0] + b0;
                    float v1 = a4[half_ * 2 + 1] + b1;
                    if (RELU) { v0 = fmaxf(v0, 0.f); v1 = fmaxf(v1, 0.f); }
                    size_t off = (size_t)r * Nn + cn;
                    if (!NBOUND) {
                        if (RES) { v0 += res[off]; v1 += res[off + 1]; }
                        if (OUTH) {
                            *(__half2*)((__half*)Cv + off) = __floats2half2_rn(v0, v1);
                        } else {
                            *(float2*)((float*)Cv + off) = make_float2(v0, v1);
                        }
                    } else {
                        float* C = (float*)Cv;
                        if (cn < Nn) {
                            if (RES) v0 += res[off];
                            C[off] = v0;
                            if (LSE) rowsum[mt][half_] += __expf(v0);
                        }
                        if (cn + 1 < Nn) {
                            if (RES) v1 += res[off + 1];
                            C[off + 1] = v1;
                            if (LSE) rowsum[mt][half_] += __expf(v1);
                        }
                    }
                }
            }
        }
        if (LSE) {
#pragma unroll
            for (int mt = 0; mt < 4; mt++) {
#pragma unroll
                for (int half_ = 0; half_ < 2; half_++) {
                    float sc = rowsum[mt][half_];
                    sc += __shfl_xor_sync(0xffffffffu, sc, 1);
                    sc += __shfl_xor_sync(0xffffffffu, sc, 2);
                    if (t4 == 0) {
                        int r = m0 + warp_m0 + mt * 16 + g + half_ * 8;
                        atomicAdd(&lse[r], sc);
                    }
                }
            }
        }
    }
}

// ---------------- embedding ----------------
__global__ void embed_kernel(const int* __restrict__ inp,
                             const float* __restrict__ tok,
                             const float* __restrict__ pos,
                             float* __restrict__ x) {
    int i = blockIdx.x;
    int t = i & (Tt - 1);
    int v = inp[i];
    const float* te = tok + (size_t)v * Cd;
    const float* pe = pos + (size_t)t * Cd;
    float* xo = x + (size_t)i * Cd;
    for (int c = threadIdx.x; c < Cd; c += blockDim.x)
        xo[c] = te[c] + pe[c];
}

// ---------------- layernorm: warp per row, fp16 output ----------------
__global__ __launch_bounds__(256) void ln_kernel(const float* __restrict__ x,
                                                 const float* __restrict__ g,
                                                 const float* __restrict__ b,
                                                 __half* __restrict__ out) {
    const int warp = threadIdx.x >> 5, lane = threadIdx.x & 31;
    const int row = blockIdx.x * 8 + warp;
    const float4* xr = (const float4*)(x + (size_t)row * Cd);
    const float4* gp = (const float4*)g;
    const float4* bp = (const float4*)b;
    __half* orow = out + (size_t)row * Cd;

    float4 v[6];
    float s = 0.f;
#pragma unroll
    for (int i = 0; i < 6; i++) {
        v[i] = xr[lane + i * 32];
        s += v[i].x + v[i].y + v[i].z + v[i].w;
    }
#pragma unroll
    for (int o = 16; o; o >>= 1) s += __shfl_xor_sync(0xffffffffu, s, o);
    float mean = s * (1.0f / Cd);

    float vs = 0.f;
#pragma unroll
    for (int i = 0; i < 6; i++) {
        float dx = v[i].x - mean, dy = v[i].y - mean,
              dz = v[i].z - mean, dw = v[i].w - mean;
        vs += dx * dx + dy * dy + dz * dz + dw * dw;
    }
#pragma unroll
    for (int o = 16; o; o >>= 1) vs += __shfl_xor_sync(0xffffffffu, vs, o);
    float rstd = rsqrtf(vs * (1.0f / Cd) + 1e-5f);

#pragma unroll
    for (int i = 0; i < 6; i++) {
        float4 gg = gp[lane + i * 32];
        float4 bb = bp[lane + i * 32];
        __half2 h01 = __floats2half2_rn((v[i].x - mean) * rstd * gg.x + bb.x,
                                        (v[i].y - mean) * rstd * gg.y + bb.y);
        __half2 h23 = __floats2half2_rn((v[i].z - mean) * rstd * gg.z + bb.z,
                                        (v[i].w - mean) * rstd * gg.w + bb.w);
        uint2 pk = make_uint2(*(uint32_t*)&h01, *(uint32_t*)&h23);
        *(uint2*)(orow + (lane + i * 32) * 4) = pk;
    }
}

// ---------------- fp16 -> fp32 convert (fallback path) ----------------
__global__ void h2f_kernel(const __half* __restrict__ src, float* __restrict__ dst, size_t n) {
    for (size_t i = (size_t)blockIdx.x * blockDim.x + threadIdx.x; i < n;
         i += (size_t)gridDim.x * blockDim.x)
        dst[i] = __half2float(src[i]);
}

// ---------------- SIMT SGEMM (loss-only fallback path) ----------------
template<bool BIAS, bool RELU, bool RES>
__global__ __launch_bounds__(256) void sgemm_kernel(
    const float* __restrict__ A, const float* __restrict__ W,
    const float* __restrict__ bias, const float* __restrict__ res,
    float* __restrict__ Cout, int M, int Nn, int K, int ldw) {
    __shared__ float As[16][132];
    __shared__ float Bs[16][64];
    int tid = threadIdx.x;
    int m0 = blockIdx.x * 128;
    int n0 = blockIdx.y * 64;
    int tx = tid & 15, ty = tid >> 4;
    float acc[8][4];
#pragma unroll
    for (int i = 0; i < 8; i++)
#pragma unroll
        for (int j = 0; j < 4; j++) acc[i][j] = 0.f;
    int am = tid >> 1;
    int ak = (tid & 1) * 8;
    int bk = tid >> 4;
    int bn = (tid & 15) * 4;
    for (int k0 = 0; k0 < K; k0 += 16) {
        const float* Ap = A + (size_t)(m0 + am) * K + k0 + ak;
        float4 a0 = *(const float4*)Ap;
        float4 a1 = *(const float4*)(Ap + 4);
        As[ak + 0][am] = a0.x; As[ak + 1][am] = a0.y;
        As[ak + 2][am] = a0.z; As[ak + 3][am] = a0.w;
        As[ak + 4][am] = a1.x; As[ak + 5][am] = a1.y;
        As[ak + 6][am] = a1.z; As[ak + 7][am] = a1.w;
        int gn = n0 + bn;
        const float* Wp = W + (size_t)(k0 + bk) * ldw + gn;
        float4 bv;
        bv.x = (gn + 0 < Nn) ? Wp[0] : 0.f;
        bv.y = (gn + 1 < Nn) ? Wp[1] : 0.f;
        bv.z = (gn + 2 < Nn) ? Wp[2] : 0.f;
        bv.w = (gn + 3 < Nn) ? Wp[3] : 0.f;
        *(float4*)&Bs[bk][bn] = bv;
        __syncthreads();
#pragma unroll
        for (int kk = 0; kk < 16; kk++) {
            float4 a04 = *(const float4*)&As[kk][ty * 8];
            float4 a14 = *(const float4*)&As[kk][ty * 8 + 4];
            float4 b4  = *(const float4*)&Bs[kk][tx * 4];
            float a[8] = {a04.x, a04.y, a04.z, a04.w, a14.x, a14.y, a14.z, a14.w};
            float bb[4] = {b4.x, b4.y, b4.z, b4.w};
#pragma unroll
            for (int i = 0; i < 8; i++)
#pragma unroll
                for (int j = 0; j < 4; j++)
                    acc[i][j] += a[i] * bb[j];
        }
        __syncthreads();
    }
    int nbase = n0 + tx * 4;
#pragma unroll
    for (int i = 0; i < 8; i++) {
        size_t rowoff = (size_t)(m0 + ty * 8 + i) * Nn;
#pragma unroll
        for (int j = 0; j < 4; j++) {
            int n = nbase + j;
            if (n < Nn) {
                float v = acc[i][j];
                if (BIAS) v += bias[n];
                if (RELU) v = fmaxf(v, 0.f);
                if (RES) v += res[rowoff + n];
                Cout[rowoff + n] = v;
            }
        }
    }
}

// =====================================================================
// fp16 tensor-core flash attention (S exact; P split hi/lo fp16)
// =====================================================================
#define AST2 72
#define ATTN_SMEM (4 * 64 * AST2 * 2)   // 36864 bytes

__global__ __launch_bounds__(128, 4) void attn_tc_kernel(const __half* __restrict__ QKV,
                                                         __half* __restrict__ O) {
    extern __shared__ __half sme[];
    __half* Ks = sme;
    __half* Vs = Ks + 64 * AST2;
    __half* Ph = Vs + 64 * AST2;
    __half* Pl = Ph + 64 * AST2;

    const int qt = gridDim.x - 1 - blockIdx.x;
    const int bh = blockIdx.y;
    const int b = bh / Hh, h = bh % Hh;
    const int tid = threadIdx.x;
    const int warp = tid >> 5, lane = tid & 31;
    const int g = lane >> 2, t4 = lane & 3;
    const int r0l = warp * 16 + g;
    const int r1l = r0l + 8;

#pragma unroll
    for (int i = 0; i < 4; i++) {
        int ch = tid + i * 128;
        int r = ch >> 3, c8 = (ch & 7) * 8;
        float4 v = *(const float4*)(QKV + (size_t)(b * Tt + qt * 64 + r) * QKVS + h * HSd + c8);
        *(float4*)(Ph + r * AST2 + c8) = v;
    }
    __syncthreads();

    uint32_t qf[4][4];
#pragma unroll
    for (int ks = 0; ks < 4; ks++) {
        int kk = ks * 16;
        qf[ks][0] = *(const uint32_t*)(Ph + r0l * AST2 + kk + 2 * t4);
        qf[ks][1] = *(const uint32_t*)(Ph + r1l * AST2 + kk + 2 * t4);
        qf[ks][2] = *(const uint32_t*)(Ph + r0l * AST2 + kk + 2 * t4 + 8);
        qf[ks][3] = *(const uint32_t*)(Ph + r1l * AST2 + kk + 2 * t4 + 8);
    }

    float o[8][4];
#pragma unroll
    for (int nt = 0; nt < 8; nt++)
#pragma unroll
        for (int j = 0; j < 4; j++) o[nt][j] = 0.f;
    float m0 = -1e30f, m1 = -1e30f, l0 = 0.f, l1 = 0.f;

    for (int kt = 0; kt <= qt; kt++) {
        __syncthreads();
#pragma unroll
        for (int i = 0; i < 4; i++) {
            int ch = tid + i * 128;
            int r = ch >> 3, c8 = (ch & 7) * 8;
            size_t go = (size_t)(b * Tt + kt * 64 + r) * QKVS + h * HSd + c8;
            float4 kv = *(const float4*)(QKV + Cd + go);
            *(float4*)(Ks + r * AST2 + c8) = kv;
            float4 vv = *(const float4*)(QKV + 2 * Cd + go);
            const __half* hv = (const __half*)&vv;
            int rs = r ^ c8;
#pragma unroll
            for (int dd = 0; dd < 8; dd++)
                Vs[(c8 + dd) * AST2 + rs] = hv[dd];
        }
        __syncthreads();

        float sacc[8][4];
#pragma unroll
        for (int nt = 0; nt < 8; nt++)
#pragma unroll
            for (int j = 0; j < 4; j++) sacc[nt][j] = 0.f;
#pragma unroll
        for (int ks = 0; ks < 4; ks++) {
            int kk = ks * 16;
#pragma unroll
            for (int nt = 0; nt < 8; nt++) {
                int j = nt * 8 + g;
                uint32_t bf[2];
                bf[0] = *(const uint32_t*)(Ks + j * AST2 + kk + 2 * t4);
                bf[1] = *(const uint32_t*)(Ks + j * AST2 + kk + 2 * t4 + 8);
                mma16(sacc[nt], qf[ks], bf);
            }
        }
#pragma unroll
        for (int nt = 0; nt < 8; nt++)
#pragma unroll
            for (int j = 0; j < 4; j++) sacc[nt][j] *= 0.125f;

        if (kt == qt) {
#pragma unroll
            for (int nt = 0; nt < 8; nt++) {
                int c0 = nt * 8 + 2 * t4;
                if (c0     > r0l) sacc[nt][0] = -1e30f;
                if (c0 + 1 > r0l) sacc[nt][1] = -1e30f;
                if (c0     > r1l) sacc[nt][2] = -1e30f;
                if (c0 + 1 > r1l) sacc[nt][3] = -1e30f;
            }
        }

        float tm0 = -1e30f, tm1 = -1e30f;
#pragma unroll
        for (int nt = 0; nt < 8; nt++) {
            tm0 = fmaxf(tm0, fmaxf(sacc[nt][0], sacc[nt][1]));
            tm1 = fmaxf(tm1, fmaxf(sacc[nt][2], sacc[nt][3]));
        }
        tm0 = fmaxf(tm0, __shfl_xor_sync(0xffffffffu, tm0, 1));
        tm0 = fmaxf(tm0, __shfl_xor_sync(0xffffffffu, tm0, 2));
        tm1 = fmaxf(tm1, __shfl_xor_sync(0xffffffffu, tm1, 1));
        tm1 = fmaxf(tm1, __shfl_xor_sync(0xffffffffu, tm1, 2));
        float mN0 = fmaxf(m0, tm0), mN1 = fmaxf(m1, tm1);
        float a0 = __expf(m0 - mN0), a1 = __expf(m1 - mN1);
        m0 = mN0; m1 = mN1;

        float sum0 = 0.f, sum1 = 0.f;
#pragma unroll
        for (int nt = 0; nt < 8; nt++) {
            float p0 = __expf(sacc[nt][0] - mN0);
            float p1 = __expf(sacc[nt][1] - mN0);
            float p2 = __expf(sacc[nt][2] - mN1);
            float p3 = __expf(sacc[nt][3] - mN1);
            sum0 += p0 + p1;
            sum1 += p2 + p3;
            int c0 = nt * 8 + 2 * t4;
            __half2 h01 = __floats2half2_rn(p0, p1);
            __half2 h23 = __floats2half2_rn(p2, p3);
            *(__half2*)(Ph + r0l * AST2 + c0) = h01;
            *(__half2*)(Ph + r1l * AST2 + c0) = h23;
            *(__half2*)(Pl + r0l * AST2 + c0) =
                __floats2half2_rn(p0 - __half2float(__low2half(h01)),
                                  p1 - __half2float(__high2half(h01)));
            *(__half2*)(Pl + r1l * AST2 + c0) =
                __floats2half2_rn(p2 - __half2float(__low2half(h23)),
                                  p3 - __half2float(__high2half(h23)));
        }
        sum0 += __shfl_xor_sync(0xffffffffu, sum0, 1);
        sum0 += __shfl_xor_sync(0xffffffffu, sum0, 2);
        sum1 += __shfl_xor_sync(0xffffffffu, sum1, 1);
        sum1 += __shfl_xor_sync(0xffffffffu, sum1, 2);
        l0 = l0 * a0 + sum0;
        l1 = l1 * a1 + sum1;
#pragma unroll
        for (int nt = 0; nt < 8; nt++) {
            o[nt][0] *= a0; o[nt][1] *= a0;
            o[nt][2] *= a1; o[nt][3] *= a1;
        }
        __syncwarp();

#pragma unroll
        for (int ks = 0; ks < 4; ks++) {
            int kk = ks * 16;
            uint32_t ah[4], al[4];
            ah[0] = *(const uint32_t*)(Ph + r0l * AST2 + kk + 2 * t4);
            ah[1] = *(const uint32_t*)(Ph + r1l * AST2 + kk + 2 * t4);
            ah[2] = *(const uint32_t*)(Ph + r0l * AST2 + kk + 2 * t4 + 8);
            ah[3] = *(const uint32_t*)(Ph + r1l * AST2 + kk + 2 * t4 + 8);
            al[0] = *(const uint32_t*)(Pl + r0l * AST2 + kk + 2 * t4);
            al[1] = *(const uint32_t*)(Pl + r1l * AST2 + kk + 2 * t4);
            al[2] = *(const uint32_t*)(Pl + r0l * AST2 + kk + 2 * t4 + 8);
            al[3] = *(const uint32_t*)(Pl + r1l * AST2 + kk + 2 * t4 + 8);
#pragma unroll
            for (int nt = 0; nt < 8; nt++) {
                int d = nt * 8 + g;
                int swz = nt * 8;
                uint32_t bf[2];
                bf[0] = *(const uint32_t*)(Vs + d * AST2 + ((kk + 2 * t4) ^ swz));
                bf[1] = *(const uint32_t*)(Vs + d * AST2 + ((kk + 2 * t4 + 8) ^ swz));
                mma16(o[nt], ah, bf);
                mma16(o[nt], al, bf);
            }
        }
    }

    float i0 = 1.f / l0, i1 = 1.f / l1;
    size_t row0 = (size_t)(b * Tt + qt * 64 + r0l) * Cd + h * HSd;
    size_t row1 = (size_t)(b * Tt + qt * 64 + r1l) * Cd + h * HSd;
#pragma unroll
    for (int nt = 0; nt < 8; nt++) {
        int c0 = nt * 8 + 2 * t4;
        *(__half2*)(O + row0 + c0) = __floats2half2_rn(o[nt][0] * i0, o[nt][1] * i0);
        *(__half2*)(O + row1 + c0) = __floats2half2_rn(o[nt][2] * i1, o[nt][3] * i1);
    }
}

// ---------------- loss kernels ----------------
__global__ void zero_kernel(float* p, int n) {
    int i = blockIdx.x * blockDim.x + threadIdx.x;
    if (i < n) p[i] = 0.f;
}

// fused final loss: mean over rows of log(sumexp) - logit[target]
__global__ __launch_bounds__(256) void lossfinal_kernel(const float* __restrict__ ls,
                                                        const float* __restrict__ logits,
                                                        const int* __restrict__ tgt,
                                                        float* __restrict__ out) {
    float s = 0.f;
    for (int r = threadIdx.x; r < NT; r += 256)
        s += logf(ls[r]) - logits[(size_t)r * Vv + tgt[r]];
    s = blockReduceSum256(s);
    if (threadIdx.x == 0) out[0] = s * (1.0f / NT);
}

__global__ __launch_bounds__(256) void lossreduce_kernel(const float* __restrict__ rl,
                                                         float* __restrict__ out) {
    float s = 0.f;
    for (int i = threadIdx.x; i < NT; i += 256) s += rl[i];
    s = blockReduceSum256(s);
    if (threadIdx.x == 0) out[0] = s * (1.0f / NT);
}

__global__ void lse_init_kernel(float* lm, float* ls, float* lt) {
    int i = blockIdx.x * blockDim.x + threadIdx.x;
    if (i < NT) { lm[i] = -1e30f; ls[i] = 0.f; lt[i] = 0.f; }
}

__global__ __launch_bounds__(256) void chunkloss_kernel(const float* __restrict__ chunk,
                                                        int width, int col0,
                                                        const int* __restrict__ tgt,
                                                        float* __restrict__ lm,
                                                        float* __restrict__ ls,
                                                        float* __restrict__ lt) {
    int r = blockIdx.x;
    const float* cr = chunk + (size_t)r * width;
    float m = -1e30f;
    for (int c = threadIdx.x; c < width; c += 256) m = fmaxf(m, cr[c]);
    m = blockReduceMax256(m);
    float s = 0.f;
    for (int c = threadIdx.x; c < width; c += 256) s += __expf(cr[c] - m);
    s = blockReduceSum256(s);
    if (threadIdx.x == 0) {
        float mOld = lm[r];
        float mNew = fmaxf(mOld, m);
        ls[r] = ls[r] * __expf(mOld - mNew) + s * __expf(m - mNew);
        lm[r] = mNew;
        int tg = tgt[r] - col0;
        if (tg >= 0 && tg < width) lt[r] = cr[tg];
    }
}

__global__ void chunkfinal_kernel(const float* lm, const float* ls, const float* lt,
                                  float* rl) {
    int i = blockIdx.x * blockDim.x + threadIdx.x;
    if (i < NT) rl[i] = lm[i] + logf(ls[i]) - lt[i];
}

// ---------------- host driver ----------------
static void* devptr(const void* sym) {
    void* p = nullptr;
    cudaGetSymbolAddress(&p, sym);
    return p;
}

extern "C" void kernel_launch(void* const* d_in, const int* in_sizes, int n_in,
                              void* d_out, int out_size) {
    const int* inputs    = (const int*)d_in[0];
    const int* targets   = (const int*)d_in[1];
    const float* tok     = (const float*)d_in[2];
    const float* pos     = (const float*)d_in[3];
    const float* ln1g    = (const float*)d_in[4];
    const float* ln1b    = (const float*)d_in[5];
    const float* ln2g    = (const float*)d_in[6];
    const float* ln2b    = (const float*)d_in[7];
    const float* wq      = (const float*)d_in[8];
    const float* wk      = (const float*)d_in[9];
    const float* wv      = (const float*)d_in[10];
    const float* wo      = (const float*)d_in[11];
    const float* bo      = (const float*)d_in[12];
    const float* w1      = (const float*)d_in[13];
    const float* b1      = (const float*)d_in[14];
    const float* w2      = (const float*)d_in[15];
    const float* b2      = (const float*)d_in[16];
    const float* lnfg    = (const float*)d_in[17];
    const float* lnfb    = (const float*)d_in[18];
    const float* whead   = (const float*)d_in[19];
    const float* bhead   = (const float*)d_in[20];

    float*  x   = (float*)devptr(g_x);
    __half* h   = (__half*)devptr(g_h);
    __half* qkv = (__half*)devptr(g_qkv);
    __half* ob  = (__half*)devptr(g_ob);
    __half* fb  = (__half*)devptr(g_f);
    float*  rl  = (float*)devptr(g_rowloss);
    float*  lm  = (float*)devptr(g_lm);
    float*  ls  = (float*)devptr(g_ls);
    float*  lt  = (float*)devptr(g_lt);
    __half* wth = (__half*)devptr(g_wth);

    cudaFuncSetAttribute(mma_gemm<false, false, false, false, true, false>, cudaFuncAttributeMaxDynamicSharedMemorySize, GEMM_SMEM);
    cudaFuncSetAttribute(mma_gemm<true, false, true, false, false, false>,  cudaFuncAttributeMaxDynamicSharedMemorySize, GEMM_SMEM);
    cudaFuncSetAttribute(mma_gemm<true, true, false, false, true, false>,   cudaFuncAttributeMaxDynamicSharedMemorySize, GEMM_SMEM);
    cudaFuncSetAttribute(mma_gemm<true, false, false, true, false, true>,   cudaFuncAttributeMaxDynamicSharedMemorySize, GEMM_SMEM);
    cudaFuncSetAttribute(mma_gemm<true, false, false, true, false, false>,  cudaFuncAttributeMaxDynamicSharedMemorySize, GEMM_SMEM);
    cudaFuncSetAttribute(attn_tc_kernel, cudaFuncAttributeMaxDynamicSharedMemorySize, ATTN_SMEM);

    // ---- weight prep: fp16 convert + transpose to [N][K], once per launch ----
    {
        dim3 blk(32, 8);
        size_t cc = (size_t)Cd * Cd, cf = (size_t)Cd * Fd;
        dim3 gCC(Cd / 32, Cd / 32, Ll);
        transpose_h_kernel<<<gCC, blk>>>(wq, wth + OFF_QKV + (size_t)0 * cc, Cd, Cd, Cd, cc, (size_t)QKVS * Cd);
        transpose_h_kernel<<<gCC, blk>>>(wk, wth + OFF_QKV + (size_t)1 * cc, Cd, Cd, Cd, cc, (size_t)QKVS * Cd);
        transpose_h_kernel<<<gCC, blk>>>(wv, wth + OFF_QKV + (size_t)2 * cc, Cd, Cd, Cd, cc, (size_t)QKVS * Cd);
        transpose_h_kernel<<<gCC, blk>>>(wo, wth + OFF_WO, Cd, Cd, Cd, cc, cc);
        dim3 gW1(Fd / 32, Cd / 32, Ll);
        transpose_h_kernel<<<gW1, blk>>>(w1, wth + OFF_W1, Cd, Fd, Fd, cf, cf);
        dim3 gW2(Cd / 32, Fd / 32, Ll);
        transpose_h_kernel<<<gW2, blk>>>(w2, wth + OFF_W2, Fd, Cd, Cd, cf, cf);
        dim3 gHd(VPAD / 32, Cd / 32, 1);
        transpose_h_kernel<<<gHd, blk>>>(whead, wth + OFF_HD, Cd, Vv, VPAD, 0, 0);
    }

    dim3 gAttn(Tt / 64, Bq * Hh);

    embed_kernel<<<NT, 256>>>(inputs, tok, pos, x);

    for (int l = 0; l < Ll; l++) {
        const __half* wqkv = wth + OFF_QKV + (size_t)l * Cd * QKVS;
        const __half* wot  = wth + OFF_WO + (size_t)l * Cd * Cd;
        const __half* w1t  = wth + OFF_W1 + (size_t)l * Cd * Fd;
        const __half* w2t  = wth + OFF_W2 + (size_t)l * Fd * Cd;

        ln_kernel<<<NT / 8, 256>>>(x, ln1g + l * Cd, ln1b + l * Cd, h);
        mma_gemm<false, false, false, false, true, false><<<GEMM_GRID, 256, GEMM_SMEM>>>(
            h, wqkv, nullptr, nullptr, qkv, NT, QKVS, Cd, QKVS / 128, nullptr);
        attn_tc_kernel<<<gAttn, 128, ATTN_SMEM>>>(qkv, ob);
        mma_gemm<true, false, true, false, false, false><<<GEMM_GRID, 256, GEMM_SMEM>>>(
            ob, wot, bo + l * Cd, x, x, NT, Cd, Cd, Cd / 128, nullptr);
        ln_kernel<<<NT / 8, 256>>>(x, ln2g + l * Cd, ln2b + l * Cd, h);
        mma_gemm<true, true, false, false, true, false><<<GEMM_GRID, 256, GEMM_SMEM>>>(
            h, w1t, b1 + (size_t)l * Fd, nullptr, fb, NT, Fd, Cd, Fd / 128, nullptr);
        mma_gemm<true, false, true, false, false, false><<<GEMM_GRID, 256, GEMM_SMEM>>>(
            fb, w2t, b2 + l * Cd, x, x, NT, Cd, Fd, Cd / 128, nullptr);
    }

    ln_kernel<<<NT / 8, 256>>>(x, lnfg, lnfb, h);

    const long long NV = (long long)NT * Vv;
    if ((long long)out_size >= NV) {
        float* logits = (float*)d_out;
        bool wantLoss = ((long long)out_size > NV);
        if (wantLoss) {
            zero_kernel<<<(NT + 255) / 256, 256>>>(ls, NT);
            mma_gemm<true, false, false, true, false, true><<<GEMM_GRID, 256, GEMM_SMEM>>>(
                h, wth + OFF_HD, bhead, nullptr, logits, NT, Vv, Cd, VPAD / 128, ls);
            lossfinal_kernel<<<1, 256>>>(ls, logits, targets, (float*)d_out + NV);
        } else {
            mma_gemm<true, false, false, true, false, false><<<GEMM_GRID, 256, GEMM_SMEM>>>(
                h, wth + OFF_HD, bhead, nullptr, logits, NT, Vv, Cd, VPAD / 128, nullptr);
        }
    } else {
        h2f_kernel<<<2048, 256>>>(h, x, (size_t)NT * Cd);
        lse_init_kernel<<<(NT + 255) / 256, 256>>>(lm, ls, lt);
        const int CW = 3072;
        float* fbuf = (float*)devptr(g_f);
        for (int col0 = 0; col0 < Vv; col0 += CW) {
            int width = (Vv - col0 < CW) ? (Vv - col0) : CW;
            dim3 gCk(NT / 128, (width + 63) / 64);
            sgemm_kernel<true, false, false><<<gCk, 256>>>(x, whead + col0, bhead + col0,
                                                           nullptr, fbuf, NT, width, Cd, Vv);
            chunkloss_kernel<<<NT, 256>>>(fbuf, width, col0, targets, lm, ls, lt);
        }
        chunkfinal_kernel<<<(NT + 255) / 256, 256>>>(lm, ls, lt, rl);
        lossreduce_kernel<<<1, 256>>>(rl, (float*)d_out);
    }
}

// round 10
// speedup vs baseline: 7.8274x; 1.0323x over previous
#include <cuda_runtime.h>
#include <cuda_fp16.h>
#include <math.h>
#include <stdint.h>

// ---------------- problem constants (GPT-2 small forward) ----------------
#define Bq   8
#define Tt   1024
#define NT   8192          // B*T tokens
#define Cd   768
#define Hh   12
#define HSd  64
#define Fd   3072
#define Ll   12
#define Vv   50257
#define VPAD 50304         // multiple of 128
#define QKVS 2304          // fused qkv width
#define GEMM_GRID 304      // ~2 CTAs/SM on 152 SMs

// ---------------- scratch (device globals: allocation-free) --------------
__device__ float  g_x[(size_t)NT * Cd];        // residual stream (fp32)
__device__ __half g_h[(size_t)NT * Cd];        // LN output (fp16)
__device__ __half g_qkv[(size_t)NT * QKVS];    // fused q|k|v (fp16)
__device__ __half g_ob[(size_t)NT * Cd];       // attention out (fp16)
__device__ __half g_f[(size_t)NT * Fd];        // MLP hidden (fp16)
__device__ float  g_rowloss[NT];
__device__ float  g_lm[NT];
__device__ float  g_ls[NT];
__device__ float  g_lt[NT];

// fp16 weights, pre-transposed to [N][K] (K-contiguous)
#define OFF_QKV ((size_t)0)                        // [L][2304][768]
#define OFF_WO  ((size_t)21233664)                 // [L][768][768]
#define OFF_W1  ((size_t)28311552)                 // [L][3072][768]
#define OFF_W2  ((size_t)56623104)                 // [L][768][3072]
#define OFF_HD  ((size_t)84934656)                 // [VPAD][768]
#define WTH_TOTAL ((size_t)84934656 + (size_t)VPAD * Cd)
__device__ __half g_wth[WTH_TOTAL];

// ---------------- helpers ----------------
__device__ __forceinline__ uint32_t smem_u32(const void* p) {
    uint32_t a;
    asm("{ .reg .u64 t; cvta.to.shared.u64 t, %1; cvt.u32.u64 %0, t; }" : "=r"(a) : "l"(p));
    return a;
}

__device__ __forceinline__ void cp16(uint32_t saddr, const void* gaddr) {
    asm volatile("cp.async.cg.shared.global [%0], [%1], 16;" :: "r"(saddr), "l"(gaddr));
}
#define CP_COMMIT() asm volatile("cp.async.commit_group;" ::: "memory")
#define CP_WAIT1()  asm volatile("cp.async.wait_group 1;" ::: "memory")
#define CP_WAIT0()  asm volatile("cp.async.wait_group 0;" ::: "memory")

__device__ __forceinline__ void mma16(float* c, const uint32_t* a, const uint32_t* b) {
    asm volatile(
        "mma.sync.aligned.m16n8k16.row.col.f32.f16.f16.f32 "
        "{%0,%1,%2,%3}, {%4,%5,%6,%7}, {%8,%9}, {%0,%1,%2,%3};\n"
        : "+f"(c[0]), "+f"(c[1]), "+f"(c[2]), "+f"(c[3])
        : "r"(a[0]), "r"(a[1]), "r"(a[2]), "r"(a[3]), "r"(b[0]), "r"(b[1]));
}

__device__ __forceinline__ void ldsm_x4(uint32_t* r, uint32_t saddr) {
    asm volatile("ldmatrix.sync.aligned.m8n8.x4.shared.b16 {%0,%1,%2,%3}, [%4];"
                 : "=r"(r[0]), "=r"(r[1]), "=r"(r[2]), "=r"(r[3]) : "r"(saddr));
}
__device__ __forceinline__ void ldsm_x2_trans(uint32_t* r, uint32_t saddr) {
    asm volatile("ldmatrix.sync.aligned.m8n8.x2.trans.shared.b16 {%0,%1}, [%2];"
                 : "=r"(r[0]), "=r"(r[1]) : "r"(saddr));
}

// ---------------- block reduce helpers ----------------
__device__ __forceinline__ float blockReduceSum256(float v) {
    __shared__ float sh[8];
    int lane = threadIdx.x & 31, w = threadIdx.x >> 5;
#pragma unroll
    for (int o = 16; o; o >>= 1) v += __shfl_xor_sync(0xffffffffu, v, o);
    if (lane == 0) sh[w] = v;
    __syncthreads();
    float r = (threadIdx.x < 8) ? sh[threadIdx.x] : 0.f;
    if (w == 0) {
#pragma unroll
        for (int o = 4; o; o >>= 1) r += __shfl_xor_sync(0xffffffffu, r, o);
    }
    __syncthreads();
    if (threadIdx.x == 0) sh[0] = r;
    __syncthreads();
    return sh[0];
}

__device__ __forceinline__ float blockReduceMax256(float v) {
    __shared__ float sh[8];
    int lane = threadIdx.x & 31, w = threadIdx.x >> 5;
#pragma unroll
    for (int o = 16; o; o >>= 1) v = fmaxf(v, __shfl_xor_sync(0xffffffffu, v, o));
    if (lane == 0) sh[w] = v;
    __syncthreads();
    float r = (threadIdx.x < 8) ? sh[threadIdx.x] : -1e30f;
    if (w == 0) {
#pragma unroll
        for (int o = 4; o; o >>= 1) r = fmaxf(r, __shfl_xor_sync(0xffffffffu, r, o));
    }
    __syncthreads();
    if (threadIdx.x == 0) sh[0] = r;
    __syncthreads();
    return sh[0];
}

// ---------------- weight prep: transpose f32 [K][N] -> fp16 [Npad][K] -----
__global__ void transpose_h_kernel(const float* __restrict__ src, __half* __restrict__ dst,
                                   int K, int N, int Npad,
                                   size_t sstride, size_t dstride) {
    src += (size_t)blockIdx.z * sstride;
    dst += (size_t)blockIdx.z * dstride;
    __shared__ float t[32][33];
    int kb = blockIdx.y * 32, nb = blockIdx.x * 32;
    int tx = threadIdx.x, ty = threadIdx.y;
    for (int i = ty; i < 32; i += 8) {
        int k = kb + i, n = nb + tx;
        t[i][tx] = (k < K && n < N) ? src[(size_t)k * N + n] : 0.f;
    }
    __syncthreads();
    for (int i = ty; i < 32; i += 8) {
        int n = nb + i, k = kb + tx;
        if (n < Npad && k < K) dst[(size_t)n * K + k] = __float2half_rn(t[tx][i]);
    }
}

// =====================================================================
// fp16 mma.sync GEMM (persistent): C[M,Nn] = A[M,K](fp16) @ Wt[N][K]^T
// BM=128, BN=128, BK=64, 256 threads; cp.async 3-stage; ldmatrix x4 loads.
// LSE: accumulate per-row sum(exp(logit)) into lse[] via atomics.
// =====================================================================
#define ASTH 72
#define HTILE_H (128 * ASTH)            // 9216 halfs
#define HSTG_H  (2 * HTILE_H)           // A + B
#define NSTG 3
#define GEMM_SMEM (NSTG * HSTG_H * 2)   // 110592 bytes

template<bool BIAS, bool RELU, bool RES, bool NBOUND, bool OUTH, bool LSE>
__global__ __launch_bounds__(256, 2) void mma_gemm(
    const __half* __restrict__ A, const __half* __restrict__ Wt,
    const float* __restrict__ bias, const float* __restrict__ res,
    void* __restrict__ Cv, int M, int Nn, int K, int ntn,
    float* __restrict__ lse) {
    extern __shared__ __half smh[];
    const uint32_t su = smem_u32(smh);
    const int tid = threadIdx.x;
    const int warp = tid >> 5, lane = tid & 31;
    const int g = lane >> 2, t4 = lane & 3;
    const int wm = warp >> 2, wn = warp & 3;
    const int warp_m0 = wm * 64, warp_n0 = wn * 32;

    // ldmatrix per-lane element offsets (within a stage)
    const int mA = lane >> 3;
    const int aRow = (mA & 1) * 8 + (lane & 7);
    const int aCol = (mA >> 1) * 8;
    uint32_t offA[4];
#pragma unroll
    for (int mt = 0; mt < 4; mt++)
        offA[mt] = (uint32_t)((warp_m0 + mt * 16 + aRow) * ASTH + aCol);
    // B via x4: tIdx 0..3 -> (row-group, k-half): rows (tIdx>>1)*8, col (tIdx&1)*8
    const int tIdx = lane >> 3;
    const int bRowAdd = (tIdx >> 1) * 8 + (lane & 7);
    const int bColAdd = (tIdx & 1) * 8;
    uint32_t offB2[2];
#pragma unroll
    for (int nt2 = 0; nt2 < 2; nt2++)
        offB2[nt2] = (uint32_t)(HTILE_H + (warp_n0 + nt2 * 16 + bRowAdd) * ASTH + bColAdd);

    const int nk = K >> 6;
    const int ntm = M >> 7;
    const int ntiles = ntm * ntn;

    for (int tile = blockIdx.x; tile < ntiles; tile += gridDim.x) {
        const int m0 = (tile % ntm) * 128;
        const int n0 = (tile / ntm) * 128;
        __syncthreads();   // guard smem reuse across tiles

        float acc[4][4][4];
#pragma unroll
        for (int mt = 0; mt < 4; mt++)
#pragma unroll
            for (int nt = 0; nt < 4; nt++)
#pragma unroll
                for (int j = 0; j < 4; j++) acc[mt][nt][j] = 0.f;

        auto load_stage = [&](int s, int kb) {
            uint32_t sa = su + (uint32_t)s * HSTG_H * 2;
#pragma unroll
            for (int i = 0; i < 4; i++) {
                int ch = tid + i * 256;
                int r = ch >> 3, c = ch & 7;
                cp16(sa + (uint32_t)(r * ASTH + c * 8) * 2,
                     A + (size_t)(m0 + r) * K + kb + c * 8);
            }
            uint32_t sb = sa + HTILE_H * 2;
#pragma unroll
            for (int i = 0; i < 4; i++) {
                int ch = tid + i * 256;
                int r = ch >> 3, c = ch & 7;
                cp16(sb + (uint32_t)(r * ASTH + c * 8) * 2,
                     Wt + (size_t)(n0 + r) * K + kb + c * 8);
            }
            CP_COMMIT();
        };

        load_stage(0, 0);
        load_stage(1, 64);

        int s = 0;
        for (int kc = 0; kc < nk; kc++) {
            if (kc + 1 < nk) CP_WAIT1(); else CP_WAIT0();
            __syncthreads();

            const uint32_t sbase = su + (uint32_t)s * HSTG_H * 2;
#pragma unroll
            for (int ks = 0; ks < 4; ks++) {
                const int kk = ks * 16;
                uint32_t af[4][4], bf[4][2];
#pragma unroll
                for (int mt = 0; mt < 4; mt++)
                    ldsm_x4(af[mt], sbase + (offA[mt] + kk) * 2);
#pragma unroll
                for (int nt2 = 0; nt2 < 2; nt2++) {
                    uint32_t bt[4];
                    ldsm_x4(bt, sbase + (offB2[nt2] + kk) * 2);
                    bf[nt2 * 2 + 0][0] = bt[0]; bf[nt2 * 2 + 0][1] = bt[1];
                    bf[nt2 * 2 + 1][0] = bt[2]; bf[nt2 * 2 + 1][1] = bt[3];
                }
#pragma unroll
                for (int mt = 0; mt < 4; mt++)
#pragma unroll
                    for (int nt = 0; nt < 4; nt++)
                        mma16(acc[mt][nt], af[mt], bf[nt]);
            }

            if (kc + 2 < nk) {
                int sw = s + 2; if (sw >= NSTG) sw -= NSTG;
                load_stage(sw, (kc + 2) * 64);
            }
            if (++s == NSTG) s = 0;
        }

        // ---- epilogue ----
        float rowsum[4][2];
        if (LSE) {
#pragma unroll
            for (int mt = 0; mt < 4; mt++) { rowsum[mt][0] = 0.f; rowsum[mt][1] = 0.f; }
        }
#pragma unroll
        for (int mt = 0; mt < 4; mt++) {
            int r0 = m0 + warp_m0 + mt * 16 + g;
#pragma unroll
            for (int nt = 0; nt < 4; nt++) {
                int cn = n0 + warp_n0 + nt * 8 + t4 * 2;
                float* a4 = acc[mt][nt];
                float b0 = 0.f, b1 = 0.f;
                if (BIAS) {
                    if (!NBOUND) { b0 = bias[cn]; b1 = bias[cn + 1]; }
                    else {
                        b0 = (cn < Nn) ? bias[cn] : 0.f;
                        b1 = (cn + 1 < Nn) ? bias[cn + 1] : 0.f;
                    }
                }
#pragma unroll
                for (int half_ = 0; half_ < 2; half_++) {
                    int r = r0 + half_ * 8;
                    float v0 = a4[half_ * 2 + 0] + b0;
                    float v1 = a4[half_ * 2 + 1] + b1;
                    if (RELU) { v0 = fmaxf(v0, 0.f); v1 = fmaxf(v1, 0.f); }
                    size_t off = (size_t)r * Nn + cn;
                    if (!NBOUND) {
                        if (RES) { v0 += res[off]; v1 += res[off + 1]; }
                        if (OUTH) {
                            *(__half2*)((__half*)Cv + off) = __floats2half2_rn(v0, v1);
                        } else {
                            *(float2*)((float*)Cv + off) = make_float2(v0, v1);
                        }
                    } else {
                        float* C = (float*)Cv;
                        if (cn < Nn) {
                            if (RES) v0 += res[off];
                            C[off] = v0;
                            if (LSE) rowsum[mt][half_] += __expf(v0);
                        }
                        if (cn + 1 < Nn) {
                            if (RES) v1 += res[off + 1];
                            C[off + 1] = v1;
                            if (LSE) rowsum[mt][half_] += __expf(v1);
                        }
                    }
                }
            }
        }
        if (LSE) {
#pragma unroll
            for (int mt = 0; mt < 4; mt++) {
#pragma unroll
                for (int half_ = 0; half_ < 2; half_++) {
                    float sc = rowsum[mt][half_];
                    sc += __shfl_xor_sync(0xffffffffu, sc, 1);
                    sc += __shfl_xor_sync(0xffffffffu, sc, 2);
                    if (t4 == 0) {
                        int r = m0 + warp_m0 + mt * 16 + g + half_ * 8;
                        atomicAdd(&lse[r], sc);
                    }
                }
            }
        }
    }
}

// ---------------- embedding ----------------
__global__ void embed_kernel(const int* __restrict__ inp,
                             const float* __restrict__ tok,
                             const float* __restrict__ pos,
                             float* __restrict__ x) {
    int i = blockIdx.x;
    int t = i & (Tt - 1);
    int v = inp[i];
    const float* te = tok + (size_t)v * Cd;
    const float* pe = pos + (size_t)t * Cd;
    float* xo = x + (size_t)i * Cd;
    for (int c = threadIdx.x; c < Cd; c += blockDim.x)
        xo[c] = te[c] + pe[c];
}

// ---------------- layernorm: warp per row, fp16 output ----------------
__global__ __launch_bounds__(256) void ln_kernel(const float* __restrict__ x,
                                                 const float* __restrict__ g,
                                                 const float* __restrict__ b,
                                                 __half* __restrict__ out) {
    const int warp = threadIdx.x >> 5, lane = threadIdx.x & 31;
    const int row = blockIdx.x * 8 + warp;
    const float4* xr = (const float4*)(x + (size_t)row * Cd);
    const float4* gp = (const float4*)g;
    const float4* bp = (const float4*)b;
    __half* orow = out + (size_t)row * Cd;

    float4 v[6];
    float s = 0.f;
#pragma unroll
    for (int i = 0; i < 6; i++) {
        v[i] = xr[lane + i * 32];
        s += v[i].x + v[i].y + v[i].z + v[i].w;
    }
#pragma unroll
    for (int o = 16; o; o >>= 1) s += __shfl_xor_sync(0xffffffffu, s, o);
    float mean = s * (1.0f / Cd);

    float vs = 0.f;
#pragma unroll
    for (int i = 0; i < 6; i++) {
        float dx = v[i].x - mean, dy = v[i].y - mean,
              dz = v[i].z - mean, dw = v[i].w - mean;
        vs += dx * dx + dy * dy + dz * dz + dw * dw;
    }
#pragma unroll
    for (int o = 16; o; o >>= 1) vs += __shfl_xor_sync(0xffffffffu, vs, o);
    float rstd = rsqrtf(vs * (1.0f / Cd) + 1e-5f);

#pragma unroll
    for (int i = 0; i < 6; i++) {
        float4 gg = gp[lane + i * 32];
        float4 bb = bp[lane + i * 32];
        __half2 h01 = __floats2half2_rn((v[i].x - mean) * rstd * gg.x + bb.x,
                                        (v[i].y - mean) * rstd * gg.y + bb.y);
        __half2 h23 = __floats2half2_rn((v[i].z - mean) * rstd * gg.z + bb.z,
                                        (v[i].w - mean) * rstd * gg.w + bb.w);
        uint2 pk = make_uint2(*(uint32_t*)&h01, *(uint32_t*)&h23);
        *(uint2*)(orow + (lane + i * 32) * 4) = pk;
    }
}

// ---------------- fp16 -> fp32 convert (fallback path) ----------------
__global__ void h2f_kernel(const __half* __restrict__ src, float* __restrict__ dst, size_t n) {
    for (size_t i = (size_t)blockIdx.x * blockDim.x + threadIdx.x; i < n;
         i += (size_t)gridDim.x * blockDim.x)
        dst[i] = __half2float(src[i]);
}

// ---------------- SIMT SGEMM (loss-only fallback path) ----------------
template<bool BIAS, bool RELU, bool RES>
__global__ __launch_bounds__(256) void sgemm_kernel(
    const float* __restrict__ A, const float* __restrict__ W,
    const float* __restrict__ bias, const float* __restrict__ res,
    float* __restrict__ Cout, int M, int Nn, int K, int ldw) {
    __shared__ float As[16][132];
    __shared__ float Bs[16][64];
    int tid = threadIdx.x;
    int m0 = blockIdx.x * 128;
    int n0 = blockIdx.y * 64;
    int tx = tid & 15, ty = tid >> 4;
    float acc[8][4];
#pragma unroll
    for (int i = 0; i < 8; i++)
#pragma unroll
        for (int j = 0; j < 4; j++) acc[i][j] = 0.f;
    int am = tid >> 1;
    int ak = (tid & 1) * 8;
    int bk = tid >> 4;
    int bn = (tid & 15) * 4;
    for (int k0 = 0; k0 < K; k0 += 16) {
        const float* Ap = A + (size_t)(m0 + am) * K + k0 + ak;
        float4 a0 = *(const float4*)Ap;
        float4 a1 = *(const float4*)(Ap + 4);
        As[ak + 0][am] = a0.x; As[ak + 1][am] = a0.y;
        As[ak + 2][am] = a0.z; As[ak + 3][am] = a0.w;
        As[ak + 4][am] = a1.x; As[ak + 5][am] = a1.y;
        As[ak + 6][am] = a1.z; As[ak + 7][am] = a1.w;
        int gn = n0 + bn;
        const float* Wp = W + (size_t)(k0 + bk) * ldw + gn;
        float4 bv;
        bv.x = (gn + 0 < Nn) ? Wp[0] : 0.f;
        bv.y = (gn + 1 < Nn) ? Wp[1] : 0.f;
        bv.z = (gn + 2 < Nn) ? Wp[2] : 0.f;
        bv.w = (gn + 3 < Nn) ? Wp[3] : 0.f;
        *(float4*)&Bs[bk][bn] = bv;
        __syncthreads();
#pragma unroll
        for (int kk = 0; kk < 16; kk++) {
            float4 a04 = *(const float4*)&As[kk][ty * 8];
            float4 a14 = *(const float4*)&As[kk][ty * 8 + 4];
            float4 b4  = *(const float4*)&Bs[kk][tx * 4];
            float a[8] = {a04.x, a04.y, a04.z, a04.w, a14.x, a14.y, a14.z, a14.w};
            float bb[4] = {b4.x, b4.y, b4.z, b4.w};
#pragma unroll
            for (int i = 0; i < 8; i++)
#pragma unroll
                for (int j = 0; j < 4; j++)
                    acc[i][j] += a[i] * bb[j];
        }
        __syncthreads();
    }
    int nbase = n0 + tx * 4;
#pragma unroll
    for (int i = 0; i < 8; i++) {
        size_t rowoff = (size_t)(m0 + ty * 8 + i) * Nn;
#pragma unroll
        for (int j = 0; j < 4; j++) {
            int n = nbase + j;
            if (n < Nn) {
                float v = acc[i][j];
                if (BIAS) v += bias[n];
                if (RELU) v = fmaxf(v, 0.f);
                if (RES) v += res[rowoff + n];
                Cout[rowoff + n] = v;
            }
        }
    }
}

// =====================================================================
// fp16 tensor-core flash attention (S exact; P split hi/lo fp16)
// cp.async double-buffered K/V tiles (row-major [j][d]); V via ldmatrix.trans
// smem: K[2], V[2], Ph, Pl each [64][72] halfs = 55296 B
// =====================================================================
#define AST2 72
#define ATILE (64 * AST2)
#define ATTN_SMEM (6 * ATILE * 2)   // 55296 bytes

__global__ __launch_bounds__(128, 4) void attn_tc_kernel(const __half* __restrict__ QKV,
                                                         __half* __restrict__ O) {
    extern __shared__ __half sme[];
    __half* Ks0 = sme;                 // stage 0: K
    __half* Vs0 = Ks0 + ATILE;         // stage 0: V
    __half* Ks1 = Vs0 + ATILE;         // stage 1: K
    __half* Vs1 = Ks1 + ATILE;         // stage 1: V
    __half* Ph  = Vs1 + ATILE;
    __half* Pl  = Ph + ATILE;
    const uint32_t suK[2] = { smem_u32(Ks0), smem_u32(Ks1) };

    const int qt = gridDim.x - 1 - blockIdx.x;
    const int bh = blockIdx.y;
    const int b = bh / Hh, h = bh % Hh;
    const int tid = threadIdx.x;
    const int warp = tid >> 5, lane = tid & 31;
    const int g = lane >> 2, t4 = lane & 3;
    const int r0l = warp * 16 + g;
    const int r1l = r0l + 8;

    // async K+V tile loader (row-major [j][d], 16B chunks)
    auto load_kv = [&](int stage, int kt) {
        uint32_t sk = suK[stage];
        const __half* base = QKV + (size_t)(b * Tt + kt * 64) * QKVS + h * HSd;
#pragma unroll
        for (int i = 0; i < 4; i++) {
            int ch = tid + i * 128;
            int r = ch >> 3, c8 = (ch & 7) * 8;
            const __half* grow = base + (size_t)r * QKVS + c8;
            cp16(sk + (uint32_t)(r * AST2 + c8) * 2, grow + Cd);             // K
            cp16(sk + (uint32_t)(ATILE + r * AST2 + c8) * 2, grow + 2 * Cd); // V
        }
        CP_COMMIT();
    };

    // prologue: issue loads for kt=0 (and kt=1), stage Q meanwhile
    load_kv(0, 0);
    if (qt >= 1) load_kv(1, 1);

#pragma unroll
    for (int i = 0; i < 4; i++) {
        int ch = tid + i * 128;
        int r = ch >> 3, c8 = (ch & 7) * 8;
        float4 v = *(const float4*)(QKV + (size_t)(b * Tt + qt * 64 + r) * QKVS + h * HSd + c8);
        *(float4*)(Ph + r * AST2 + c8) = v;
    }
    __syncthreads();

    uint32_t qf[4][4];
#pragma unroll
    for (int ks = 0; ks < 4; ks++) {
        int kk = ks * 16;
        qf[ks][0] = *(const uint32_t*)(Ph + r0l * AST2 + kk + 2 * t4);
        qf[ks][1] = *(const uint32_t*)(Ph + r1l * AST2 + kk + 2 * t4);
        qf[ks][2] = *(const uint32_t*)(Ph + r0l * AST2 + kk + 2 * t4 + 8);
        qf[ks][3] = *(const uint32_t*)(Ph + r1l * AST2 + kk + 2 * t4 + 8);
    }

    // ldmatrix.trans per-lane V offset: lanes 0-15 address rows kk + (lane&7) + ((lane>>3)&1)*8
    const int vRow = (lane & 7) + ((lane >> 3) & 1) * 8;

    float o[8][4];
#pragma unroll
    for (int nt = 0; nt < 8; nt++)
#pragma unroll
        for (int j = 0; j < 4; j++) o[nt][j] = 0.f;
    float m0 = -1e30f, m1 = -1e30f, l0 = 0.f, l1 = 0.f;

    for (int kt = 0; kt <= qt; kt++) {
        const int st = kt & 1;
        if (kt < qt) CP_WAIT1(); else CP_WAIT0();
        __syncthreads();   // tile kt visible; all warps past reads of this stage

        const __half* Ks = (st == 0) ? Ks0 : Ks1;
        const uint32_t vbase = suK[st] + ATILE * 2;

        // ---- S = Q K^T (exact fp16 mma), then scale in fp32 ----
        float sacc[8][4];
#pragma unroll
        for (int nt = 0; nt < 8; nt++)
#pragma unroll
            for (int j = 0; j < 4; j++) sacc[nt][j] = 0.f;
#pragma unroll
        for (int ks = 0; ks < 4; ks++) {
            int kk = ks * 16;
#pragma unroll
            for (int nt = 0; nt < 8; nt++) {
                int j = nt * 8 + g;
                uint32_t bf[2];
                bf[0] = *(const uint32_t*)(Ks + j * AST2 + kk + 2 * t4);
                bf[1] = *(const uint32_t*)(Ks + j * AST2 + kk + 2 * t4 + 8);
                mma16(sacc[nt], qf[ks], bf);
            }
        }
#pragma unroll
        for (int nt = 0; nt < 8; nt++)
#pragma unroll
            for (int j = 0; j < 4; j++) sacc[nt][j] *= 0.125f;

        // ---- causal mask on diagonal tile ----
        if (kt == qt) {
#pragma unroll
            for (int nt = 0; nt < 8; nt++) {
                int c0 = nt * 8 + 2 * t4;
                if (c0     > r0l) sacc[nt][0] = -1e30f;
                if (c0 + 1 > r0l) sacc[nt][1] = -1e30f;
                if (c0     > r1l) sacc[nt][2] = -1e30f;
                if (c0 + 1 > r1l) sacc[nt][3] = -1e30f;
            }
        }

        // ---- online softmax ----
        float tm0 = -1e30f, tm1 = -1e30f;
#pragma unroll
        for (int nt = 0; nt < 8; nt++) {
            tm0 = fmaxf(tm0, fmaxf(sacc[nt][0], sacc[nt][1]));
            tm1 = fmaxf(tm1, fmaxf(sacc[nt][2], sacc[nt][3]));
        }
        tm0 = fmaxf(tm0, __shfl_xor_sync(0xffffffffu, tm0, 1));
        tm0 = fmaxf(tm0, __shfl_xor_sync(0xffffffffu, tm0, 2));
        tm1 = fmaxf(tm1, __shfl_xor_sync(0xffffffffu, tm1, 1));
        tm1 = fmaxf(tm1, __shfl_xor_sync(0xffffffffu, tm1, 2));
        float mN0 = fmaxf(m0, tm0), mN1 = fmaxf(m1, tm1);
        float a0 = __expf(m0 - mN0), a1 = __expf(m1 - mN1);
        m0 = mN0; m1 = mN1;

        float sum0 = 0.f, sum1 = 0.f;
#pragma unroll
        for (int nt = 0; nt < 8; nt++) {
            float p0 = __expf(sacc[nt][0] - mN0);
            float p1 = __expf(sacc[nt][1] - mN0);
            float p2 = __expf(sacc[nt][2] - mN1);
            float p3 = __expf(sacc[nt][3] - mN1);
            sum0 += p0 + p1;
            sum1 += p2 + p3;
            int c0 = nt * 8 + 2 * t4;
            __half2 h01 = __floats2half2_rn(p0, p1);
            __half2 h23 = __floats2half2_rn(p2, p3);
            *(__half2*)(Ph + r0l * AST2 + c0) = h01;
            *(__half2*)(Ph + r1l * AST2 + c0) = h23;
            *(__half2*)(Pl + r0l * AST2 + c0) =
                __floats2half2_rn(p0 - __half2float(__low2half(h01)),
                                  p1 - __half2float(__high2half(h01)));
            *(__half2*)(Pl + r1l * AST2 + c0) =
                __floats2half2_rn(p2 - __half2float(__low2half(h23)),
                                  p3 - __half2float(__high2half(h23)));
        }
        sum0 += __shfl_xor_sync(0xffffffffu, sum0, 1);
        sum0 += __shfl_xor_sync(0xffffffffu, sum0, 2);
        sum1 += __shfl_xor_sync(0xffffffffu, sum1, 1);
        sum1 += __shfl_xor_sync(0xffffffffu, sum1, 2);
        l0 = l0 * a0 + sum0;
        l1 = l1 * a1 + sum1;
#pragma unroll
        for (int nt = 0; nt < 8; nt++) {
            o[nt][0] *= a0; o[nt][1] *= a0;
            o[nt][2] *= a1; o[nt][3] *= a1;
        }
        __syncwarp();

        // ---- O += P V (P hi+lo; V via ldmatrix.trans from [j][d]) ----
#pragma unroll
        for (int ks = 0; ks < 4; ks++) {
            int kk = ks * 16;
            uint32_t ah[4], al[4];
            ah[0] = *(const uint32_t*)(Ph + r0l * AST2 + kk + 2 * t4);
            ah[1] = *(const uint32_t*)(Ph + r1l * AST2 + kk + 2 * t4);
            ah[2] = *(const uint32_t*)(Ph + r0l * AST2 + kk + 2 * t4 + 8);
            ah[3] = *(const uint32_t*)(Ph + r1l * AST2 + kk + 2 * t4 + 8);
            al[0] = *(const uint32_t*)(Pl + r0l * AST2 + kk + 2 * t4);
            al[1] = *(const uint32_t*)(Pl + r1l * AST2 + kk + 2 * t4);
            al[2] = *(const uint32_t*)(Pl + r0l * AST2 + kk + 2 * t4 + 8);
            al[3] = *(const uint32_t*)(Pl + r1l * AST2 + kk + 2 * t4 + 8);
            uint32_t vaddr = vbase + (uint32_t)((kk + vRow) * AST2) * 2;
#pragma unroll
            for (int nt = 0; nt < 8; nt++) {
                uint32_t bf[2];
                ldsm_x2_trans(bf, vaddr + (uint32_t)(nt * 8) * 2);
                mma16(o[nt], ah, bf);
                mma16(o[nt], al, bf);
            }
        }

        // prefetch tile kt+2 into this stage (all reads of stage done this iter;
        // next iter's top barrier orders these writes vs other warps)
        __syncthreads();
        if (kt + 2 <= qt) load_kv(st, kt + 2);
    }

    // ---- epilogue: normalize, store fp16 ----
    float i0 = 1.f / l0, i1 = 1.f / l1;
    size_t row0 = (size_t)(b * Tt + qt * 64 + r0l) * Cd + h * HSd;
    size_t row1 = (size_t)(b * Tt + qt * 64 + r1l) * Cd + h * HSd;
#pragma unroll
    for (int nt = 0; nt < 8; nt++) {
        int c0 = nt * 8 + 2 * t4;
        *(__half2*)(O + row0 + c0) = __floats2half2_rn(o[nt][0] * i0, o[nt][1] * i0);
        *(__half2*)(O + row1 + c0) = __floats2half2_rn(o[nt][2] * i1, o[nt][3] * i1);
    }
}

// ---------------- loss kernels ----------------
__global__ void zero_kernel(float* p, int n) {
    int i = blockIdx.x * blockDim.x + threadIdx.x;
    if (i < n) p[i] = 0.f;
}

__global__ __launch_bounds__(256) void lossfinal_kernel(const float* __restrict__ ls,
                                                        const float* __restrict__ logits,
                                                        const int* __restrict__ tgt,
                                                        float* __restrict__ out) {
    float s = 0.f;
    for (int r = threadIdx.x; r < NT; r += 256)
        s += logf(ls[r]) - logits[(size_t)r * Vv + tgt[r]];
    s = blockReduceSum256(s);
    if (threadIdx.x == 0) out[0] = s * (1.0f / NT);
}

__global__ __launch_bounds__(256) void lossreduce_kernel(const float* __restrict__ rl,
                                                         float* __restrict__ out) {
    float s = 0.f;
    for (int i = threadIdx.x; i < NT; i += 256) s += rl[i];
    s = blockReduceSum256(s);
    if (threadIdx.x == 0) out[0] = s * (1.0f / NT);
}

__global__ void lse_init_kernel(float* lm, float* ls, float* lt) {
    int i = blockIdx.x * blockDim.x + threadIdx.x;
    if (i < NT) { lm[i] = -1e30f; ls[i] = 0.f; lt[i] = 0.f; }
}

__global__ __launch_bounds__(256) void chunkloss_kernel(const float* __restrict__ chunk,
                                                        int width, int col0,
                                                        const int* __restrict__ tgt,
                                                        float* __restrict__ lm,
                                                        float* __restrict__ ls,
                                                        float* __restrict__ lt) {
    int r = blockIdx.x;
    const float* cr = chunk + (size_t)r * width;
    float m = -1e30f;
    for (int c = threadIdx.x; c < width; c += 256) m = fmaxf(m, cr[c]);
    m = blockReduceMax256(m);
    float s = 0.f;
    for (int c = threadIdx.x; c < width; c += 256) s += __expf(cr[c] - m);
    s = blockReduceSum256(s);
    if (threadIdx.x == 0) {
        float mOld = lm[r];
        float mNew = fmaxf(mOld, m);
        ls[r] = ls[r] * __expf(mOld - mNew) + s * __expf(m - mNew);
        lm[r] = mNew;
        int tg = tgt[r] - col0;
        if (tg >= 0 && tg < width) lt[r] = cr[tg];
    }
}

__global__ void chunkfinal_kernel(const float* lm, const float* ls, const float* lt,
                                  float* rl) {
    int i = blockIdx.x * blockDim.x + threadIdx.x;
    if (i < NT) rl[i] = lm[i] + logf(ls[i]) - lt[i];
}

// ---------------- host driver ----------------
static void* devptr(const void* sym) {
    void* p = nullptr;
    cudaGetSymbolAddress(&p, sym);
    return p;
}

extern "C" void kernel_launch(void* const* d_in, const int* in_sizes, int n_in,
                              void* d_out, int out_size) {
    const int* inputs    = (const int*)d_in[0];
    const int* targets   = (const int*)d_in[1];
    const float* tok     = (const float*)d_in[2];
    const float* pos     = (const float*)d_in[3];
    const float* ln1g    = (const float*)d_in[4];
    const float* ln1b    = (const float*)d_in[5];
    const float* ln2g    = (const float*)d_in[6];
    const float* ln2b    = (const float*)d_in[7];
    const float* wq      = (const float*)d_in[8];
    const float* wk      = (const float*)d_in[9];
    const float* wv      = (const float*)d_in[10];
    const float* wo      = (const float*)d_in[11];
    const float* bo      = (const float*)d_in[12];
    const float* w1      = (const float*)d_in[13];
    const float* b1      = (const float*)d_in[14];
    const float* w2      = (const float*)d_in[15];
    const float* b2      = (const float*)d_in[16];
    const float* lnfg    = (const float*)d_in[17];
    const float* lnfb    = (const float*)d_in[18];
    const float* whead   = (const float*)d_in[19];
    const float* bhead   = (const float*)d_in[20];

    float*  x   = (float*)devptr(g_x);
    __half* h   = (__half*)devptr(g_h);
    __half* qkv = (__half*)devptr(g_qkv);
    __half* ob  = (__half*)devptr(g_ob);
    __half* fb  = (__half*)devptr(g_f);
    float*  rl  = (float*)devptr(g_rowloss);
    float*  lm  = (float*)devptr(g_lm);
    float*  ls  = (float*)devptr(g_ls);
    float*  lt  = (float*)devptr(g_lt);
    __half* wth = (__half*)devptr(g_wth);

    cudaFuncSetAttribute(mma_gemm<false, false, false, false, true, false>, cudaFuncAttributeMaxDynamicSharedMemorySize, GEMM_SMEM);
    cudaFuncSetAttribute(mma_gemm<true, false, true, false, false, false>,  cudaFuncAttributeMaxDynamicSharedMemorySize, GEMM_SMEM);
    cudaFuncSetAttribute(mma_gemm<true, true, false, false, true, false>,   cudaFuncAttributeMaxDynamicSharedMemorySize, GEMM_SMEM);
    cudaFuncSetAttribute(mma_gemm<true, false, false, true, false, true>,   cudaFuncAttributeMaxDynamicSharedMemorySize, GEMM_SMEM);
    cudaFuncSetAttribute(mma_gemm<true, false, false, true, false, false>,  cudaFuncAttributeMaxDynamicSharedMemorySize, GEMM_SMEM);
    cudaFuncSetAttribute(attn_tc_kernel, cudaFuncAttributeMaxDynamicSharedMemorySize, ATTN_SMEM);

    // ---- weight prep: fp16 convert + transpose to [N][K], once per launch ----
    {
        dim3 blk(32, 8);
        size_t cc = (size_t)Cd * Cd, cf = (size_t)Cd * Fd;
        dim3 gCC(Cd / 32, Cd / 32, Ll);
        transpose_h_kernel<<<gCC, blk>>>(wq, wth + OFF_QKV + (size_t)0 * cc, Cd, Cd, Cd, cc, (size_t)QKVS * Cd);
        transpose_h_kernel<<<gCC, blk>>>(wk, wth + OFF_QKV + (size_t)1 * cc, Cd, Cd, Cd, cc, (size_t)QKVS * Cd);
        transpose_h_kernel<<<gCC, blk>>>(wv, wth + OFF_QKV + (size_t)2 * cc, Cd, Cd, Cd, cc, (size_t)QKVS * Cd);
        transpose_h_kernel<<<gCC, blk>>>(wo, wth + OFF_WO, Cd, Cd, Cd, cc, cc);
        dim3 gW1(Fd / 32, Cd / 32, Ll);
        transpose_h_kernel<<<gW1, blk>>>(w1, wth + OFF_W1, Cd, Fd, Fd, cf, cf);
        dim3 gW2(Cd / 32, Fd / 32, Ll);
        transpose_h_kernel<<<gW2, blk>>>(w2, wth + OFF_W2, Fd, Cd, Cd, cf, cf);
        dim3 gHd(VPAD / 32, Cd / 32, 1);
        transpose_h_kernel<<<gHd, blk>>>(whead, wth + OFF_HD, Cd, Vv, VPAD, 0, 0);
    }

    dim3 gAttn(Tt / 64, Bq * Hh);

    embed_kernel<<<NT, 256>>>(inputs, tok, pos, x);

    for (int l = 0; l < Ll; l++) {
        const __half* wqkv = wth + OFF_QKV + (size_t)l * Cd * QKVS;
        const __half* wot  = wth + OFF_WO + (size_t)l * Cd * Cd;
        const __half* w1t  = wth + OFF_W1 + (size_t)l * Cd * Fd;
        const __half* w2t  = wth + OFF_W2 + (size_t)l * Fd * Cd;

        ln_kernel<<<NT / 8, 256>>>(x, ln1g + l * Cd, ln1b + l * Cd, h);
        mma_gemm<false, false, false, false, true, false><<<GEMM_GRID, 256, GEMM_SMEM>>>(
            h, wqkv, nullptr, nullptr, qkv, NT, QKVS, Cd, QKVS / 128, nullptr);
        attn_tc_kernel<<<gAttn, 128, ATTN_SMEM>>>(qkv, ob);
        mma_gemm<true, false, true, false, false, false><<<GEMM_GRID, 256, GEMM_SMEM>>>(
            ob, wot, bo + l * Cd, x, x, NT, Cd, Cd, Cd / 128, nullptr);
        ln_kernel<<<NT / 8, 256>>>(x, ln2g + l * Cd, ln2b + l * Cd, h);
        mma_gemm<true, true, false, false, true, false><<<GEMM_GRID, 256, GEMM_SMEM>>>(
            h, w1t, b1 + (size_t)l * Fd, nullptr, fb, NT, Fd, Cd, Fd / 128, nullptr);
        mma_gemm<true, false, true, false, false, false><<<GEMM_GRID, 256, GEMM_SMEM>>>(
            fb, w2t, b2 + l * Cd, x, x, NT, Cd, Fd, Cd / 128, nullptr);
    }

    ln_kernel<<<NT / 8, 256>>>(x, lnfg, lnfb, h);

    const long long NV = (long long)NT * Vv;
    if ((long long)out_size >= NV) {
        float* logits = (float*)d_out;
        bool wantLoss = ((long long)out_size > NV);
        if (wantLoss) {
            zero_kernel<<<(NT + 255) / 256, 256>>>(ls, NT);
            mma_gemm<true, false, false, true, false, true><<<GEMM_GRID, 256, GEMM_SMEM>>>(
                h, wth + OFF_HD, bhead, nullptr, logits, NT, Vv, Cd, VPAD / 128, ls);
            lossfinal_kernel<<<1, 256>>>(ls, logits, targets, (float*)d_out + NV);
        } else {
            mma_gemm<true, false, false, true, false, false><<<GEMM_GRID, 256, GEMM_SMEM>>>(
                h, wth + OFF_HD, bhead, nullptr, logits, NT, Vv, Cd, VPAD / 128, nullptr);
        }
    } else {
        h2f_kernel<<<2048, 256>>>(h, x, (size_t)NT * Cd);
        lse_init_kernel<<<(NT + 255) / 256, 256>>>(lm, ls, lt);
        const int CW = 3072;
        float* fbuf = (float*)devptr(g_f);
        for (int col0 = 0; col0 < Vv; col0 += CW) {
            int width = (Vv - col0 < CW) ? (Vv - col0) : CW;
            dim3 gCk(NT / 128, (width + 63) / 64);
            sgemm_kernel<true, false, false><<<gCk, 256>>>(x, whead + col0, bhead + col0,
                                                           nullptr, fbuf, NT, width, Cd, Vv);
            chunkloss_kernel<<<NT, 256>>>(fbuf, width, col0, targets, lm, ls, lt);
        }
        chunkfinal_kernel<<<(NT + 255) / 256, 256>>>(lm, ls, lt, rl);
        lossreduce_kernel<<<1, 256>>>(rl, (float*)d_out);
    }
}

// round 11
// speedup vs baseline: 7.9860x; 1.0203x over previous
#include <cuda_runtime.h>
#include <cuda_fp16.h>
#include <math.h>
#include <stdint.h>

// ---------------- problem constants (GPT-2 small forward) ----------------
#define Bq   8
#define Tt   1024
#define NT   8192          // B*T tokens
#define Cd   768
#define Hh   12
#define HSd  64
#define Fd   3072
#define Ll   12
#define Vv   50257
#define VPAD 50304         // multiple of 128
#define QKVS 2304          // fused qkv width
#define GEMM_GRID 304      // ~2 CTAs/SM on 152 SMs

// ---------------- scratch (device globals: allocation-free) --------------
__device__ float  g_x[(size_t)NT * Cd];        // residual stream (fp32)
__device__ __half g_h[(size_t)NT * Cd];        // LN output (fp16)
__device__ __half g_qkv[(size_t)NT * QKVS];    // fused q|k|v (fp16)
__device__ __half g_ob[(size_t)NT * Cd];       // attention out (fp16)
__device__ __half g_f[(size_t)NT * Fd];        // MLP hidden (fp16)
__device__ float  g_rowloss[NT];
__device__ float  g_lm[NT];
__device__ float  g_ls[NT];
__device__ float  g_lt[NT];

// fp16 weights, pre-transposed to [N][K] (K-contiguous)
#define OFF_QKV ((size_t)0)                        // [L][2304][768]
#define OFF_WO  ((size_t)21233664)                 // [L][768][768]
#define OFF_W1  ((size_t)28311552)                 // [L][3072][768]
#define OFF_W2  ((size_t)56623104)                 // [L][768][3072]
#define OFF_HD  ((size_t)84934656)                 // [VPAD][768]
#define WTH_TOTAL ((size_t)84934656 + (size_t)VPAD * Cd)
__device__ __half g_wth[WTH_TOTAL];

// ---------------- helpers ----------------
__device__ __forceinline__ uint32_t smem_u32(const void* p) {
    uint32_t a;
    asm("{ .reg .u64 t; cvta.to.shared.u64 t, %1; cvt.u32.u64 %0, t; }" : "=r"(a) : "l"(p));
    return a;
}

__device__ __forceinline__ void cp16(uint32_t saddr, const void* gaddr) {
    asm volatile("cp.async.cg.shared.global [%0], [%1], 16;" :: "r"(saddr), "l"(gaddr));
}
#define CP_COMMIT() asm volatile("cp.async.commit_group;" ::: "memory")
#define CP_WAIT1()  asm volatile("cp.async.wait_group 1;" ::: "memory")
#define CP_WAIT0()  asm volatile("cp.async.wait_group 0;" ::: "memory")

__device__ __forceinline__ void mma16(float* c, const uint32_t* a, const uint32_t* b) {
    asm volatile(
        "mma.sync.aligned.m16n8k16.row.col.f32.f16.f16.f32 "
        "{%0,%1,%2,%3}, {%4,%5,%6,%7}, {%8,%9}, {%0,%1,%2,%3};\n"
        : "+f"(c[0]), "+f"(c[1]), "+f"(c[2]), "+f"(c[3])
        : "r"(a[0]), "r"(a[1]), "r"(a[2]), "r"(a[3]), "r"(b[0]), "r"(b[1]));
}

__device__ __forceinline__ void ldsm_x4(uint32_t* r, uint32_t saddr) {
    asm volatile("ldmatrix.sync.aligned.m8n8.x4.shared.b16 {%0,%1,%2,%3}, [%4];"
                 : "=r"(r[0]), "=r"(r[1]), "=r"(r[2]), "=r"(r[3]) : "r"(saddr));
}
__device__ __forceinline__ void ldsm_x2_trans(uint32_t* r, uint32_t saddr) {
    asm volatile("ldmatrix.sync.aligned.m8n8.x2.trans.shared.b16 {%0,%1}, [%2];"
                 : "=r"(r[0]), "=r"(r[1]) : "r"(saddr));
}

// ---------------- block reduce helpers ----------------
__device__ __forceinline__ float blockReduceSum256(float v) {
    __shared__ float sh[8];
    int lane = threadIdx.x & 31, w = threadIdx.x >> 5;
#pragma unroll
    for (int o = 16; o; o >>= 1) v += __shfl_xor_sync(0xffffffffu, v, o);
    if (lane == 0) sh[w] = v;
    __syncthreads();
    float r = (threadIdx.x < 8) ? sh[threadIdx.x] : 0.f;
    if (w == 0) {
#pragma unroll
        for (int o = 4; o; o >>= 1) r += __shfl_xor_sync(0xffffffffu, r, o);
    }
    __syncthreads();
    if (threadIdx.x == 0) sh[0] = r;
    __syncthreads();
    return sh[0];
}

__device__ __forceinline__ float blockReduceMax256(float v) {
    __shared__ float sh[8];
    int lane = threadIdx.x & 31, w = threadIdx.x >> 5;
#pragma unroll
    for (int o = 16; o; o >>= 1) v = fmaxf(v, __shfl_xor_sync(0xffffffffu, v, o));
    if (lane == 0) sh[w] = v;
    __syncthreads();
    float r = (threadIdx.x < 8) ? sh[threadIdx.x] : -1e30f;
    if (w == 0) {
#pragma unroll
        for (int o = 4; o; o >>= 1) r = fmaxf(r, __shfl_xor_sync(0xffffffffu, r, o));
    }
    __syncthreads();
    if (threadIdx.x == 0) sh[0] = r;
    __syncthreads();
    return sh[0];
}

// ---------------- weight prep: transpose f32 [K][N] -> fp16 [Npad][K] -----
// 64(k) x 32(n) tiles; writes half2 pairs => 128B per warp store.
__global__ __launch_bounds__(256) void transpose_h_kernel(
    const float* __restrict__ src, __half* __restrict__ dst,
    int K, int N, int Npad, size_t sstride, size_t dstride) {
    src += (size_t)blockIdx.z * sstride;
    dst += (size_t)blockIdx.z * dstride;
    __shared__ float t[64][33];
    const int kb = blockIdx.y * 64, nb = blockIdx.x * 32;
    const int warp = threadIdx.x >> 5, lane = threadIdx.x & 31;
#pragma unroll
    for (int j = 0; j < 8; j++) {
        int r = warp * 8 + j;            // k-row within tile
        int k = kb + r, n = nb + lane;
        t[r][lane] = (k < K && n < N) ? src[(size_t)k * N + n] : 0.f;
    }
    __syncthreads();
#pragma unroll
    for (int j = 0; j < 4; j++) {
        int nl = warp * 4 + j;           // n within tile
        int n = nb + nl;
        int k = kb + lane * 2;           // K is a multiple of 64 -> k+1 < K when k < K
        if (n < Npad && k < K) {
            __half2 v = __floats2half2_rn(t[lane * 2][nl], t[lane * 2 + 1][nl]);
            *(__half2*)(dst + (size_t)n * K + k) = v;
        }
    }
}

// =====================================================================
// fp16 mma.sync GEMM (persistent): C[M,Nn] = A[M,K](fp16) @ Wt[N][K]^T
// BM=128, BN=128, BK=64, 256 threads; cp.async 3-stage; ldmatrix x4 loads.
// LSE: accumulate per-row sum(exp(logit)) into lse[] via atomics.
// =====================================================================
#define ASTH 72
#define HTILE_H (128 * ASTH)            // 9216 halfs
#define HSTG_H  (2 * HTILE_H)           // A + B
#define NSTG 3
#define GEMM_SMEM (NSTG * HSTG_H * 2)   // 110592 bytes

template<bool BIAS, bool RELU, bool RES, bool NBOUND, bool OUTH, bool LSE>
__global__ __launch_bounds__(256, 2) void mma_gemm(
    const __half* __restrict__ A, const __half* __restrict__ Wt,
    const float* __restrict__ bias, const float* __restrict__ res,
    void* __restrict__ Cv, int M, int Nn, int K, int ntn,
    float* __restrict__ lse) {
    extern __shared__ __half smh[];
    const uint32_t su = smem_u32(smh);
    const int tid = threadIdx.x;
    const int warp = tid >> 5, lane = tid & 31;
    const int g = lane >> 2, t4 = lane & 3;
    const int wm = warp >> 2, wn = warp & 3;
    const int warp_m0 = wm * 64, warp_n0 = wn * 32;

    const int mA = lane >> 3;
    const int aRow = (mA & 1) * 8 + (lane & 7);
    const int aCol = (mA >> 1) * 8;
    uint32_t offA[4];
#pragma unroll
    for (int mt = 0; mt < 4; mt++)
        offA[mt] = (uint32_t)((warp_m0 + mt * 16 + aRow) * ASTH + aCol);
    const int tIdx = lane >> 3;
    const int bRowAdd = (tIdx >> 1) * 8 + (lane & 7);
    const int bColAdd = (tIdx & 1) * 8;
    uint32_t offB2[2];
#pragma unroll
    for (int nt2 = 0; nt2 < 2; nt2++)
        offB2[nt2] = (uint32_t)(HTILE_H + (warp_n0 + nt2 * 16 + bRowAdd) * ASTH + bColAdd);

    const int nk = K >> 6;
    const int ntm = M >> 7;
    const int ntiles = ntm * ntn;

    for (int tile = blockIdx.x; tile < ntiles; tile += gridDim.x) {
        const int m0 = (tile % ntm) * 128;
        const int n0 = (tile / ntm) * 128;
        __syncthreads();   // guard smem reuse across tiles

        float acc[4][4][4];
#pragma unroll
        for (int mt = 0; mt < 4; mt++)
#pragma unroll
            for (int nt = 0; nt < 4; nt++)
#pragma unroll
                for (int j = 0; j < 4; j++) acc[mt][nt][j] = 0.f;

        auto load_stage = [&](int s, int kb) {
            uint32_t sa = su + (uint32_t)s * HSTG_H * 2;
#pragma unroll
            for (int i = 0; i < 4; i++) {
                int ch = tid + i * 256;
                int r = ch >> 3, c = ch & 7;
                cp16(sa + (uint32_t)(r * ASTH + c * 8) * 2,
                     A + (size_t)(m0 + r) * K + kb + c * 8);
            }
            uint32_t sb = sa + HTILE_H * 2;
#pragma unroll
            for (int i = 0; i < 4; i++) {
                int ch = tid + i * 256;
                int r = ch >> 3, c = ch & 7;
                cp16(sb + (uint32_t)(r * ASTH + c * 8) * 2,
                     Wt + (size_t)(n0 + r) * K + kb + c * 8);
            }
            CP_COMMIT();
        };

        load_stage(0, 0);
        load_stage(1, 64);

        int s = 0;
        for (int kc = 0; kc < nk; kc++) {
            if (kc + 1 < nk) CP_WAIT1(); else CP_WAIT0();
            __syncthreads();

            const uint32_t sbase = su + (uint32_t)s * HSTG_H * 2;
#pragma unroll
            for (int ks = 0; ks < 4; ks++) {
                const int kk = ks * 16;
                uint32_t af[4][4], bf[4][2];
#pragma unroll
                for (int mt = 0; mt < 4; mt++)
                    ldsm_x4(af[mt], sbase + (offA[mt] + kk) * 2);
#pragma unroll
                for (int nt2 = 0; nt2 < 2; nt2++) {
                    uint32_t bt[4];
                    ldsm_x4(bt, sbase + (offB2[nt2] + kk) * 2);
                    bf[nt2 * 2 + 0][0] = bt[0]; bf[nt2 * 2 + 0][1] = bt[1];
                    bf[nt2 * 2 + 1][0] = bt[2]; bf[nt2 * 2 + 1][1] = bt[3];
                }
#pragma unroll
                for (int mt = 0; mt < 4; mt++)
#pragma unroll
                    for (int nt = 0; nt < 4; nt++)
                        mma16(acc[mt][nt], af[mt], bf[nt]);
            }

            if (kc + 2 < nk) {
                int sw = s + 2; if (sw >= NSTG) sw -= NSTG;
                load_stage(sw, (kc + 2) * 64);
            }
            if (++s == NSTG) s = 0;
        }

        // ---- epilogue ----
        float rowsum[4][2];
        if (LSE) {
#pragma unroll
            for (int mt = 0; mt < 4; mt++) { rowsum[mt][0] = 0.f; rowsum[mt][1] = 0.f; }
        }
#pragma unroll
        for (int mt = 0; mt < 4; mt++) {
            int r0 = m0 + warp_m0 + mt * 16 + g;
#pragma unroll
            for (int nt = 0; nt < 4; nt++) {
                int cn = n0 + warp_n0 + nt * 8 + t4 * 2;
                float* a4 = acc[mt][nt];
                float b0 = 0.f, b1 = 0.f;
                if (BIAS) {
                    if (!NBOUND) { b0 = bias[cn]; b1 = bias[cn + 1]; }
                    else {
                        b0 = (cn < Nn) ? bias[cn] : 0.f;
                        b1 = (cn + 1 < Nn) ? bias[cn + 1] : 0.f;
                    }
                }
#pragma unroll
                for (int half_ = 0; half_ < 2; half_++) {
                    int r = r0 + half_ * 8;
                    float v0 = a4[half_ * 2 + 0] + b0;
                    float v1 = a4[half_ * 2 + 1] + b1;
                    if (RELU) { v0 = fmaxf(v0, 0.f); v1 = fmaxf(v1, 0.f); }
                    size_t off = (size_t)r * Nn + cn;
                    if (!NBOUND) {
                        if (RES) { v0 += res[off]; v1 += res[off + 1]; }
                        if (OUTH) {
                            *(__half2*)((__half*)Cv + off) = __floats2half2_rn(v0, v1);
                        } else {
                            *(float2*)((float*)Cv + off) = make_float2(v0, v1);
                        }
                    } else {
                        float* C = (float*)Cv;
                        if (cn < Nn) {
                            if (RES) v0 += res[off];
                            C[off] = v0;
                            if (LSE) rowsum[mt][half_] += __expf(v0);
                        }
                        if (cn + 1 < Nn) {
                            if (RES) v1 += res[off + 1];
                            C[off + 1] = v1;
                            if (LSE) rowsum[mt][half_] += __expf(v1);
                        }
                    }
                }
            }
        }
        if (LSE) {
#pragma unroll
            for (int mt = 0; mt < 4; mt++) {
#pragma unroll
                for (int half_ = 0; half_ < 2; half_++) {
                    float sc = rowsum[mt][half_];
                    sc += __shfl_xor_sync(0xffffffffu, sc, 1);
                    sc += __shfl_xor_sync(0xffffffffu, sc, 2);
                    if (t4 == 0) {
                        int r = m0 + warp_m0 + mt * 16 + g + half_ * 8;
                        atomicAdd(&lse[r], sc);
                    }
                }
            }
        }
    }
}

// ---------------- embedding ----------------
__global__ void embed_kernel(const int* __restrict__ inp,
                             const float* __restrict__ tok,
                             const float* __restrict__ pos,
                             float* __restrict__ x) {
    int i = blockIdx.x;
    int t = i & (Tt - 1);
    int v = inp[i];
    const float* te = tok + (size_t)v * Cd;
    const float* pe = pos + (size_t)t * Cd;
    float* xo = x + (size_t)i * Cd;
    for (int c = threadIdx.x; c < Cd; c += blockDim.x)
        xo[c] = te[c] + pe[c];
}

// ---------------- layernorm: warp per row, fp16 output ----------------
__global__ __launch_bounds__(256) void ln_kernel(const float* __restrict__ x,
                                                 const float* __restrict__ g,
                                                 const float* __restrict__ b,
                                                 __half* __restrict__ out) {
    const int warp = threadIdx.x >> 5, lane = threadIdx.x & 31;
    const int row = blockIdx.x * 8 + warp;
    const float4* xr = (const float4*)(x + (size_t)row * Cd);
    const float4* gp = (const float4*)g;
    const float4* bp = (const float4*)b;
    __half* orow = out + (size_t)row * Cd;

    float4 v[6];
    float s = 0.f;
#pragma unroll
    for (int i = 0; i < 6; i++) {
        v[i] = xr[lane + i * 32];
        s += v[i].x + v[i].y + v[i].z + v[i].w;
    }
#pragma unroll
    for (int o = 16; o; o >>= 1) s += __shfl_xor_sync(0xffffffffu, s, o);
    float mean = s * (1.0f / Cd);

    float vs = 0.f;
#pragma unroll
    for (int i = 0; i < 6; i++) {
        float dx = v[i].x - mean, dy = v[i].y - mean,
              dz = v[i].z - mean, dw = v[i].w - mean;
        vs += dx * dx + dy * dy + dz * dz + dw * dw;
    }
#pragma unroll
    for (int o = 16; o; o >>= 1) vs += __shfl_xor_sync(0xffffffffu, vs, o);
    float rstd = rsqrtf(vs * (1.0f / Cd) + 1e-5f);

#pragma unroll
    for (int i = 0; i < 6; i++) {
        float4 gg = gp[lane + i * 32];
        float4 bb = bp[lane + i * 32];
        __half2 h01 = __floats2half2_rn((v[i].x - mean) * rstd * gg.x + bb.x,
                                        (v[i].y - mean) * rstd * gg.y + bb.y);
        __half2 h23 = __floats2half2_rn((v[i].z - mean) * rstd * gg.z + bb.z,
                                        (v[i].w - mean) * rstd * gg.w + bb.w);
        uint2 pk = make_uint2(*(uint32_t*)&h01, *(uint32_t*)&h23);
        *(uint2*)(orow + (lane + i * 32) * 4) = pk;
    }
}

// ---------------- fp16 -> fp32 convert (fallback path) ----------------
__global__ void h2f_kernel(const __half* __restrict__ src, float* __restrict__ dst, size_t n) {
    for (size_t i = (size_t)blockIdx.x * blockDim.x + threadIdx.x; i < n;
         i += (size_t)gridDim.x * blockDim.x)
        dst[i] = __half2float(src[i]);
}

// ---------------- SIMT SGEMM (loss-only fallback path) ----------------
template<bool BIAS, bool RELU, bool RES>
__global__ __launch_bounds__(256) void sgemm_kernel(
    const float* __restrict__ A, const float* __restrict__ W,
    const float* __restrict__ bias, const float* __restrict__ res,
    float* __restrict__ Cout, int M, int Nn, int K, int ldw) {
    __shared__ float As[16][132];
    __shared__ float Bs[16][64];
    int tid = threadIdx.x;
    int m0 = blockIdx.x * 128;
    int n0 = blockIdx.y * 64;
    int tx = tid & 15, ty = tid >> 4;
    float acc[8][4];
#pragma unroll
    for (int i = 0; i < 8; i++)
#pragma unroll
        for (int j = 0; j < 4; j++) acc[i][j] = 0.f;
    int am = tid >> 1;
    int ak = (tid & 1) * 8;
    int bk = tid >> 4;
    int bn = (tid & 15) * 4;
    for (int k0 = 0; k0 < K; k0 += 16) {
        const float* Ap = A + (size_t)(m0 + am) * K + k0 + ak;
        float4 a0 = *(const float4*)Ap;
        float4 a1 = *(const float4*)(Ap + 4);
        As[ak + 0][am] = a0.x; As[ak + 1][am] = a0.y;
        As[ak + 2][am] = a0.z; As[ak + 3][am] = a0.w;
        As[ak + 4][am] = a1.x; As[ak + 5][am] = a1.y;
        As[ak + 6][am] = a1.z; As[ak + 7][am] = a1.w;
        int gn = n0 + bn;
        const float* Wp = W + (size_t)(k0 + bk) * ldw + gn;
        float4 bv;
        bv.x = (gn + 0 < Nn) ? Wp[0] : 0.f;
        bv.y = (gn + 1 < Nn) ? Wp[1] : 0.f;
        bv.z = (gn + 2 < Nn) ? Wp[2] : 0.f;
        bv.w = (gn + 3 < Nn) ? Wp[3] : 0.f;
        *(float4*)&Bs[bk][bn] = bv;
        __syncthreads();
#pragma unroll
        for (int kk = 0; kk < 16; kk++) {
            float4 a04 = *(const float4*)&As[kk][ty * 8];
            float4 a14 = *(const float4*)&As[kk][ty * 8 + 4];
            float4 b4  = *(const float4*)&Bs[kk][tx * 4];
            float a[8] = {a04.x, a04.y, a04.z, a04.w, a14.x, a14.y, a14.z, a14.w};
            float bb[4] = {b4.x, b4.y, b4.z, b4.w};
#pragma unroll
            for (int i = 0; i < 8; i++)
#pragma unroll
                for (int j = 0; j < 4; j++)
                    acc[i][j] += a[i] * bb[j];
        }
        __syncthreads();
    }
    int nbase = n0 + tx * 4;
#pragma unroll
    for (int i = 0; i < 8; i++) {
        size_t rowoff = (size_t)(m0 + ty * 8 + i) * Nn;
#pragma unroll
        for (int j = 0; j < 4; j++) {
            int n = nbase + j;
            if (n < Nn) {
                float v = acc[i][j];
                if (BIAS) v += bias[n];
                if (RELU) v = fmaxf(v, 0.f);
                if (RES) v += res[rowoff + n];
                Cout[rowoff + n] = v;
            }
        }
    }
}

// =====================================================================
// fp16 tensor-core flash attention (S exact; P split hi/lo fp16)
// cp.async double-buffered K/V tiles (row-major [j][d]); V via ldmatrix.trans
// =====================================================================
#define AST2 72
#define ATILE (64 * AST2)
#define ATTN_SMEM (6 * ATILE * 2)   // 55296 bytes

__global__ __launch_bounds__(128, 4) void attn_tc_kernel(const __half* __restrict__ QKV,
                                                         __half* __restrict__ O) {
    extern __shared__ __half sme[];
    __half* Ks0 = sme;
    __half* Vs0 = Ks0 + ATILE;
    __half* Ks1 = Vs0 + ATILE;
    __half* Vs1 = Ks1 + ATILE;
    __half* Ph  = Vs1 + ATILE;
    __half* Pl  = Ph + ATILE;
    const uint32_t suK[2] = { smem_u32(Ks0), smem_u32(Ks1) };

    const int qt = gridDim.x - 1 - blockIdx.x;
    const int bh = blockIdx.y;
    const int b = bh / Hh, h = bh % Hh;
    const int tid = threadIdx.x;
    const int warp = tid >> 5, lane = tid & 31;
    const int g = lane >> 2, t4 = lane & 3;
    const int r0l = warp * 16 + g;
    const int r1l = r0l + 8;

    auto load_kv = [&](int stage, int kt) {
        uint32_t sk = suK[stage];
        const __half* base = QKV + (size_t)(b * Tt + kt * 64) * QKVS + h * HSd;
#pragma unroll
        for (int i = 0; i < 4; i++) {
            int ch = tid + i * 128;
            int r = ch >> 3, c8 = (ch & 7) * 8;
            const __half* grow = base + (size_t)r * QKVS + c8;
            cp16(sk + (uint32_t)(r * AST2 + c8) * 2, grow + Cd);
            cp16(sk + (uint32_t)(ATILE + r * AST2 + c8) * 2, grow + 2 * Cd);
        }
        CP_COMMIT();
    };

    load_kv(0, 0);
    if (qt >= 1) load_kv(1, 1);

#pragma unroll
    for (int i = 0; i < 4; i++) {
        int ch = tid + i * 128;
        int r = ch >> 3, c8 = (ch & 7) * 8;
        float4 v = *(const float4*)(QKV + (size_t)(b * Tt + qt * 64 + r) * QKVS + h * HSd + c8);
        *(float4*)(Ph + r * AST2 + c8) = v;
    }
    __syncthreads();

    uint32_t qf[4][4];
#pragma unroll
    for (int ks = 0; ks < 4; ks++) {
        int kk = ks * 16;
        qf[ks][0] = *(const uint32_t*)(Ph + r0l * AST2 + kk + 2 * t4);
        qf[ks][1] = *(const uint32_t*)(Ph + r1l * AST2 + kk + 2 * t4);
        qf[ks][2] = *(const uint32_t*)(Ph + r0l * AST2 + kk + 2 * t4 + 8);
        qf[ks][3] = *(const uint32_t*)(Ph + r1l * AST2 + kk + 2 * t4 + 8);
    }

    const int vRow = (lane & 7) + ((lane >> 3) & 1) * 8;

    float o[8][4];
#pragma unroll
    for (int nt = 0; nt < 8; nt++)
#pragma unroll
        for (int j = 0; j < 4; j++) o[nt][j] = 0.f;
    float m0 = -1e30f, m1 = -1e30f, l0 = 0.f, l1 = 0.f;

    for (int kt = 0; kt <= qt; kt++) {
        const int st = kt & 1;
        if (kt < qt) CP_WAIT1(); else CP_WAIT0();
        __syncthreads();

        const __half* Ks = (st == 0) ? Ks0 : Ks1;
        const uint32_t vbase = suK[st] + ATILE * 2;

        float sacc[8][4];
#pragma unroll
        for (int nt = 0; nt < 8; nt++)
#pragma unroll
            for (int j = 0; j < 4; j++) sacc[nt][j] = 0.f;
#pragma unroll
        for (int ks = 0; ks < 4; ks++) {
            int kk = ks * 16;
#pragma unroll
            for (int nt = 0; nt < 8; nt++) {
                int j = nt * 8 + g;
                uint32_t bf[2];
                bf[0] = *(const uint32_t*)(Ks + j * AST2 + kk + 2 * t4);
                bf[1] = *(const uint32_t*)(Ks + j * AST2 + kk + 2 * t4 + 8);
                mma16(sacc[nt], qf[ks], bf);
            }
        }
#pragma unroll
        for (int nt = 0; nt < 8; nt++)
#pragma unroll
            for (int j = 0; j < 4; j++) sacc[nt][j] *= 0.125f;

        if (kt == qt) {
#pragma unroll
            for (int nt = 0; nt < 8; nt++) {
                int c0 = nt * 8 + 2 * t4;
                if (c0     > r0l) sacc[nt][0] = -1e30f;
                if (c0 + 1 > r0l) sacc[nt][1] = -1e30f;
                if (c0     > r1l) sacc[nt][2] = -1e30f;
                if (c0 + 1 > r1l) sacc[nt][3] = -1e30f;
            }
        }

        float tm0 = -1e30f, tm1 = -1e30f;
#pragma unroll
        for (int nt = 0; nt < 8; nt++) {
            tm0 = fmaxf(tm0, fmaxf(sacc[nt][0], sacc[nt][1]));
            tm1 = fmaxf(tm1, fmaxf(sacc[nt][2], sacc[nt][3]));
        }
        tm0 = fmaxf(tm0, __shfl_xor_sync(0xffffffffu, tm0, 1));
        tm0 = fmaxf(tm0, __shfl_xor_sync(0xffffffffu, tm0, 2));
        tm1 = fmaxf(tm1, __shfl_xor_sync(0xffffffffu, tm1, 1));
        tm1 = fmaxf(tm1, __shfl_xor_sync(0xffffffffu, tm1, 2));
        float mN0 = fmaxf(m0, tm0), mN1 = fmaxf(m1, tm1);
        float a0 = __expf(m0 - mN0), a1 = __expf(m1 - mN1);
        m0 = mN0; m1 = mN1;

        float sum0 = 0.f, sum1 = 0.f;
#pragma unroll
        for (int nt = 0; nt < 8; nt++) {
            float p0 = __expf(sacc[nt][0] - mN0);
            float p1 = __expf(sacc[nt][1] - mN0);
            float p2 = __expf(sacc[nt][2] - mN1);
            float p3 = __expf(sacc[nt][3] - mN1);
            sum0 += p0 + p1;
            sum1 += p2 + p3;
            int c0 = nt * 8 + 2 * t4;
            __half2 h01 = __floats2half2_rn(p0, p1);
            __half2 h23 = __floats2half2_rn(p2, p3);
            *(__half2*)(Ph + r0l * AST2 + c0) = h01;
            *(__half2*)(Ph + r1l * AST2 + c0) = h23;
            *(__half2*)(Pl + r0l * AST2 + c0) =
                __floats2half2_rn(p0 - __half2float(__low2half(h01)),
                                  p1 - __half2float(__high2half(h01)));
            *(__half2*)(Pl + r1l * AST2 + c0) =
                __floats2half2_rn(p2 - __half2float(__low2half(h23)),
                                  p3 - __half2float(__high2half(h23)));
        }
        sum0 += __shfl_xor_sync(0xffffffffu, sum0, 1);
        sum0 += __shfl_xor_sync(0xffffffffu, sum0, 2);
        sum1 += __shfl_xor_sync(0xffffffffu, sum1, 1);
        sum1 += __shfl_xor_sync(0xffffffffu, sum1, 2);
        l0 = l0 * a0 + sum0;
        l1 = l1 * a1 + sum1;
#pragma unroll
        for (int nt = 0; nt < 8; nt++) {
            o[nt][0] *= a0; o[nt][1] *= a0;
            o[nt][2] *= a1; o[nt][3] *= a1;
        }
        __syncwarp();

#pragma unroll
        for (int ks = 0; ks < 4; ks++) {
            int kk = ks * 16;
            uint32_t ah[4], al[4];
            ah[0] = *(const uint32_t*)(Ph + r0l * AST2 + kk + 2 * t4);
            ah[1] = *(const uint32_t*)(Ph + r1l * AST2 + kk + 2 * t4);
            ah[2] = *(const uint32_t*)(Ph + r0l * AST2 + kk + 2 * t4 + 8);
            ah[3] = *(const uint32_t*)(Ph + r1l * AST2 + kk + 2 * t4 + 8);
            al[0] = *(const uint32_t*)(Pl + r0l * AST2 + kk + 2 * t4);
            al[1] = *(const uint32_t*)(Pl + r1l * AST2 + kk + 2 * t4);
            al[2] = *(const uint32_t*)(Pl + r0l * AST2 + kk + 2 * t4 + 8);
            al[3] = *(const uint32_t*)(Pl + r1l * AST2 + kk + 2 * t4 + 8);
            uint32_t vaddr = vbase + (uint32_t)((kk + vRow) * AST2) * 2;
#pragma unroll
            for (int nt = 0; nt < 8; nt++) {
                uint32_t bf[2];
                ldsm_x2_trans(bf, vaddr + (uint32_t)(nt * 8) * 2);
                mma16(o[nt], ah, bf);
                mma16(o[nt], al, bf);
            }
        }

        __syncthreads();
        if (kt + 2 <= qt) load_kv(st, kt + 2);
    }

    float i0 = 1.f / l0, i1 = 1.f / l1;
    size_t row0 = (size_t)(b * Tt + qt * 64 + r0l) * Cd + h * HSd;
    size_t row1 = (size_t)(b * Tt + qt * 64 + r1l) * Cd + h * HSd;
#pragma unroll
    for (int nt = 0; nt < 8; nt++) {
        int c0 = nt * 8 + 2 * t4;
        *(__half2*)(O + row0 + c0) = __floats2half2_rn(o[nt][0] * i0, o[nt][1] * i0);
        *(__half2*)(O + row1 + c0) = __floats2half2_rn(o[nt][2] * i1, o[nt][3] * i1);
    }
}

// ---------------- loss kernels ----------------
__global__ void zero_kernel(float* p, int n) {
    int i = blockIdx.x * blockDim.x + threadIdx.x;
    if (i < n) p[i] = 0.f;
}

__global__ __launch_bounds__(256) void lossfinal_kernel(const float* __restrict__ ls,
                                                        const float* __restrict__ logits,
                                                        const int* __restrict__ tgt,
                                                        float* __restrict__ out) {
    float s = 0.f;
    for (int r = threadIdx.x; r < NT; r += 256)
        s += logf(ls[r]) - logits[(size_t)r * Vv + tgt[r]];
    s = blockReduceSum256(s);
    if (threadIdx.x == 0) out[0] = s * (1.0f / NT);
}

__global__ __launch_bounds__(256) void lossreduce_kernel(const float* __restrict__ rl,
                                                         float* __restrict__ out) {
    float s = 0.f;
    for (int i = threadIdx.x; i < NT; i += 256) s += rl[i];
    s = blockReduceSum256(s);
    if (threadIdx.x == 0) out[0] = s * (1.0f / NT);
}

__global__ void lse_init_kernel(float* lm, float* ls, float* lt) {
    int i = blockIdx.x * blockDim.x + threadIdx.x;
    if (i < NT) { lm[i] = -1e30f; ls[i] = 0.f; lt[i] = 0.f; }
}

__global__ __launch_bounds__(256) void chunkloss_kernel(const float* __restrict__ chunk,
                                                        int width, int col0,
                                                        const int* __restrict__ tgt,
                                                        float* __restrict__ lm,
                                                        float* __restrict__ ls,
                                                        float* __restrict__ lt) {
    int r = blockIdx.x;
    const float* cr = chunk + (size_t)r * width;
    float m = -1e30f;
    for (int c = threadIdx.x; c < width; c += 256) m = fmaxf(m, cr[c]);
    m = blockReduceMax256(m);
    float s = 0.f;
    for (int c = threadIdx.x; c < width; c += 256) s += __expf(cr[c] - m);
    s = blockReduceSum256(s);
    if (threadIdx.x == 0) {
        float mOld = lm[r];
        float mNew = fmaxf(mOld, m);
        ls[r] = ls[r] * __expf(mOld - mNew) + s * __expf(m - mNew);
        lm[r] = mNew;
        int tg = tgt[r] - col0;
        if (tg >= 0 && tg < width) lt[r] = cr[tg];
    }
}

__global__ void chunkfinal_kernel(const float* lm, const float* ls, const float* lt,
                                  float* rl) {
    int i = blockIdx.x * blockDim.x + threadIdx.x;
    if (i < NT) rl[i] = lm[i] + logf(ls[i]) - lt[i];
}

// ---------------- host driver ----------------
static void* devptr(const void* sym) {
    void* p = nullptr;
    cudaGetSymbolAddress(&p, sym);
    return p;
}

extern "C" void kernel_launch(void* const* d_in, const int* in_sizes, int n_in,
                              void* d_out, int out_size) {
    const int* inputs    = (const int*)d_in[0];
    const int* targets   = (const int*)d_in[1];
    const float* tok     = (const float*)d_in[2];
    const float* pos     = (const float*)d_in[3];
    const float* ln1g    = (const float*)d_in[4];
    const float* ln1b    = (const float*)d_in[5];
    const float* ln2g    = (const float*)d_in[6];
    const float* ln2b    = (const float*)d_in[7];
    const float* wq      = (const float*)d_in[8];
    const float* wk      = (const float*)d_in[9];
    const float* wv      = (const float*)d_in[10];
    const float* wo      = (const float*)d_in[11];
    const float* bo      = (const float*)d_in[12];
    const float* w1      = (const float*)d_in[13];
    const float* b1      = (const float*)d_in[14];
    const float* w2      = (const float*)d_in[15];
    const float* b2      = (const float*)d_in[16];
    const float* lnfg    = (const float*)d_in[17];
    const float* lnfb    = (const float*)d_in[18];
    const float* whead   = (const float*)d_in[19];
    const float* bhead   = (const float*)d_in[20];

    float*  x   = (float*)devptr(g_x);
    __half* h   = (__half*)devptr(g_h);
    __half* qkv = (__half*)devptr(g_qkv);
    __half* ob  = (__half*)devptr(g_ob);
    __half* fb  = (__half*)devptr(g_f);
    float*  rl  = (float*)devptr(g_rowloss);
    float*  lm  = (float*)devptr(g_lm);
    float*  ls  = (float*)devptr(g_ls);
    float*  lt  = (float*)devptr(g_lt);
    __half* wth = (__half*)devptr(g_wth);

    cudaFuncSetAttribute(mma_gemm<false, false, false, false, true, false>, cudaFuncAttributeMaxDynamicSharedMemorySize, GEMM_SMEM);
    cudaFuncSetAttribute(mma_gemm<true, false, true, false, false, false>,  cudaFuncAttributeMaxDynamicSharedMemorySize, GEMM_SMEM);
    cudaFuncSetAttribute(mma_gemm<true, true, false, false, true, false>,   cudaFuncAttributeMaxDynamicSharedMemorySize, GEMM_SMEM);
    cudaFuncSetAttribute(mma_gemm<true, false, false, true, false, true>,   cudaFuncAttributeMaxDynamicSharedMemorySize, GEMM_SMEM);
    cudaFuncSetAttribute(mma_gemm<true, false, false, true, false, false>,  cudaFuncAttributeMaxDynamicSharedMemorySize, GEMM_SMEM);
    cudaFuncSetAttribute(attn_tc_kernel, cudaFuncAttributeMaxDynamicSharedMemorySize, ATTN_SMEM);

    // ---- weight prep: fp16 convert + transpose to [N][K], once per launch ----
    {
        dim3 blk(256);
        size_t cc = (size_t)Cd * Cd, cf = (size_t)Cd * Fd;
        dim3 gCC(Cd / 32, Cd / 64, Ll);
        transpose_h_kernel<<<gCC, blk>>>(wq, wth + OFF_QKV + (size_t)0 * cc, Cd, Cd, Cd, cc, (size_t)QKVS * Cd);
        transpose_h_kernel<<<gCC, blk>>>(wk, wth + OFF_QKV + (size_t)1 * cc, Cd, Cd, Cd, cc, (size_t)QKVS * Cd);
        transpose_h_kernel<<<gCC, blk>>>(wv, wth + OFF_QKV + (size_t)2 * cc, Cd, Cd, Cd, cc, (size_t)QKVS * Cd);
        transpose_h_kernel<<<gCC, blk>>>(wo, wth + OFF_WO, Cd, Cd, Cd, cc, cc);
        dim3 gW1(Fd / 32, Cd / 64, Ll);
        transpose_h_kernel<<<gW1, blk>>>(w1, wth + OFF_W1, Cd, Fd, Fd, cf, cf);
        dim3 gW2(Cd / 32, Fd / 64, Ll);
        transpose_h_kernel<<<gW2, blk>>>(w2, wth + OFF_W2, Fd, Cd, Cd, cf, cf);
        dim3 gHd(VPAD / 32, Cd / 64, 1);
        transpose_h_kernel<<<gHd, blk>>>(whead, wth + OFF_HD, Cd, Vv, VPAD, 0, 0);
    }

    dim3 gAttn(Tt / 64, Bq * Hh);

    embed_kernel<<<NT, 256>>>(inputs, tok, pos, x);

    for (int l = 0; l < Ll; l++) {
        const __half* wqkv = wth + OFF_QKV + (size_t)l * Cd * QKVS;
        const __half* wot  = wth + OFF_WO + (size_t)l * Cd * Cd;
        const __half* w1t  = wth + OFF_W1 + (size_t)l * Cd * Fd;
        const __half* w2t  = wth + OFF_W2 + (size_t)l * Fd * Cd;

        ln_kernel<<<NT / 8, 256>>>(x, ln1g + l * Cd, ln1b + l * Cd, h);
        mma_gemm<false, false, false, false, true, false><<<GEMM_GRID, 256, GEMM_SMEM>>>(
            h, wqkv, nullptr, nullptr, qkv, NT, QKVS, Cd, QKVS / 128, nullptr);
        attn_tc_kernel<<<gAttn, 128, ATTN_SMEM>>>(qkv, ob);
        mma_gemm<true, false, true, false, false, false><<<GEMM_GRID, 256, GEMM_SMEM>>>(
            ob, wot, bo + l * Cd, x, x, NT, Cd, Cd, Cd / 128, nullptr);
        ln_kernel<<<NT / 8, 256>>>(x, ln2g + l * Cd, ln2b + l * Cd, h);
        mma_gemm<true, true, false, false, true, false><<<GEMM_GRID, 256, GEMM_SMEM>>>(
            h, w1t, b1 + (size_t)l * Fd, nullptr, fb, NT, Fd, Cd, Fd / 128, nullptr);
        mma_gemm<true, false, true, false, false, false><<<GEMM_GRID, 256, GEMM_SMEM>>>(
            fb, w2t, b2 + l * Cd, x, x, NT, Cd, Fd, Cd / 128, nullptr);
    }

    ln_kernel<<<NT / 8, 256>>>(x, lnfg, lnfb, h);

    const long long NV = (long long)NT * Vv;
    if ((long long)out_size >= NV) {
        float* logits = (float*)d_out;
        bool wantLoss = ((long long)out_size > NV);
        if (wantLoss) {
            zero_kernel<<<(NT + 255) / 256, 256>>>(ls, NT);
            mma_gemm<true, false, false, true, false, true><<<GEMM_GRID, 256, GEMM_SMEM>>>(
                h, wth + OFF_HD, bhead, nullptr, logits, NT, Vv, Cd, VPAD / 128, ls);
            lossfinal_kernel<<<1, 256>>>(ls, logits, targets, (float*)d_out + NV);
        } else {
            mma_gemm<true, false, false, true, false, false><<<GEMM_GRID, 256, GEMM_SMEM>>>(
                h, wth + OFF_HD, bhead, nullptr, logits, NT, Vv, Cd, VPAD / 128, nullptr);
        }
    } else {
        h2f_kernel<<<2048, 256>>>(h, x, (size_t)NT * Cd);
        lse_init_kernel<<<(NT + 255) / 256, 256>>>(lm, ls, lt);
        const int CW = 3072;
        float* fbuf = (float*)devptr(g_f);
        for (int col0 = 0; col0 < Vv; col0 += CW) {
            int width = (Vv - col0 < CW) ? (Vv - col0) : CW;
            dim3 gCk(NT / 128, (width + 63) / 64);
            sgemm_kernel<true, false, false><<<gCk, 256>>>(x, whead + col0, bhead + col0,
                                                           nullptr, fbuf, NT, width, Cd, Vv);
            chunkloss_kernel<<<NT, 256>>>(fbuf, width, col0, targets, lm, ls, lt);
        }
        chunkfinal_kernel<<<(NT + 255) / 256, 256>>>(lm, ls, lt, rl);
        lossreduce_kernel<<<1, 256>>>(rl, (float*)d_out);
    }
}